// round 9
// baseline (speedup 1.0000x reference)
#include <cuda_runtime.h>
#include <cuda_fp16.h>
#include <math.h>
#include <stdint.h>

// ---------------- problem constants ----------------
#define IH 384
#define IW 384
#define NPIX (IH*IW)
#define NIMG 4
#define NT 577
#define DM 768
#define NL 12
#define NHD 12
#define BT (NIMG*NT)    // 2308
#define NPATCH 576
#define BIGF 1e4f
#define SP 640          // padded attention row stride

// static scales (fp16 range management)
#define WS  4096.f
#define AS  256.f
#define PS  32.f
#define SS  256.f       // softmax prob scale

// ---------------- scratch (device globals) ----------------
__device__ float d_g2fg[NIMG*NPIX];
__device__ float d_g2bg[NIMG*NPIX];
__device__ float d_tok [NIMG*NPATCH*DM];
__device__ float d_x   [BT*DM];
__device__ float d_h   [BT*DM];
__device__ float d_S   [(size_t)NIMG*NHD*NT*NT];

// fp16 split-2 activation planes (scaled)
__device__ __align__(128) __half d_h0[BT*DM],    d_h1[BT*DM];
__device__ __align__(128) __half d_a0[BT*DM],    d_a1[BT*DM];
__device__ __align__(128) __half d_m0[BT*3072],  d_m1[BT*3072];
__device__ __align__(128) __half d_p0[NIMG*NPATCH*256], d_p1[NIMG*NPATCH*256];
__device__ __align__(128) __half d_q0[BT*3*DM],  d_q1[BT*3*DM];      // qkv splits
__device__ __align__(128) __half d_S0[(size_t)NIMG*NHD*NT*SP];
__device__ __align__(128) __half d_S1[(size_t)NIMG*NHD*NT*SP];

// fp16 split-2, transposed weight planes [N][K] (scaled by WS)
__device__ __align__(128) __half d_ws0[DM*256],       d_ws1[DM*256];
__device__ __align__(128) __half d_qT0[NL*2304*DM],   d_qT1[NL*2304*DM];
__device__ __align__(128) __half d_pT0[NL*DM*DM],     d_pT1[NL*DM*DM];
__device__ __align__(128) __half d_f1T0[NL*3072*DM],  d_f1T1[NL*3072*DM];
__device__ __align__(128) __half d_f2T0[NL*DM*3072],  d_f2T1[NL*DM*3072];

// ---------------- helpers ----------------
__device__ __forceinline__ void split2h(float x, float s, __half& h0, __half& h1) {
    float xs = x * s;
    h0 = __float2half_rn(xs);
    h1 = __float2half_rn(xs - __half2float(h0));
}
__device__ __forceinline__ uint32_t s2u(const void* p) {
    uint32_t a;
    asm("{ .reg .u64 t; cvta.to.shared.u64 t, %1; cvt.u32.u64 %0, t; }" : "=r"(a) : "l"(p));
    return a;
}
#define CP16(s,g)  asm volatile("cp.async.cg.shared.global [%0], [%1], 16;" :: "r"(s), "l"(g))
#define CPCOMMIT() asm volatile("cp.async.commit_group;")
#define CPWAIT0()  asm volatile("cp.async.wait_group 0;")

__device__ __forceinline__ void ldsm4(unsigned &r0, unsigned &r1, unsigned &r2,
                                      unsigned &r3, uint32_t addr) {
    asm volatile("ldmatrix.sync.aligned.m8n8.x4.shared.b16 {%0,%1,%2,%3}, [%4];"
        : "=r"(r0), "=r"(r1), "=r"(r2), "=r"(r3) : "r"(addr));
}
__device__ __forceinline__ void ldsm4t(unsigned &r0, unsigned &r1, unsigned &r2,
                                       unsigned &r3, uint32_t addr) {
    asm volatile("ldmatrix.sync.aligned.m8n8.x4.trans.shared.b16 {%0,%1,%2,%3}, [%4];"
        : "=r"(r0), "=r"(r1), "=r"(r2), "=r"(r3) : "r"(addr));
}
#define MMA_F16(c, a, b0v, b1v) \
    asm volatile("mma.sync.aligned.m16n8k16.row.col.f32.f16.f16.f32 " \
                 "{%0,%1,%2,%3},{%4,%5,%6,%7},{%8,%9},{%0,%1,%2,%3};" \
                 : "+f"((c)[0]), "+f"((c)[1]), "+f"((c)[2]), "+f"((c)[3]) \
                 : "r"((a)[0]), "r"((a)[1]), "r"((a)[2]), "r"((a)[3]), \
                   "r"(b0v), "r"(b1v))

// ---------------- EDT row pass (mask fused, computed on the fly) -----------
__global__ void k_edt_row(const float* __restrict__ logits, const int* __restrict__ tr) {
    int idx = blockIdx.x*blockDim.x + threadIdx.x;
    if (idx >= NIMG*IH) return;
    int img = idx / IH, i = idx % IH;
    float* gf = d_g2fg + (size_t)img*NPIX + (size_t)i*IW;
    float* gb = d_g2bg + (size_t)img*NPIX + (size_t)i*IW;
    const float* l0p = logits + ((size_t)img*2)*NPIX + (size_t)i*IW;
    const float* l1p = l0p + NPIX;
    const int*   trp = tr + (size_t)(img-2)*NPIX + (size_t)i*IW;
    bool islog = (img < 2);

    float lf = -BIGF, lb = -BIGF;
    for (int j = 0; j < IW; j++) {
        bool mz = islog ? !(l1p[j] > l0p[j]) : (trp[j] == 0);
        float jj = (float)j;
        if (mz) lf = jj; else lb = jj;
        gf[j] = jj - lf;
        gb[j] = jj - lb;
    }
    float rf = BIGF, rb = BIGF;
    for (int j = IW-1; j >= 0; j--) {
        bool mz = islog ? !(l1p[j] > l0p[j]) : (trp[j] == 0);
        float jj = (float)j;
        if (mz) rf = jj; else rb = jj;
        float g1 = fminf(fminf(gf[j], rf - jj), BIGF);
        float g2 = fminf(fminf(gb[j], rb - jj), BIGF);
        gf[j] = g1*g1;
        gb[j] = g2*g2;
    }
}

// ---------------- EDT column pass + SDM + patch-split write ----------------
__global__ void k_edt_col() {
    int idx = blockIdx.x*blockDim.x + threadIdx.x;
    if (idx >= NIMG*NPIX) return;
    int img = idx / NPIX, r = idx % NPIX;
    int i = r / IW, j = r % IW;
    const float* gf = d_g2fg + (size_t)img*NPIX;
    const float* gb = d_g2bg + (size_t)img*NPIX;
    float mf = 3.4e38f, mb = 3.4e38f;
    float fi = (float)i;
    for (int ii = 0; ii < IH; ii++) {
        float off = fi - (float)ii; off *= off;
        mf = fminf(mf, gf[(size_t)ii*IW + j] + off);
        mb = fminf(mb, gb[(size_t)ii*IW + j] + off);
    }
    float v = sqrtf(mb) - sqrtf(mf);
    int t = (i >> 4)*24 + (j >> 4);
    int k = ((i & 15) << 4) + (j & 15);
    size_t o = (size_t)img*NPATCH*256 + (size_t)t*256 + k;
    split2h(v, PS, d_p0[o], d_p1[o]);
}

// ---------------- weight prep ----------------
__global__ void k_wsumT(const float* __restrict__ pw) {
    int idx = blockIdx.x*blockDim.x + threadIdx.x;
    if (idx >= DM*256) return;
    int o = idx / 256, k = idx % 256;
    float v = pw[(size_t)k*DM + o] + pw[(size_t)(256+k)*DM + o] + pw[(size_t)(512+k)*DM + o];
    split2h(v, WS, d_ws0[idx], d_ws1[idx]);
}

__global__ void k_tsplit(const float* __restrict__ W, __half* __restrict__ T0,
                         __half* __restrict__ T1, int K, int N) {
    __shared__ float t[32][33];
    size_t off = (size_t)blockIdx.z * K * N;
    const float* w = W + off;
    int bx = blockIdx.x*32, by = blockIdx.y*32;
    int tx = threadIdx.x, ty = threadIdx.y;
    #pragma unroll
    for (int r = 0; r < 4; r++)
        t[ty + r*8][tx] = w[(size_t)(by + ty + r*8)*N + bx + tx];
    __syncthreads();
    #pragma unroll
    for (int r = 0; r < 4; r++) {
        int n = bx + ty + r*8, k = by + tx;
        float v = t[tx][ty + r*8];
        size_t o = off + (size_t)n*K + k;
        split2h(v, WS, T0[o], T1[o]);
    }
}

__global__ void k_assemble(const float* __restrict__ cls, const float* __restrict__ pos) {
    int idx = blockIdx.x*blockDim.x + threadIdx.x;
    if (idx >= BT*DM) return;
    int img = idx / (NT*DM);
    int rem = idx % (NT*DM);
    int t = rem / DM, c = rem % DM;
    float v = (t == 0) ? cls[c] : d_tok[((size_t)img*NPATCH + (t-1))*DM + c];
    d_x[idx] = v + pos[(size_t)t*DM + c];
}

// ---------------- layernorm (split planes; fp32 out only when wout) --------
__global__ void k_ln(const float* __restrict__ in, float* __restrict__ out,
                     const float* __restrict__ g, const float* __restrict__ b,
                     int wout) {
    int row = blockIdx.x;
    int tid = threadIdx.x;
    const float* xr = in + (size_t)row*DM;
    __shared__ float red[256];
    float s = 0.f;
    for (int c = tid; c < DM; c += 256) s += xr[c];
    red[tid] = s; __syncthreads();
    for (int o = 128; o > 0; o >>= 1) { if (tid < o) red[tid] += red[tid+o]; __syncthreads(); }
    float mu = red[0] * (1.f/768.f);
    __syncthreads();
    float v = 0.f;
    for (int c = tid; c < DM; c += 256) { float dd = xr[c]-mu; v += dd*dd; }
    red[tid] = v; __syncthreads();
    for (int o = 128; o > 0; o >>= 1) { if (tid < o) red[tid] += red[tid+o]; __syncthreads(); }
    float rstd = rsqrtf(red[0] * (1.f/768.f) + 1e-6f);
    for (int c = tid; c < DM; c += 256) {
        float val = (xr[c]-mu)*rstd*g[c] + b[c];
        size_t o = (size_t)row*DM + c;
        if (wout) out[o] = val;
        split2h(val, AS, d_h0[o], d_h1[o]);
    }
}

// ================= fp16 split-2 tensor-core GEMM (templated N-tile) =========
// epi: 0 = bias -> C(float); 1 = gelu(bias+..) -> split planes C0/C1;
//      2 = bias + residual -> C(float); 3 = bias -> split planes C0/C1
#define APL 10240u

template<int BN>
__global__ __launch_bounds__(256, 2) void k_gemm_h(
        const __half* __restrict__ A0, const __half* __restrict__ A1,
        const __half* __restrict__ B0, const __half* __restrict__ B1,
        const float* __restrict__ bias, const float* __restrict__ res,
        float* __restrict__ C, __half* __restrict__ C0, __half* __restrict__ C1,
        int M, int N, int K, float inv, int epi) {
    constexpr unsigned BPL  = (unsigned)BN * 80u;       // B plane bytes
    constexpr unsigned BUFB = 2u*APL + 2u*BPL;
    constexpr int NQ = BN / 32;                         // b ldsm groups per ks
    constexpr int NJ = BN / 16;                         // acc column groups
    constexpr int WNW = BN / 2;                         // warp n-tile

    extern __shared__ char smem[];
    uint32_t sb = s2u(smem);
    int tid = threadIdx.x, lane = tid & 31, warp = tid >> 5;
    int wm = (warp & 3)*32, wn = (warp >> 2)*WNW;
    int bm = blockIdx.y*128, bn = blockIdx.x*BN;
    int g = lane >> 2, q = lane & 3;

    float acc[2][NJ][4];
    #pragma unroll
    for (int i=0;i<2;i++)
        #pragma unroll
        for (int j=0;j<NJ;j++)
            #pragma unroll
            for (int r=0;r<4;r++) acc[i][j][r]=0.f;

    int lrow = tid >> 2;
    int lc   = tid & 3;

    auto load_chunk = [&](int kt, int buf) {
        int k0 = kt * 32;
        uint32_t base = sb + (uint32_t)buf * BUFB;
        const __half* Ap[2] = {A0, A1};
        const __half* Bp[2] = {B0, B1};
        #pragma unroll
        for (int p = 0; p < 2; p++) {
            #pragma unroll
            for (int l = 0; l < 2; l++) {
                int row = lrow + l*64;
                int gr = bm + row; if (gr >= M) gr = M - 1;
                CP16(base + p*APL + (uint32_t)(row*80 + lc*16),
                     Ap[p] + (size_t)gr*K + k0 + lc*8);
            }
            #pragma unroll
            for (int l = 0; l < BN/64; l++) {
                int row = lrow + l*64;
                CP16(base + 2*APL + p*BPL + (uint32_t)(row*80 + lc*16),
                     Bp[p] + (size_t)(bn + row)*K + k0 + lc*8);
            }
        }
    };

    int KT = K >> 5;
    load_chunk(0, 0);
    CPCOMMIT();
    for (int kt = 0; kt < KT; kt++) {
        CPWAIT0();
        __syncthreads();
        if (kt + 1 < KT) { load_chunk(kt + 1, (kt + 1) & 1); CPCOMMIT(); }
        uint32_t base = sb + (uint32_t)(kt & 1) * BUFB;
        uint32_t aBase = base + (uint32_t)((wm + (lane & 15))*80 + (lane >> 4)*16);
        int bn8 = (lane & 7) + ((lane >> 4) << 3);
        uint32_t bBase = base + 2*APL + (uint32_t)((wn + bn8)*80 + ((lane >> 3) & 1)*16);
        #pragma unroll
        for (int ks = 0; ks < 2; ks++) {
            unsigned a0f[2][4], a1f[2][4];
            #pragma unroll
            for (int mi = 0; mi < 2; mi++) {
                ldsm4(a0f[mi][0],a0f[mi][1],a0f[mi][2],a0f[mi][3],
                      aBase + mi*1280u + ks*32u);
                ldsm4(a1f[mi][0],a1f[mi][1],a1f[mi][2],a1f[mi][3],
                      aBase + APL + mi*1280u + ks*32u);
            }
            #pragma unroll
            for (int nq = 0; nq < NQ; nq++) {
                unsigned b0f[4], b1f[4];
                ldsm4(b0f[0],b0f[1],b0f[2],b0f[3], bBase + nq*1280u + ks*32u);
                ldsm4(b1f[0],b1f[1],b1f[2],b1f[3], bBase + BPL + nq*1280u + ks*32u);
                #pragma unroll
                for (int mi = 0; mi < 2; mi++)
                    #pragma unroll
                    for (int h = 0; h < 2; h++) {
                        MMA_F16(acc[mi][nq*2+h], a0f[mi], b0f[h*2], b0f[h*2+1]);
                        MMA_F16(acc[mi][nq*2+h], a0f[mi], b1f[h*2], b1f[h*2+1]);
                        MMA_F16(acc[mi][nq*2+h], a1f[mi], b0f[h*2], b0f[h*2+1]);
                    }
            }
        }
        __syncthreads();
    }

    #pragma unroll
    for (int mi = 0; mi < 2; mi++) {
        #pragma unroll
        for (int rr = 0; rr < 2; rr++) {
            int gr = bm + wm + mi*16 + g + rr*8;
            if (gr >= M) continue;
            #pragma unroll
            for (int nj = 0; nj < NJ; nj++) {
                int gc = bn + wn + nj*8 + 2*q;
                float v0 = acc[mi][nj][rr*2+0]*inv + bias[gc];
                float v1 = acc[mi][nj][rr*2+1]*inv + bias[gc+1];
                if (epi == 1 || epi == 3) {
                    if (epi == 1) {
                        v0 = 0.5f*v0*(1.f + erff(v0*0.70710678118654752f));
                        v1 = 0.5f*v1*(1.f + erff(v1*0.70710678118654752f));
                    }
                    size_t o = (size_t)gr*N + gc;
                    __half h00, h01, h10, h11;
                    split2h(v0, AS, h00, h01);
                    split2h(v1, AS, h10, h11);
                    __half2 p0; p0.x = h00; p0.y = h10;
                    __half2 p1; p1.x = h01; p1.y = h11;
                    *(__half2*)&C0[o] = p0;
                    *(__half2*)&C1[o] = p1;
                } else {
                    if (epi == 2) {
                        float2 r2 = *(const float2*)&res[(size_t)gr*N + gc];
                        v0 += r2.x; v1 += r2.y;
                    }
                    *(float2*)&C[(size_t)gr*N + gc] = make_float2(v0, v1);
                }
            }
        }
    }
}

#define SMEM_GH128 (2u*(2u*APL + 2u*128u*80u))   // 81920
#define SMEM_GH64  (2u*(2u*APL + 2u*64u*80u))    // 61440

// ================= attention scores (tensorized split-2) =====================
#define SROW 144u
#define SPL  (128u*SROW)
#define SMEM_SC (4u*SPL)

__global__ __launch_bounds__(256, 2) void k_scores_h() {
    extern __shared__ char smem[];
    uint32_t sb = s2u(smem);
    int bh = blockIdx.z, b = bh / NHD, h = bh % NHD;
    int m0 = blockIdx.y*128, n0 = blockIdx.x*128;
    int tid = threadIdx.x, lane = tid & 31, warp = tid >> 5;
    int wm = (warp & 3)*32, wn = (warp >> 2)*64;
    int g = lane >> 2, q = lane & 3;

    #pragma unroll
    for (int l = 0; l < 4; l++) {
        int id = tid + l*256;
        int row = id >> 3, c = id & 7;
        int gm = m0 + row; if (gm >= NT) gm = NT - 1;
        int gn = n0 + row; if (gn >= NT) gn = NT - 1;
        size_t qo = (size_t)(b*NT + gm)*2304 + h*64 + c*8;
        size_t ko = (size_t)(b*NT + gn)*2304 + 768 + h*64 + c*8;
        uint32_t so = (uint32_t)(row*SROW + c*16);
        CP16(sb + so,          d_q0 + qo);
        CP16(sb + SPL + so,    d_q1 + qo);
        CP16(sb + 2*SPL + so,  d_q0 + ko);
        CP16(sb + 3*SPL + so,  d_q1 + ko);
    }
    CPCOMMIT(); CPWAIT0();
    __syncthreads();

    float acc[2][8][4];
    #pragma unroll
    for (int i=0;i<2;i++)
        #pragma unroll
        for (int j=0;j<8;j++)
            #pragma unroll
            for (int r=0;r<4;r++) acc[i][j][r]=0.f;

    uint32_t aBase = sb + (uint32_t)((wm + (lane & 15))*SROW + (lane >> 4)*16);
    int bn8 = (lane & 7) + ((lane >> 4) << 3);
    uint32_t bBase = sb + 2*SPL + (uint32_t)((wn + bn8)*SROW + ((lane >> 3) & 1)*16);

    #pragma unroll
    for (int ks = 0; ks < 4; ks++) {
        unsigned a0f[2][4], a1f[2][4];
        #pragma unroll
        for (int mi = 0; mi < 2; mi++) {
            ldsm4(a0f[mi][0],a0f[mi][1],a0f[mi][2],a0f[mi][3],
                  aBase + mi*16*SROW + ks*32u);
            ldsm4(a1f[mi][0],a1f[mi][1],a1f[mi][2],a1f[mi][3],
                  aBase + SPL + mi*16*SROW + ks*32u);
        }
        #pragma unroll
        for (int nq = 0; nq < 4; nq++) {
            unsigned b0f[4], b1f[4];
            ldsm4(b0f[0],b0f[1],b0f[2],b0f[3], bBase + nq*16*SROW + ks*32u);
            ldsm4(b1f[0],b1f[1],b1f[2],b1f[3], bBase + SPL + nq*16*SROW + ks*32u);
            #pragma unroll
            for (int mi = 0; mi < 2; mi++)
                #pragma unroll
                for (int hh = 0; hh < 2; hh++) {
                    MMA_F16(acc[mi][nq*2+hh], a0f[mi], b0f[hh*2], b0f[hh*2+1]);
                    MMA_F16(acc[mi][nq*2+hh], a0f[mi], b1f[hh*2], b1f[hh*2+1]);
                    MMA_F16(acc[mi][nq*2+hh], a1f[mi], b0f[hh*2], b0f[hh*2+1]);
                }
        }
    }

    const float SCL = 0.125f/(AS*AS);
    float* sbase = d_S + (size_t)bh*NT*NT;
    #pragma unroll
    for (int mi = 0; mi < 2; mi++)
        #pragma unroll
        for (int rr = 0; rr < 2; rr++) {
            int gm = m0 + wm + mi*16 + g + rr*8;
            if (gm >= NT) continue;
            #pragma unroll
            for (int nj = 0; nj < 8; nj++) {
                int gc = n0 + wn + nj*8 + 2*q;
                if (gc < NT)   sbase[(size_t)gm*NT + gc]   = acc[mi][nj][rr*2+0]*SCL;
                if (gc+1 < NT) sbase[(size_t)gm*NT + gc+1] = acc[mi][nj][rr*2+1]*SCL;
            }
        }
}

// ---------------- softmax: single __expf pass, split-2 out, pads zeros ------
__global__ void k_softmax() {
    size_t row = blockIdx.x;
    const float* s = d_S + row*NT;
    __half* o0 = d_S0 + row*SP;
    __half* o1 = d_S1 + row*SP;
    int tid = threadIdx.x;
    __shared__ float red[128];
    float v[5];
    float mx = -3.4e38f;
    #pragma unroll
    for (int i = 0; i < 5; i++) {
        int c = tid + i*128;
        v[i] = (c < NT) ? s[c] : -3.4e38f;
        mx = fmaxf(mx, v[i]);
    }
    red[tid] = mx; __syncthreads();
    for (int o = 64; o > 0; o >>= 1) { if (tid < o) red[tid] = fmaxf(red[tid], red[tid+o]); __syncthreads(); }
    mx = red[0]; __syncthreads();
    float sum = 0.f;
    #pragma unroll
    for (int i = 0; i < 5; i++) { v[i] = __expf(v[i] - mx); sum += v[i]; }
    red[tid] = sum; __syncthreads();
    for (int o = 64; o > 0; o >>= 1) { if (tid < o) red[tid] += red[tid+o]; __syncthreads(); }
    float inv = SS / red[0];
    #pragma unroll
    for (int i = 0; i < 5; i++) {
        int c = tid + i*128;
        float p = v[i] * inv;
        __half h0 = __float2half_rn(p);
        o0[c] = h0;
        o1[c] = __float2half_rn(p - __half2float(h0));
    }
}

// ================= AV (tensorized split-2, trans V) ==========================
#define AVAR 80u
#define AVAPL (128u*AVAR)
#define AVBR 144u
#define AVBPL (32u*AVBR)
#define AVBUF (2u*AVAPL + 2u*AVBPL)
#define SMEM_AV (2u*AVBUF)

__global__ __launch_bounds__(256, 2) void k_av_h() {
    extern __shared__ char smem[];
    uint32_t sb = s2u(smem);
    int bh = blockIdx.y, b = bh / NHD, h = bh % NHD;
    int m0 = blockIdx.x*128;
    int tid = threadIdx.x, lane = tid & 31, warp = tid >> 5;
    int wm = (warp & 3)*32, wn = (warp >> 2)*32;
    int g = lane >> 2, q = lane & 3;

    float acc[2][4][4];
    #pragma unroll
    for (int i=0;i<2;i++)
        #pragma unroll
        for (int j=0;j<4;j++)
            #pragma unroll
            for (int r=0;r<4;r++) acc[i][j][r]=0.f;

    const __half* S0b = d_S0 + (size_t)bh*NT*SP;
    const __half* S1b = d_S1 + (size_t)bh*NT*SP;

    auto load_chunk = [&](int kt, int buf) {
        int k0 = kt * 32;
        uint32_t base = sb + (uint32_t)buf * AVBUF;
        #pragma unroll
        for (int l = 0; l < 2; l++) {
            int id = tid + l*256;
            int row = id >> 2, c = id & 3;
            int gm = m0 + row; if (gm >= NT) gm = NT - 1;
            size_t so = (size_t)gm*SP + k0 + c*8;
            uint32_t d = (uint32_t)(row*AVAR + c*16);
            CP16(base + d,          S0b + so);
            CP16(base + AVAPL + d,  S1b + so);
        }
        {
            int row = tid >> 3, c = tid & 7;
            int gk = k0 + row; if (gk >= NT) gk = NT - 1;
            size_t vo = (size_t)(b*NT + gk)*2304 + 1536 + h*64 + c*8;
            uint32_t d = (uint32_t)(row*AVBR + c*16);
            CP16(base + 2*AVAPL + d,          d_q0 + vo);
            CP16(base + 2*AVAPL + AVBPL + d,  d_q1 + vo);
        }
    };

    const int KT = (NT + 31) / 32;   // 19
    load_chunk(0, 0);
    CPCOMMIT();
    for (int kt = 0; kt < KT; kt++) {
        CPWAIT0();
        __syncthreads();
        if (kt + 1 < KT) { load_chunk(kt + 1, (kt + 1) & 1); CPCOMMIT(); }
        uint32_t base = sb + (uint32_t)(kt & 1) * AVBUF;
        uint32_t aBase = base + (uint32_t)((wm + (lane & 15))*AVAR + (lane >> 4)*16);
        uint32_t bBase = base + 2*AVAPL +
                         (uint32_t)((lane & 15)*AVBR + wn*2 + (lane >> 4)*16);
        #pragma unroll
        for (int ks = 0; ks < 2; ks++) {
            unsigned a0f[2][4], a1f[2][4];
            #pragma unroll
            for (int mi = 0; mi < 2; mi++) {
                ldsm4(a0f[mi][0],a0f[mi][1],a0f[mi][2],a0f[mi][3],
                      aBase + mi*16*AVAR + ks*32u);
                ldsm4(a1f[mi][0],a1f[mi][1],a1f[mi][2],a1f[mi][3],
                      aBase + AVAPL + mi*16*AVAR + ks*32u);
            }
            #pragma unroll
            for (int nq = 0; nq < 2; nq++) {
                unsigned b0f[4], b1f[4];
                uint32_t ba = bBase + ks*16*AVBR + nq*32u;
                ldsm4t(b0f[0],b0f[1],b0f[2],b0f[3], ba);
                ldsm4t(b1f[0],b1f[1],b1f[2],b1f[3], ba + AVBPL);
                #pragma unroll
                for (int mi = 0; mi < 2; mi++)
                    #pragma unroll
                    for (int hh = 0; hh < 2; hh++) {
                        MMA_F16(acc[mi][nq*2+hh], a0f[mi], b0f[hh*2], b0f[hh*2+1]);
                        MMA_F16(acc[mi][nq*2+hh], a0f[mi], b1f[hh*2], b1f[hh*2+1]);
                        MMA_F16(acc[mi][nq*2+hh], a1f[mi], b0f[hh*2], b0f[hh*2+1]);
                    }
            }
        }
        __syncthreads();
    }

    const float INV_AV = 1.f/(SS*AS);
    #pragma unroll
    for (int mi = 0; mi < 2; mi++)
        #pragma unroll
        for (int rr = 0; rr < 2; rr++) {
            int gm = m0 + wm + mi*16 + g + rr*8;
            if (gm >= NT) continue;
            #pragma unroll
            for (int nj = 0; nj < 4; nj++) {
                int gc = wn + nj*8 + 2*q;
                size_t o = (size_t)(b*NT + gm)*DM + h*64 + gc;
                float v0 = acc[mi][nj][rr*2+0]*INV_AV;
                float v1 = acc[mi][nj][rr*2+1]*INV_AV;
                __half h00, h01, h10, h11;
                split2h(v0, AS, h00, h01);
                split2h(v1, AS, h10, h11);
                __half2 p0; p0.x = h00; p0.y = h10;
                __half2 p1; p1.x = h01; p1.y = h11;
                *(__half2*)&d_a0[o] = p0;
                *(__half2*)&d_a1[o] = p1;
            }
        }
}

// ---------------- final cosine loss ----------------
__global__ void k_loss(float* out) {
    __shared__ float sd[256], sa[256], sb2[256];
    int tid = threadIdx.x;
    float coss[2];
    for (int b = 0; b < 2; b++) {
        const float* fp = d_h + (size_t)b*NT*DM;
        const float* ft = d_h + (size_t)(2+b)*NT*DM;
        float dt = 0.f, na = 0.f, nb = 0.f;
        for (int c = tid; c < DM; c += 256) {
            float a = fp[c], bb = ft[c];
            dt += a*bb; na += a*a; nb += bb*bb;
        }
        sd[tid] = dt; sa[tid] = na; sb2[tid] = nb; __syncthreads();
        for (int o = 128; o > 0; o >>= 1) {
            if (tid < o) { sd[tid]+=sd[tid+o]; sa[tid]+=sa[tid+o]; sb2[tid]+=sb2[tid+o]; }
            __syncthreads();
        }
        coss[b] = sd[0] / (fmaxf(sqrtf(sa[0]), 1e-8f) * fmaxf(sqrtf(sb2[0]), 1e-8f));
        __syncthreads();
    }
    if (tid == 0) out[0] = 1.f - 0.5f*(coss[0] + coss[1]);
}

// ---------------- launch ----------------
extern "C" void kernel_launch(void* const* d_in, const int* in_sizes, int n_in,
                              void* d_out, int out_size) {
    const float* pred   = (const float*)d_in[0];
    const int*   tru    = (const int*)  d_in[1];
    const float* patchw = (const float*)d_in[2];
    const float* patchb = (const float*)d_in[3];
    const float* cls    = (const float*)d_in[4];
    const float* pos    = (const float*)d_in[5];
    const float* ln1g   = (const float*)d_in[6];
    const float* ln1b   = (const float*)d_in[7];
    const float* qkvw   = (const float*)d_in[8];
    const float* qkvb   = (const float*)d_in[9];
    const float* projw  = (const float*)d_in[10];
    const float* projb  = (const float*)d_in[11];
    const float* ln2g   = (const float*)d_in[12];
    const float* ln2b   = (const float*)d_in[13];
    const float* fc1w   = (const float*)d_in[14];
    const float* fc1b   = (const float*)d_in[15];
    const float* fc2w   = (const float*)d_in[16];
    const float* fc2b   = (const float*)d_in[17];
    const float* normg  = (const float*)d_in[18];
    const float* normb  = (const float*)d_in[19];

    float *px, *ph, *ptok;
    cudaGetSymbolAddress((void**)&px,   d_x);
    cudaGetSymbolAddress((void**)&ph,   d_h);
    cudaGetSymbolAddress((void**)&ptok, d_tok);

    __half *h0,*h1,*a0,*a1,*m0,*m1,*p0,*p1,*qk0,*qk1;
    __half *ws0,*ws1,*q0,*q1,*pr0,*pr1,*f10,*f11,*f20,*f21;
    cudaGetSymbolAddress((void**)&h0, d_h0);   cudaGetSymbolAddress((void**)&h1, d_h1);
    cudaGetSymbolAddress((void**)&a0, d_a0);   cudaGetSymbolAddress((void**)&a1, d_a1);
    cudaGetSymbolAddress((void**)&m0, d_m0);   cudaGetSymbolAddress((void**)&m1, d_m1);
    cudaGetSymbolAddress((void**)&p0, d_p0);   cudaGetSymbolAddress((void**)&p1, d_p1);
    cudaGetSymbolAddress((void**)&qk0, d_q0);  cudaGetSymbolAddress((void**)&qk1, d_q1);
    cudaGetSymbolAddress((void**)&ws0, d_ws0); cudaGetSymbolAddress((void**)&ws1, d_ws1);
    cudaGetSymbolAddress((void**)&q0, d_qT0);  cudaGetSymbolAddress((void**)&q1, d_qT1);
    cudaGetSymbolAddress((void**)&pr0, d_pT0); cudaGetSymbolAddress((void**)&pr1, d_pT1);
    cudaGetSymbolAddress((void**)&f10, d_f1T0); cudaGetSymbolAddress((void**)&f11, d_f1T1);
    cudaGetSymbolAddress((void**)&f20, d_f2T0); cudaGetSymbolAddress((void**)&f21, d_f2T1);

    cudaFuncSetAttribute(k_gemm_h<128>, cudaFuncAttributeMaxDynamicSharedMemorySize, SMEM_GH128);
    cudaFuncSetAttribute(k_gemm_h<64>,  cudaFuncAttributeMaxDynamicSharedMemorySize, SMEM_GH64);
    cudaFuncSetAttribute(k_scores_h,    cudaFuncAttributeMaxDynamicSharedMemorySize, SMEM_SC);
    cudaFuncSetAttribute(k_av_h,        cudaFuncAttributeMaxDynamicSharedMemorySize, SMEM_AV);

    const float INV_W = 1.f/(AS*WS);
    const float INV_P = 1.f/(PS*WS);

    // front sequence: ncu capture (index 3) lands on the patch weight GEMM
    k_edt_row<<<(NIMG*IH+127)/128, 128>>>(pred, tru);           // 0
    k_edt_col<<<(NIMG*NPIX+255)/256, 256>>>();                  // 1
    k_wsumT  <<<(DM*256+255)/256, 256>>>(patchw);               // 2
    k_gemm_h<64><<<dim3(DM/64, (NIMG*NPATCH)/128), 256, SMEM_GH64>>>(  // 3 <- ncu
        p0, p1, ws0, ws1, patchb, nullptr, ptok, nullptr, nullptr,
        NIMG*NPATCH, DM, 256, INV_P, 0);
    k_assemble<<<(BT*DM+255)/256, 256>>>(cls, pos);

    // weight prep (transpose + fp16 split-2, scaled)
    k_tsplit<<<dim3(2304/32, DM/32, NL),  dim3(32,8)>>>(qkvw,  q0, q1, DM,   2304);
    k_tsplit<<<dim3(DM/32,   DM/32, NL),  dim3(32,8)>>>(projw, pr0, pr1, DM, DM);
    k_tsplit<<<dim3(3072/32, DM/32, NL),  dim3(32,8)>>>(fc1w,  f10, f11, DM, 3072);
    k_tsplit<<<dim3(DM/32, 3072/32, NL),  dim3(32,8)>>>(fc2w,  f20, f21, 3072, DM);

    int MT = (BT + 127) / 128;   // 19

    for (int l = 0; l < NL; l++) {
        k_ln<<<BT, 256>>>(px, ph, ln1g + (size_t)l*DM, ln1b + (size_t)l*DM, 0);
        k_gemm_h<128><<<dim3(2304/128, MT), 256, SMEM_GH128>>>(
            h0, h1, q0 + (size_t)l*2304*DM, q1 + (size_t)l*2304*DM,
            qkvb + (size_t)l*2304, nullptr, nullptr, qk0, qk1,
            BT, 2304, DM, INV_W, 3);
        k_scores_h<<<dim3(5, 5, NIMG*NHD), 256, SMEM_SC>>>();
        k_softmax <<<NIMG*NHD*NT, 128>>>();
        k_av_h    <<<dim3(5, NIMG*NHD), 256, SMEM_AV>>>();
        k_gemm_h<64><<<dim3(DM/64, MT), 256, SMEM_GH64>>>(
            a0, a1, pr0 + (size_t)l*DM*DM, pr1 + (size_t)l*DM*DM,
            projb + (size_t)l*DM, px, px, nullptr, nullptr,
            BT, DM, DM, INV_W, 2);
        k_ln<<<BT, 256>>>(px, ph, ln2g + (size_t)l*DM, ln2b + (size_t)l*DM, 0);
        k_gemm_h<128><<<dim3(3072/128, MT), 256, SMEM_GH128>>>(
            h0, h1, f10 + (size_t)l*3072*DM, f11 + (size_t)l*3072*DM,
            fc1b + (size_t)l*3072, nullptr, nullptr, m0, m1,
            BT, 3072, DM, INV_W, 1);
        k_gemm_h<64><<<dim3(DM/64, MT), 256, SMEM_GH64>>>(
            m0, m1, f20 + (size_t)l*DM*3072, f21 + (size_t)l*DM*3072,
            fc2b + (size_t)l*DM, px, px, nullptr, nullptr,
            BT, DM, 3072, INV_W, 2);
    }

    k_ln<<<BT, 256>>>(px, ph, normg, normb, 1);
    k_loss<<<1, 256>>>((float*)d_out);
}

// round 10
// speedup vs baseline: 1.0481x; 1.0481x over previous
#include <cuda_runtime.h>
#include <cuda_fp16.h>
#include <math.h>
#include <stdint.h>

// ---------------- problem constants ----------------
#define IH 384
#define IW 384
#define NPIX (IH*IW)
#define NIMG 4
#define NT 577
#define DM 768
#define NL 12
#define NHD 12
#define BT (NIMG*NT)    // 2308
#define NPATCH 576
#define BIGF 1e4f
#define SP 640

// static scales (fp16 range management)
#define WS  4096.f
#define AS  256.f
#define PS  32.f
#define SS  256.f

// ---------------- scratch (device globals) ----------------
__device__ float d_g2fg[NIMG*NPIX];
__device__ float d_g2bg[NIMG*NPIX];
__device__ float d_tok [NIMG*NPATCH*DM];
__device__ float d_x   [BT*DM];
__device__ float d_h   [BT*DM];
__device__ float d_S   [(size_t)NIMG*NHD*NT*NT];

__device__ __align__(128) __half d_h0[BT*DM],    d_h1[BT*DM];
__device__ __align__(128) __half d_a0[BT*DM],    d_a1[BT*DM];
__device__ __align__(128) __half d_m0[BT*3072],  d_m1[BT*3072];
__device__ __align__(128) __half d_p0[NIMG*NPATCH*256], d_p1[NIMG*NPATCH*256];
__device__ __align__(128) __half d_q0[BT*3*DM],  d_q1[BT*3*DM];
__device__ __align__(128) __half d_S0[(size_t)NIMG*NHD*NT*SP];
__device__ __align__(128) __half d_S1[(size_t)NIMG*NHD*NT*SP];

__device__ __align__(128) __half d_ws0[DM*256],       d_ws1[DM*256];
__device__ __align__(128) __half d_qT0[NL*2304*DM],   d_qT1[NL*2304*DM];
__device__ __align__(128) __half d_pT0[NL*DM*DM],     d_pT1[NL*DM*DM];
__device__ __align__(128) __half d_f1T0[NL*3072*DM],  d_f1T1[NL*3072*DM];
__device__ __align__(128) __half d_f2T0[NL*DM*3072],  d_f2T1[NL*DM*3072];

// ---------------- helpers ----------------
__device__ __forceinline__ void split2h(float x, float s, __half& h0, __half& h1) {
    float xs = x * s;
    h0 = __float2half_rn(xs);
    h1 = __float2half_rn(xs - __half2float(h0));
}
__device__ __forceinline__ uint32_t s2u(const void* p) {
    uint32_t a;
    asm("{ .reg .u64 t; cvta.to.shared.u64 t, %1; cvt.u32.u64 %0, t; }" : "=r"(a) : "l"(p));
    return a;
}
#define CP16(s,g)  asm volatile("cp.async.cg.shared.global [%0], [%1], 16;" :: "r"(s), "l"(g))
#define CPCOMMIT() asm volatile("cp.async.commit_group;")
#define CPWAIT0()  asm volatile("cp.async.wait_group 0;")

__device__ __forceinline__ void ldsm4(unsigned &r0, unsigned &r1, unsigned &r2,
                                      unsigned &r3, uint32_t addr) {
    asm volatile("ldmatrix.sync.aligned.m8n8.x4.shared.b16 {%0,%1,%2,%3}, [%4];"
        : "=r"(r0), "=r"(r1), "=r"(r2), "=r"(r3) : "r"(addr));
}
__device__ __forceinline__ void ldsm4t(unsigned &r0, unsigned &r1, unsigned &r2,
                                       unsigned &r3, uint32_t addr) {
    asm volatile("ldmatrix.sync.aligned.m8n8.x4.trans.shared.b16 {%0,%1,%2,%3}, [%4];"
        : "=r"(r0), "=r"(r1), "=r"(r2), "=r"(r3) : "r"(addr));
}
#define MMA_F16(c, a, b0v, b1v) \
    asm volatile("mma.sync.aligned.m16n8k16.row.col.f32.f16.f16.f32 " \
                 "{%0,%1,%2,%3},{%4,%5,%6,%7},{%8,%9},{%0,%1,%2,%3};" \
                 : "+f"((c)[0]), "+f"((c)[1]), "+f"((c)[2]), "+f"((c)[3]) \
                 : "r"((a)[0]), "r"((a)[1]), "r"((a)[2]), "r"((a)[3]), \
                   "r"(b0v), "r"(b1v))

// ---------------- EDT row pass (mask fused) ----------------
__global__ void k_edt_row(const float* __restrict__ logits, const int* __restrict__ tr) {
    int idx = blockIdx.x*blockDim.x + threadIdx.x;
    if (idx >= NIMG*IH) return;
    int img = idx / IH, i = idx % IH;
    float* gf = d_g2fg + (size_t)img*NPIX + (size_t)i*IW;
    float* gb = d_g2bg + (size_t)img*NPIX + (size_t)i*IW;
    const float* l0p = logits + ((size_t)img*2)*NPIX + (size_t)i*IW;
    const float* l1p = l0p + NPIX;
    const int*   trp = tr + (size_t)(img-2)*NPIX + (size_t)i*IW;
    bool islog = (img < 2);

    float lf = -BIGF, lb = -BIGF;
    for (int j = 0; j < IW; j++) {
        bool mz = islog ? !(l1p[j] > l0p[j]) : (trp[j] == 0);
        float jj = (float)j;
        if (mz) lf = jj; else lb = jj;
        gf[j] = jj - lf;
        gb[j] = jj - lb;
    }
    float rf = BIGF, rb = BIGF;
    for (int j = IW-1; j >= 0; j--) {
        bool mz = islog ? !(l1p[j] > l0p[j]) : (trp[j] == 0);
        float jj = (float)j;
        if (mz) rf = jj; else rb = jj;
        float g1 = fminf(fminf(gf[j], rf - jj), BIGF);
        float g2 = fminf(fminf(gb[j], rb - jj), BIGF);
        gf[j] = g1*g1;
        gb[j] = g2*g2;
    }
}

// ---------------- EDT column pass + SDM + patch-split write ----------------
__global__ void k_edt_col() {
    int idx = blockIdx.x*blockDim.x + threadIdx.x;
    if (idx >= NIMG*NPIX) return;
    int img = idx / NPIX, r = idx % NPIX;
    int i = r / IW, j = r % IW;
    const float* gf = d_g2fg + (size_t)img*NPIX;
    const float* gb = d_g2bg + (size_t)img*NPIX;
    float mf = 3.4e38f, mb = 3.4e38f;
    float fi = (float)i;
    for (int ii = 0; ii < IH; ii++) {
        float off = fi - (float)ii; off *= off;
        mf = fminf(mf, gf[(size_t)ii*IW + j] + off);
        mb = fminf(mb, gb[(size_t)ii*IW + j] + off);
    }
    float v = sqrtf(mb) - sqrtf(mf);
    int t = (i >> 4)*24 + (j >> 4);
    int k = ((i & 15) << 4) + (j & 15);
    size_t o = (size_t)img*NPATCH*256 + (size_t)t*256 + k;
    split2h(v, PS, d_p0[o], d_p1[o]);
}

// ---------------- weight prep ----------------
__global__ void k_wsumT(const float* __restrict__ pw) {
    int idx = blockIdx.x*blockDim.x + threadIdx.x;
    if (idx >= DM*256) return;
    int o = idx / 256, k = idx % 256;
    float v = pw[(size_t)k*DM + o] + pw[(size_t)(256+k)*DM + o] + pw[(size_t)(512+k)*DM + o];
    split2h(v, WS, d_ws0[idx], d_ws1[idx]);
}

__global__ void k_tsplit(const float* __restrict__ W, __half* __restrict__ T0,
                         __half* __restrict__ T1, int K, int N) {
    __shared__ float t[32][33];
    size_t off = (size_t)blockIdx.z * K * N;
    const float* w = W + off;
    int bx = blockIdx.x*32, by = blockIdx.y*32;
    int tx = threadIdx.x, ty = threadIdx.y;
    #pragma unroll
    for (int r = 0; r < 4; r++)
        t[ty + r*8][tx] = w[(size_t)(by + ty + r*8)*N + bx + tx];
    __syncthreads();
    #pragma unroll
    for (int r = 0; r < 4; r++) {
        int n = bx + ty + r*8, k = by + tx;
        float v = t[tx][ty + r*8];
        size_t o = off + (size_t)n*K + k;
        split2h(v, WS, T0[o], T1[o]);
    }
}

__global__ void k_assemble(const float* __restrict__ cls, const float* __restrict__ pos) {
    int idx = blockIdx.x*blockDim.x + threadIdx.x;
    if (idx >= BT*DM) return;
    int img = idx / (NT*DM);
    int rem = idx % (NT*DM);
    int t = rem / DM, c = rem % DM;
    float v = (t == 0) ? cls[c] : d_tok[((size_t)img*NPATCH + (t-1))*DM + c];
    d_x[idx] = v + pos[(size_t)t*DM + c];
}

// ---------------- layernorm ----------------
__global__ void k_ln(const float* __restrict__ in, float* __restrict__ out,
                     const float* __restrict__ g, const float* __restrict__ b,
                     int wout) {
    int row = blockIdx.x;
    int tid = threadIdx.x;
    const float* xr = in + (size_t)row*DM;
    __shared__ float red[256];
    float s = 0.f;
    for (int c = tid; c < DM; c += 256) s += xr[c];
    red[tid] = s; __syncthreads();
    for (int o = 128; o > 0; o >>= 1) { if (tid < o) red[tid] += red[tid+o]; __syncthreads(); }
    float mu = red[0] * (1.f/768.f);
    __syncthreads();
    float v = 0.f;
    for (int c = tid; c < DM; c += 256) { float dd = xr[c]-mu; v += dd*dd; }
    red[tid] = v; __syncthreads();
    for (int o = 128; o > 0; o >>= 1) { if (tid < o) red[tid] += red[tid+o]; __syncthreads(); }
    float rstd = rsqrtf(red[0] * (1.f/768.f) + 1e-6f);
    for (int c = tid; c < DM; c += 256) {
        float val = (xr[c]-mu)*rstd*g[c] + b[c];
        size_t o = (size_t)row*DM + c;
        if (wout) out[o] = val;
        split2h(val, AS, d_h0[o], d_h1[o]);
    }
}

// ---------------- shared epilogue ----------------
__device__ __forceinline__ void gemm_epilogue(
        float v0, float v1, int gr, int gc, int N, int epi,
        const float* res, float* C, __half* C0, __half* C1) {
    if (epi == 1 || epi == 3) {
        if (epi == 1) {
            v0 = 0.5f*v0*(1.f + erff(v0*0.70710678118654752f));
            v1 = 0.5f*v1*(1.f + erff(v1*0.70710678118654752f));
        }
        size_t o = (size_t)gr*N + gc;
        __half h00, h01, h10, h11;
        split2h(v0, AS, h00, h01);
        split2h(v1, AS, h10, h11);
        __half2 p0; p0.x = h00; p0.y = h10;
        __half2 p1; p1.x = h01; p1.y = h11;
        *(__half2*)&C0[o] = p0;
        *(__half2*)&C1[o] = p1;
    } else {
        if (epi == 2) {
            float2 r2 = *(const float2*)&res[(size_t)gr*N + gc];
            v0 += r2.x; v1 += r2.y;
        }
        *(float2*)&C[(size_t)gr*N + gc] = make_float2(v0, v1);
    }
}

// ================= GEMM A: 256 threads, 128x128 tile (qkv / fc1) ============
#define APL 10240u
#define BPL128 10240u
#define BUFB128 (2u*APL + 2u*BPL128)     // 40960
#define SMEM_GH (2u*BUFB128)             // 81920

__global__ __launch_bounds__(256, 2) void k_gemm_h(
        const __half* __restrict__ A0, const __half* __restrict__ A1,
        const __half* __restrict__ B0, const __half* __restrict__ B1,
        const float* __restrict__ bias, const float* __restrict__ res,
        float* __restrict__ C, __half* __restrict__ C0, __half* __restrict__ C1,
        int M, int N, int K, float inv, int epi) {
    extern __shared__ char smem[];
    uint32_t sb = s2u(smem);
    int tid = threadIdx.x, lane = tid & 31, warp = tid >> 5;
    int wm = (warp & 3)*32, wn = (warp >> 2)*64;
    int bm = blockIdx.y*128, bn = blockIdx.x*128;
    int g = lane >> 2, q = lane & 3;

    float acc[2][8][4];
    #pragma unroll
    for (int i=0;i<2;i++)
        #pragma unroll
        for (int j=0;j<8;j++)
            #pragma unroll
            for (int r=0;r<4;r++) acc[i][j][r]=0.f;

    int lrow = tid >> 2;
    int lc   = tid & 3;

    auto load_chunk = [&](int kt, int buf) {
        int k0 = kt * 32;
        uint32_t base = sb + (uint32_t)buf * BUFB128;
        const __half* Ap[2] = {A0, A1};
        const __half* Bp[2] = {B0, B1};
        #pragma unroll
        for (int p = 0; p < 2; p++) {
            #pragma unroll
            for (int l = 0; l < 2; l++) {
                int row = lrow + l*64;
                int gr = bm + row; if (gr >= M) gr = M - 1;
                CP16(base + p*APL + (uint32_t)(row*80 + lc*16),
                     Ap[p] + (size_t)gr*K + k0 + lc*8);
                CP16(base + 2*APL + p*BPL128 + (uint32_t)(row*80 + lc*16),
                     Bp[p] + (size_t)(bn + row)*K + k0 + lc*8);
            }
        }
    };

    int KT = K >> 5;
    load_chunk(0, 0);
    CPCOMMIT();
    for (int kt = 0; kt < KT; kt++) {
        CPWAIT0();
        __syncthreads();
        if (kt + 1 < KT) { load_chunk(kt + 1, (kt + 1) & 1); CPCOMMIT(); }
        uint32_t base = sb + (uint32_t)(kt & 1) * BUFB128;
        uint32_t aBase = base + (uint32_t)((wm + (lane & 15))*80 + (lane >> 4)*16);
        int bn8 = (lane & 7) + ((lane >> 4) << 3);
        uint32_t bBase = base + 2*APL + (uint32_t)((wn + bn8)*80 + ((lane >> 3) & 1)*16);
        #pragma unroll
        for (int ks = 0; ks < 2; ks++) {
            unsigned a0f[2][4], a1f[2][4];
            #pragma unroll
            for (int mi = 0; mi < 2; mi++) {
                ldsm4(a0f[mi][0],a0f[mi][1],a0f[mi][2],a0f[mi][3],
                      aBase + mi*1280u + ks*32u);
                ldsm4(a1f[mi][0],a1f[mi][1],a1f[mi][2],a1f[mi][3],
                      aBase + APL + mi*1280u + ks*32u);
            }
            #pragma unroll
            for (int nq = 0; nq < 4; nq++) {
                unsigned b0f[4], b1f[4];
                ldsm4(b0f[0],b0f[1],b0f[2],b0f[3], bBase + nq*1280u + ks*32u);
                ldsm4(b1f[0],b1f[1],b1f[2],b1f[3], bBase + BPL128 + nq*1280u + ks*32u);
                #pragma unroll
                for (int mi = 0; mi < 2; mi++)
                    #pragma unroll
                    for (int h = 0; h < 2; h++) {
                        MMA_F16(acc[mi][nq*2+h], a0f[mi], b0f[h*2], b0f[h*2+1]);
                        MMA_F16(acc[mi][nq*2+h], a0f[mi], b1f[h*2], b1f[h*2+1]);
                        MMA_F16(acc[mi][nq*2+h], a1f[mi], b0f[h*2], b0f[h*2+1]);
                    }
            }
        }
        __syncthreads();
    }

    #pragma unroll
    for (int mi = 0; mi < 2; mi++)
        #pragma unroll
        for (int rr = 0; rr < 2; rr++) {
            int gr = bm + wm + mi*16 + g + rr*8;
            if (gr >= M) continue;
            #pragma unroll
            for (int nj = 0; nj < 8; nj++) {
                int gc = bn + wn + nj*8 + 2*q;
                gemm_epilogue(acc[mi][nj][rr*2+0]*inv + bias[gc],
                              acc[mi][nj][rr*2+1]*inv + bias[gc+1],
                              gr, gc, N, epi, res, C, C0, C1);
            }
        }
}

// ================= GEMM W: 512 threads, 128x128 tile (patch / proj / fc2) ===
// 16 warps: 4M x 4N, warp tile 32x32. One CTA/SM, 16 warps for latency hiding.
__global__ __launch_bounds__(512, 1) void k_gemm_w(
        const __half* __restrict__ A0, const __half* __restrict__ A1,
        const __half* __restrict__ B0, const __half* __restrict__ B1,
        const float* __restrict__ bias, const float* __restrict__ res,
        float* __restrict__ C, __half* __restrict__ C0, __half* __restrict__ C1,
        int M, int N, int K, float inv, int epi) {
    extern __shared__ char smem[];
    uint32_t sb = s2u(smem);
    int tid = threadIdx.x, lane = tid & 31, warp = tid >> 5;
    int wm = (warp & 3)*32, wn = (warp >> 2)*32;
    int bm = blockIdx.y*128, bn = blockIdx.x*128;
    int g = lane >> 2, q = lane & 3;

    float acc[2][4][4];
    #pragma unroll
    for (int i=0;i<2;i++)
        #pragma unroll
        for (int j=0;j<4;j++)
            #pragma unroll
            for (int r=0;r<4;r++) acc[i][j][r]=0.f;

    int lrow = tid >> 2;     // 0..127
    int lc   = tid & 3;

    auto load_chunk = [&](int kt, int buf) {
        int k0 = kt * 32;
        uint32_t base = sb + (uint32_t)buf * BUFB128;
        const __half* Ap[2] = {A0, A1};
        const __half* Bp[2] = {B0, B1};
        int gr = bm + lrow; if (gr >= M) gr = M - 1;
        #pragma unroll
        for (int p = 0; p < 2; p++) {
            CP16(base + p*APL + (uint32_t)(lrow*80 + lc*16),
                 Ap[p] + (size_t)gr*K + k0 + lc*8);
            CP16(base + 2*APL + p*BPL128 + (uint32_t)(lrow*80 + lc*16),
                 Bp[p] + (size_t)(bn + lrow)*K + k0 + lc*8);
        }
    };

    int KT = K >> 5;
    load_chunk(0, 0);
    CPCOMMIT();
    for (int kt = 0; kt < KT; kt++) {
        CPWAIT0();
        __syncthreads();
        if (kt + 1 < KT) { load_chunk(kt + 1, (kt + 1) & 1); CPCOMMIT(); }
        uint32_t base = sb + (uint32_t)(kt & 1) * BUFB128;
        uint32_t aBase = base + (uint32_t)((wm + (lane & 15))*80 + (lane >> 4)*16);
        int bn8 = (lane & 7) + ((lane >> 4) << 3);
        uint32_t bBase = base + 2*APL + (uint32_t)((wn + bn8)*80 + ((lane >> 3) & 1)*16);
        #pragma unroll
        for (int ks = 0; ks < 2; ks++) {
            unsigned a0f[2][4], a1f[2][4];
            #pragma unroll
            for (int mi = 0; mi < 2; mi++) {
                ldsm4(a0f[mi][0],a0f[mi][1],a0f[mi][2],a0f[mi][3],
                      aBase + mi*1280u + ks*32u);
                ldsm4(a1f[mi][0],a1f[mi][1],a1f[mi][2],a1f[mi][3],
                      aBase + APL + mi*1280u + ks*32u);
            }
            #pragma unroll
            for (int nq = 0; nq < 2; nq++) {
                unsigned b0f[4], b1f[4];
                ldsm4(b0f[0],b0f[1],b0f[2],b0f[3], bBase + nq*1280u + ks*32u);
                ldsm4(b1f[0],b1f[1],b1f[2],b1f[3], bBase + BPL128 + nq*1280u + ks*32u);
                #pragma unroll
                for (int mi = 0; mi < 2; mi++)
                    #pragma unroll
                    for (int h = 0; h < 2; h++) {
                        MMA_F16(acc[mi][nq*2+h], a0f[mi], b0f[h*2], b0f[h*2+1]);
                        MMA_F16(acc[mi][nq*2+h], a0f[mi], b1f[h*2], b1f[h*2+1]);
                        MMA_F16(acc[mi][nq*2+h], a1f[mi], b0f[h*2], b0f[h*2+1]);
                    }
            }
        }
        __syncthreads();
    }

    #pragma unroll
    for (int mi = 0; mi < 2; mi++)
        #pragma unroll
        for (int rr = 0; rr < 2; rr++) {
            int gr = bm + wm + mi*16 + g + rr*8;
            if (gr >= M) continue;
            #pragma unroll
            for (int nj = 0; nj < 4; nj++) {
                int gc = bn + wn + nj*8 + 2*q;
                gemm_epilogue(acc[mi][nj][rr*2+0]*inv + bias[gc],
                              acc[mi][nj][rr*2+1]*inv + bias[gc+1],
                              gr, gc, N, epi, res, C, C0, C1);
            }
        }
}

// ================= attention scores =================
#define SROW 144u
#define SPL  (128u*SROW)
#define SMEM_SC (4u*SPL)

__global__ __launch_bounds__(256, 2) void k_scores_h() {
    extern __shared__ char smem[];
    uint32_t sb = s2u(smem);
    int bh = blockIdx.z, b = bh / NHD, h = bh % NHD;
    int m0 = blockIdx.y*128, n0 = blockIdx.x*128;
    int tid = threadIdx.x, lane = tid & 31, warp = tid >> 5;
    int wm = (warp & 3)*32, wn = (warp >> 2)*64;
    int g = lane >> 2, q = lane & 3;

    #pragma unroll
    for (int l = 0; l < 4; l++) {
        int id = tid + l*256;
        int row = id >> 3, c = id & 7;
        int gm = m0 + row; if (gm >= NT) gm = NT - 1;
        int gn = n0 + row; if (gn >= NT) gn = NT - 1;
        size_t qo = (size_t)(b*NT + gm)*2304 + h*64 + c*8;
        size_t ko = (size_t)(b*NT + gn)*2304 + 768 + h*64 + c*8;
        uint32_t so = (uint32_t)(row*SROW + c*16);
        CP16(sb + so,          d_q0 + qo);
        CP16(sb + SPL + so,    d_q1 + qo);
        CP16(sb + 2*SPL + so,  d_q0 + ko);
        CP16(sb + 3*SPL + so,  d_q1 + ko);
    }
    CPCOMMIT(); CPWAIT0();
    __syncthreads();

    float acc[2][8][4];
    #pragma unroll
    for (int i=0;i<2;i++)
        #pragma unroll
        for (int j=0;j<8;j++)
            #pragma unroll
            for (int r=0;r<4;r++) acc[i][j][r]=0.f;

    uint32_t aBase = sb + (uint32_t)((wm + (lane & 15))*SROW + (lane >> 4)*16);
    int bn8 = (lane & 7) + ((lane >> 4) << 3);
    uint32_t bBase = sb + 2*SPL + (uint32_t)((wn + bn8)*SROW + ((lane >> 3) & 1)*16);

    #pragma unroll
    for (int ks = 0; ks < 4; ks++) {
        unsigned a0f[2][4], a1f[2][4];
        #pragma unroll
        for (int mi = 0; mi < 2; mi++) {
            ldsm4(a0f[mi][0],a0f[mi][1],a0f[mi][2],a0f[mi][3],
                  aBase + mi*16*SROW + ks*32u);
            ldsm4(a1f[mi][0],a1f[mi][1],a1f[mi][2],a1f[mi][3],
                  aBase + SPL + mi*16*SROW + ks*32u);
        }
        #pragma unroll
        for (int nq = 0; nq < 4; nq++) {
            unsigned b0f[4], b1f[4];
            ldsm4(b0f[0],b0f[1],b0f[2],b0f[3], bBase + nq*16*SROW + ks*32u);
            ldsm4(b1f[0],b1f[1],b1f[2],b1f[3], bBase + SPL + nq*16*SROW + ks*32u);
            #pragma unroll
            for (int mi = 0; mi < 2; mi++)
                #pragma unroll
                for (int hh = 0; hh < 2; hh++) {
                    MMA_F16(acc[mi][nq*2+hh], a0f[mi], b0f[hh*2], b0f[hh*2+1]);
                    MMA_F16(acc[mi][nq*2+hh], a0f[mi], b1f[hh*2], b1f[hh*2+1]);
                    MMA_F16(acc[mi][nq*2+hh], a1f[mi], b0f[hh*2], b0f[hh*2+1]);
                }
        }
    }

    const float SCL = 0.125f/(AS*AS);
    float* sbase = d_S + (size_t)bh*NT*NT;
    #pragma unroll
    for (int mi = 0; mi < 2; mi++)
        #pragma unroll
        for (int rr = 0; rr < 2; rr++) {
            int gm = m0 + wm + mi*16 + g + rr*8;
            if (gm >= NT) continue;
            #pragma unroll
            for (int nj = 0; nj < 8; nj++) {
                int gc = n0 + wn + nj*8 + 2*q;
                if (gc < NT)   sbase[(size_t)gm*NT + gc]   = acc[mi][nj][rr*2+0]*SCL;
                if (gc+1 < NT) sbase[(size_t)gm*NT + gc+1] = acc[mi][nj][rr*2+1]*SCL;
            }
        }
}

// ---------------- softmax ----------------
__global__ void k_softmax() {
    size_t row = blockIdx.x;
    const float* s = d_S + row*NT;
    __half* o0 = d_S0 + row*SP;
    __half* o1 = d_S1 + row*SP;
    int tid = threadIdx.x;
    __shared__ float red[128];
    float v[5];
    float mx = -3.4e38f;
    #pragma unroll
    for (int i = 0; i < 5; i++) {
        int c = tid + i*128;
        v[i] = (c < NT) ? s[c] : -3.4e38f;
        mx = fmaxf(mx, v[i]);
    }
    red[tid] = mx; __syncthreads();
    for (int o = 64; o > 0; o >>= 1) { if (tid < o) red[tid] = fmaxf(red[tid], red[tid+o]); __syncthreads(); }
    mx = red[0]; __syncthreads();
    float sum = 0.f;
    #pragma unroll
    for (int i = 0; i < 5; i++) { v[i] = __expf(v[i] - mx); sum += v[i]; }
    red[tid] = sum; __syncthreads();
    for (int o = 64; o > 0; o >>= 1) { if (tid < o) red[tid] += red[tid+o]; __syncthreads(); }
    float inv = SS / red[0];
    #pragma unroll
    for (int i = 0; i < 5; i++) {
        int c = tid + i*128;
        float p = v[i] * inv;
        __half h0 = __float2half_rn(p);
        o0[c] = h0;
        o1[c] = __float2half_rn(p - __half2float(h0));
    }
}

// ================= AV =================
#define AVAR 80u
#define AVAPL (128u*AVAR)
#define AVBR 144u
#define AVBPL (32u*AVBR)
#define AVBUF (2u*AVAPL + 2u*AVBPL)
#define SMEM_AV (2u*AVBUF)

__global__ __launch_bounds__(256, 2) void k_av_h() {
    extern __shared__ char smem[];
    uint32_t sb = s2u(smem);
    int bh = blockIdx.y, b = bh / NHD, h = bh % NHD;
    int m0 = blockIdx.x*128;
    int tid = threadIdx.x, lane = tid & 31, warp = tid >> 5;
    int wm = (warp & 3)*32, wn = (warp >> 2)*32;
    int g = lane >> 2, q = lane & 3;

    float acc[2][4][4];
    #pragma unroll
    for (int i=0;i<2;i++)
        #pragma unroll
        for (int j=0;j<4;j++)
            #pragma unroll
            for (int r=0;r<4;r++) acc[i][j][r]=0.f;

    const __half* S0b = d_S0 + (size_t)bh*NT*SP;
    const __half* S1b = d_S1 + (size_t)bh*NT*SP;

    auto load_chunk = [&](int kt, int buf) {
        int k0 = kt * 32;
        uint32_t base = sb + (uint32_t)buf * AVBUF;
        #pragma unroll
        for (int l = 0; l < 2; l++) {
            int id = tid + l*256;
            int row = id >> 2, c = id & 3;
            int gm = m0 + row; if (gm >= NT) gm = NT - 1;
            size_t so = (size_t)gm*SP + k0 + c*8;
            uint32_t d = (uint32_t)(row*AVAR + c*16);
            CP16(base + d,          S0b + so);
            CP16(base + AVAPL + d,  S1b + so);
        }
        {
            int row = tid >> 3, c = tid & 7;
            int gk = k0 + row; if (gk >= NT) gk = NT - 1;
            size_t vo = (size_t)(b*NT + gk)*2304 + 1536 + h*64 + c*8;
            uint32_t d = (uint32_t)(row*AVBR + c*16);
            CP16(base + 2*AVAPL + d,          d_q0 + vo);
            CP16(base + 2*AVAPL + AVBPL + d,  d_q1 + vo);
        }
    };

    const int KT = (NT + 31) / 32;   // 19
    load_chunk(0, 0);
    CPCOMMIT();
    for (int kt = 0; kt < KT; kt++) {
        CPWAIT0();
        __syncthreads();
        if (kt + 1 < KT) { load_chunk(kt + 1, (kt + 1) & 1); CPCOMMIT(); }
        uint32_t base = sb + (uint32_t)(kt & 1) * AVBUF;
        uint32_t aBase = base + (uint32_t)((wm + (lane & 15))*AVAR + (lane >> 4)*16);
        uint32_t bBase = base + 2*AVAPL +
                         (uint32_t)((lane & 15)*AVBR + wn*2 + (lane >> 4)*16);
        #pragma unroll
        for (int ks = 0; ks < 2; ks++) {
            unsigned a0f[2][4], a1f[2][4];
            #pragma unroll
            for (int mi = 0; mi < 2; mi++) {
                ldsm4(a0f[mi][0],a0f[mi][1],a0f[mi][2],a0f[mi][3],
                      aBase + mi*16*AVAR + ks*32u);
                ldsm4(a1f[mi][0],a1f[mi][1],a1f[mi][2],a1f[mi][3],
                      aBase + AVAPL + mi*16*AVAR + ks*32u);
            }
            #pragma unroll
            for (int nq = 0; nq < 2; nq++) {
                unsigned b0f[4], b1f[4];
                uint32_t ba = bBase + ks*16*AVBR + nq*32u;
                ldsm4t(b0f[0],b0f[1],b0f[2],b0f[3], ba);
                ldsm4t(b1f[0],b1f[1],b1f[2],b1f[3], ba + AVBPL);
                #pragma unroll
                for (int mi = 0; mi < 2; mi++)
                    #pragma unroll
                    for (int hh = 0; hh < 2; hh++) {
                        MMA_F16(acc[mi][nq*2+hh], a0f[mi], b0f[hh*2], b0f[hh*2+1]);
                        MMA_F16(acc[mi][nq*2+hh], a0f[mi], b1f[hh*2], b1f[hh*2+1]);
                        MMA_F16(acc[mi][nq*2+hh], a1f[mi], b0f[hh*2], b0f[hh*2+1]);
                    }
            }
        }
        __syncthreads();
    }

    const float INV_AV = 1.f/(SS*AS);
    #pragma unroll
    for (int mi = 0; mi < 2; mi++)
        #pragma unroll
        for (int rr = 0; rr < 2; rr++) {
            int gm = m0 + wm + mi*16 + g + rr*8;
            if (gm >= NT) continue;
            #pragma unroll
            for (int nj = 0; nj < 4; nj++) {
                int gc = wn + nj*8 + 2*q;
                size_t o = (size_t)(b*NT + gm)*DM + h*64 + gc;
                float v0 = acc[mi][nj][rr*2+0]*INV_AV;
                float v1 = acc[mi][nj][rr*2+1]*INV_AV;
                __half h00, h01, h10, h11;
                split2h(v0, AS, h00, h01);
                split2h(v1, AS, h10, h11);
                __half2 p0; p0.x = h00; p0.y = h10;
                __half2 p1; p1.x = h01; p1.y = h11;
                *(__half2*)&d_a0[o] = p0;
                *(__half2*)&d_a1[o] = p1;
            }
        }
}

// ---------------- final cosine loss ----------------
__global__ void k_loss(float* out) {
    __shared__ float sd[256], sa[256], sb2[256];
    int tid = threadIdx.x;
    float coss[2];
    for (int b = 0; b < 2; b++) {
        const float* fp = d_h + (size_t)b*NT*DM;
        const float* ft = d_h + (size_t)(2+b)*NT*DM;
        float dt = 0.f, na = 0.f, nb = 0.f;
        for (int c = tid; c < DM; c += 256) {
            float a = fp[c], bb = ft[c];
            dt += a*bb; na += a*a; nb += bb*bb;
        }
        sd[tid] = dt; sa[tid] = na; sb2[tid] = nb; __syncthreads();
        for (int o = 128; o > 0; o >>= 1) {
            if (tid < o) { sd[tid]+=sd[tid+o]; sa[tid]+=sa[tid+o]; sb2[tid]+=sb2[tid+o]; }
            __syncthreads();
        }
        coss[b] = sd[0] / (fmaxf(sqrtf(sa[0]), 1e-8f) * fmaxf(sqrtf(sb2[0]), 1e-8f));
        __syncthreads();
    }
    if (tid == 0) out[0] = 1.f - 0.5f*(coss[0] + coss[1]);
}

// ---------------- launch ----------------
extern "C" void kernel_launch(void* const* d_in, const int* in_sizes, int n_in,
                              void* d_out, int out_size) {
    const float* pred   = (const float*)d_in[0];
    const int*   tru    = (const int*)  d_in[1];
    const float* patchw = (const float*)d_in[2];
    const float* patchb = (const float*)d_in[3];
    const float* cls    = (const float*)d_in[4];
    const float* pos    = (const float*)d_in[5];
    const float* ln1g   = (const float*)d_in[6];
    const float* ln1b   = (const float*)d_in[7];
    const float* qkvw   = (const float*)d_in[8];
    const float* qkvb   = (const float*)d_in[9];
    const float* projw  = (const float*)d_in[10];
    const float* projb  = (const float*)d_in[11];
    const float* ln2g   = (const float*)d_in[12];
    const float* ln2b   = (const float*)d_in[13];
    const float* fc1w   = (const float*)d_in[14];
    const float* fc1b   = (const float*)d_in[15];
    const float* fc2w   = (const float*)d_in[16];
    const float* fc2b   = (const float*)d_in[17];
    const float* normg  = (const float*)d_in[18];
    const float* normb  = (const float*)d_in[19];

    float *px, *ph, *ptok;
    cudaGetSymbolAddress((void**)&px,   d_x);
    cudaGetSymbolAddress((void**)&ph,   d_h);
    cudaGetSymbolAddress((void**)&ptok, d_tok);

    __half *h0,*h1,*a0,*a1,*m0,*m1,*p0,*p1,*qk0,*qk1;
    __half *ws0,*ws1,*q0,*q1,*pr0,*pr1,*f10,*f11,*f20,*f21;
    cudaGetSymbolAddress((void**)&h0, d_h0);   cudaGetSymbolAddress((void**)&h1, d_h1);
    cudaGetSymbolAddress((void**)&a0, d_a0);   cudaGetSymbolAddress((void**)&a1, d_a1);
    cudaGetSymbolAddress((void**)&m0, d_m0);   cudaGetSymbolAddress((void**)&m1, d_m1);
    cudaGetSymbolAddress((void**)&p0, d_p0);   cudaGetSymbolAddress((void**)&p1, d_p1);
    cudaGetSymbolAddress((void**)&qk0, d_q0);  cudaGetSymbolAddress((void**)&qk1, d_q1);
    cudaGetSymbolAddress((void**)&ws0, d_ws0); cudaGetSymbolAddress((void**)&ws1, d_ws1);
    cudaGetSymbolAddress((void**)&q0, d_qT0);  cudaGetSymbolAddress((void**)&q1, d_qT1);
    cudaGetSymbolAddress((void**)&pr0, d_pT0); cudaGetSymbolAddress((void**)&pr1, d_pT1);
    cudaGetSymbolAddress((void**)&f10, d_f1T0); cudaGetSymbolAddress((void**)&f11, d_f1T1);
    cudaGetSymbolAddress((void**)&f20, d_f2T0); cudaGetSymbolAddress((void**)&f21, d_f2T1);

    cudaFuncSetAttribute(k_gemm_h, cudaFuncAttributeMaxDynamicSharedMemorySize, SMEM_GH);
    cudaFuncSetAttribute(k_gemm_w, cudaFuncAttributeMaxDynamicSharedMemorySize, SMEM_GH);
    cudaFuncSetAttribute(k_scores_h, cudaFuncAttributeMaxDynamicSharedMemorySize, SMEM_SC);
    cudaFuncSetAttribute(k_av_h,     cudaFuncAttributeMaxDynamicSharedMemorySize, SMEM_AV);

    const float INV_W = 1.f/(AS*WS);
    const float INV_P = 1.f/(PS*WS);

    // front sequence: ncu capture (index 3) lands on the patch weight GEMM (512thd)
    k_edt_row<<<(NIMG*IH+127)/128, 128>>>(pred, tru);           // 0
    k_edt_col<<<(NIMG*NPIX+255)/256, 256>>>();                  // 1
    k_wsumT  <<<(DM*256+255)/256, 256>>>(patchw);               // 2
    k_gemm_w<<<dim3(DM/128, (NIMG*NPATCH)/128), 512, SMEM_GH>>>( // 3 <- ncu
        p0, p1, ws0, ws1, patchb, nullptr, ptok, nullptr, nullptr,
        NIMG*NPATCH, DM, 256, INV_P, 0);
    k_assemble<<<(BT*DM+255)/256, 256>>>(cls, pos);

    // weight prep
    k_tsplit<<<dim3(2304/32, DM/32, NL),  dim3(32,8)>>>(qkvw,  q0, q1, DM,   2304);
    k_tsplit<<<dim3(DM/32,   DM/32, NL),  dim3(32,8)>>>(projw, pr0, pr1, DM, DM);
    k_tsplit<<<dim3(3072/32, DM/32, NL),  dim3(32,8)>>>(fc1w,  f10, f11, DM, 3072);
    k_tsplit<<<dim3(DM/32, 3072/32, NL),  dim3(32,8)>>>(fc2w,  f20, f21, 3072, DM);

    int MT = (BT + 127) / 128;   // 19

    for (int l = 0; l < NL; l++) {
        k_ln<<<BT, 256>>>(px, ph, ln1g + (size_t)l*DM, ln1b + (size_t)l*DM, 0);
        k_gemm_h<<<dim3(2304/128, MT), 256, SMEM_GH>>>(
            h0, h1, q0 + (size_t)l*2304*DM, q1 + (size_t)l*2304*DM,
            qkvb + (size_t)l*2304, nullptr, nullptr, qk0, qk1,
            BT, 2304, DM, INV_W, 3);
        k_scores_h<<<dim3(5, 5, NIMG*NHD), 256, SMEM_SC>>>();
        k_softmax <<<NIMG*NHD*NT, 128>>>();
        k_av_h    <<<dim3(5, NIMG*NHD), 256, SMEM_AV>>>();
        k_gemm_w<<<dim3(DM/128, MT), 512, SMEM_GH>>>(
            a0, a1, pr0 + (size_t)l*DM*DM, pr1 + (size_t)l*DM*DM,
            projb + (size_t)l*DM, px, px, nullptr, nullptr,
            BT, DM, DM, INV_W, 2);
        k_ln<<<BT, 256>>>(px, ph, ln2g + (size_t)l*DM, ln2b + (size_t)l*DM, 0);
        k_gemm_h<<<dim3(3072/128, MT), 256, SMEM_GH>>>(
            h0, h1, f10 + (size_t)l*3072*DM, f11 + (size_t)l*3072*DM,
            fc1b + (size_t)l*3072, nullptr, nullptr, m0, m1,
            BT, 3072, DM, INV_W, 1);
        k_gemm_w<<<dim3(DM/128, MT), 512, SMEM_GH>>>(
            m0, m1, f20 + (size_t)l*DM*3072, f21 + (size_t)l*DM*3072,
            fc2b + (size_t)l*DM, px, px, nullptr, nullptr,
            BT, DM, 3072, INV_W, 2);
    }

    k_ln<<<BT, 256>>>(px, ph, normg, normb, 1);
    k_loss<<<1, 256>>>((float*)d_out);
}

// round 11
// speedup vs baseline: 1.1171x; 1.0659x over previous
#include <cuda_runtime.h>
#include <cuda_fp16.h>
#include <math.h>
#include <stdint.h>

// ---------------- problem constants ----------------
#define IH 384
#define IW 384
#define NPIX (IH*IW)
#define NIMG 4
#define NT 577
#define DM 768
#define NL 12
#define NHD 12
#define BT (NIMG*NT)    // 2308
#define NPATCH 576
#define BIGF 1e4f
#define SP 640

// static scales (fp16 range management)
#define WS  4096.f
#define AS  256.f
#define PS  32.f
#define SS  256.f

// ---------------- scratch (device globals) ----------------
__device__ float d_g2fg[NIMG*NPIX];
__device__ float d_g2bg[NIMG*NPIX];
__device__ float d_tok [NIMG*NPATCH*DM];
__device__ float d_x   [BT*DM];
__device__ float d_h   [BT*DM];
__device__ float d_S   [(size_t)NIMG*NHD*NT*NT];
__device__ float d_part[(size_t)4*BT*DM];          // split-K partials

__device__ __align__(128) __half d_h0[BT*DM],    d_h1[BT*DM];
__device__ __align__(128) __half d_a0[BT*DM],    d_a1[BT*DM];
__device__ __align__(128) __half d_m0[BT*3072],  d_m1[BT*3072];
__device__ __align__(128) __half d_p0[NIMG*NPATCH*256], d_p1[NIMG*NPATCH*256];
__device__ __align__(128) __half d_q0[BT*3*DM],  d_q1[BT*3*DM];
__device__ __align__(128) __half d_S0[(size_t)NIMG*NHD*NT*SP];
__device__ __align__(128) __half d_S1[(size_t)NIMG*NHD*NT*SP];

__device__ __align__(128) __half d_ws0[DM*256],       d_ws1[DM*256];
__device__ __align__(128) __half d_qT0[NL*2304*DM],   d_qT1[NL*2304*DM];
__device__ __align__(128) __half d_pT0[NL*DM*DM],     d_pT1[NL*DM*DM];
__device__ __align__(128) __half d_f1T0[NL*3072*DM],  d_f1T1[NL*3072*DM];
__device__ __align__(128) __half d_f2T0[NL*DM*3072],  d_f2T1[NL*DM*3072];

// ---------------- helpers ----------------
__device__ __forceinline__ void split2h(float x, float s, __half& h0, __half& h1) {
    float xs = x * s;
    h0 = __float2half_rn(xs);
    h1 = __float2half_rn(xs - __half2float(h0));
}
__device__ __forceinline__ uint32_t s2u(const void* p) {
    uint32_t a;
    asm("{ .reg .u64 t; cvta.to.shared.u64 t, %1; cvt.u32.u64 %0, t; }" : "=r"(a) : "l"(p));
    return a;
}
#define CP16(s,g)  asm volatile("cp.async.cg.shared.global [%0], [%1], 16;" :: "r"(s), "l"(g))
#define CPCOMMIT() asm volatile("cp.async.commit_group;")
#define CPWAIT0()  asm volatile("cp.async.wait_group 0;")

__device__ __forceinline__ void ldsm4(unsigned &r0, unsigned &r1, unsigned &r2,
                                      unsigned &r3, uint32_t addr) {
    asm volatile("ldmatrix.sync.aligned.m8n8.x4.shared.b16 {%0,%1,%2,%3}, [%4];"
        : "=r"(r0), "=r"(r1), "=r"(r2), "=r"(r3) : "r"(addr));
}
__device__ __forceinline__ void ldsm4t(unsigned &r0, unsigned &r1, unsigned &r2,
                                       unsigned &r3, uint32_t addr) {
    asm volatile("ldmatrix.sync.aligned.m8n8.x4.trans.shared.b16 {%0,%1,%2,%3}, [%4];"
        : "=r"(r0), "=r"(r1), "=r"(r2), "=r"(r3) : "r"(addr));
}
#define MMA_F16(c, a, b0v, b1v) \
    asm volatile("mma.sync.aligned.m16n8k16.row.col.f32.f16.f16.f32 " \
                 "{%0,%1,%2,%3},{%4,%5,%6,%7},{%8,%9},{%0,%1,%2,%3};" \
                 : "+f"((c)[0]), "+f"((c)[1]), "+f"((c)[2]), "+f"((c)[3]) \
                 : "r"((a)[0]), "r"((a)[1]), "r"((a)[2]), "r"((a)[3]), \
                   "r"(b0v), "r"(b1v))

// ---------------- EDT row pass (mask fused) ----------------
__global__ void k_edt_row(const float* __restrict__ logits, const int* __restrict__ tr) {
    int idx = blockIdx.x*blockDim.x + threadIdx.x;
    if (idx >= NIMG*IH) return;
    int img = idx / IH, i = idx % IH;
    float* gf = d_g2fg + (size_t)img*NPIX + (size_t)i*IW;
    float* gb = d_g2bg + (size_t)img*NPIX + (size_t)i*IW;
    const float* l0p = logits + ((size_t)img*2)*NPIX + (size_t)i*IW;
    const float* l1p = l0p + NPIX;
    const int*   trp = tr + (size_t)(img-2)*NPIX + (size_t)i*IW;
    bool islog = (img < 2);

    float lf = -BIGF, lb = -BIGF;
    for (int j = 0; j < IW; j++) {
        bool mz = islog ? !(l1p[j] > l0p[j]) : (trp[j] == 0);
        float jj = (float)j;
        if (mz) lf = jj; else lb = jj;
        gf[j] = jj - lf;
        gb[j] = jj - lb;
    }
    float rf = BIGF, rb = BIGF;
    for (int j = IW-1; j >= 0; j--) {
        bool mz = islog ? !(l1p[j] > l0p[j]) : (trp[j] == 0);
        float jj = (float)j;
        if (mz) rf = jj; else rb = jj;
        float g1 = fminf(fminf(gf[j], rf - jj), BIGF);
        float g2 = fminf(fminf(gb[j], rb - jj), BIGF);
        gf[j] = g1*g1;
        gb[j] = g2*g2;
    }
}

// ---------------- EDT column pass + SDM + patch-split write ----------------
__global__ void k_edt_col() {
    int idx = blockIdx.x*blockDim.x + threadIdx.x;
    if (idx >= NIMG*NPIX) return;
    int img = idx / NPIX, r = idx % NPIX;
    int i = r / IW, j = r % IW;
    const float* gf = d_g2fg + (size_t)img*NPIX;
    const float* gb = d_g2bg + (size_t)img*NPIX;
    float mf = 3.4e38f, mb = 3.4e38f;
    float fi = (float)i;
    for (int ii = 0; ii < IH; ii++) {
        float off = fi - (float)ii; off *= off;
        mf = fminf(mf, gf[(size_t)ii*IW + j] + off);
        mb = fminf(mb, gb[(size_t)ii*IW + j] + off);
    }
    float v = sqrtf(mb) - sqrtf(mf);
    int t = (i >> 4)*24 + (j >> 4);
    int k = ((i & 15) << 4) + (j & 15);
    size_t o = (size_t)img*NPATCH*256 + (size_t)t*256 + k;
    split2h(v, PS, d_p0[o], d_p1[o]);
}

// ---------------- weight prep ----------------
__global__ void k_wsumT(const float* __restrict__ pw) {
    int idx = blockIdx.x*blockDim.x + threadIdx.x;
    if (idx >= DM*256) return;
    int o = idx / 256, k = idx % 256;
    float v = pw[(size_t)k*DM + o] + pw[(size_t)(256+k)*DM + o] + pw[(size_t)(512+k)*DM + o];
    split2h(v, WS, d_ws0[idx], d_ws1[idx]);
}

__global__ void k_tsplit(const float* __restrict__ W, __half* __restrict__ T0,
                         __half* __restrict__ T1, int K, int N) {
    __shared__ float t[32][33];
    size_t off = (size_t)blockIdx.z * K * N;
    const float* w = W + off;
    int bx = blockIdx.x*32, by = blockIdx.y*32;
    int tx = threadIdx.x, ty = threadIdx.y;
    #pragma unroll
    for (int r = 0; r < 4; r++)
        t[ty + r*8][tx] = w[(size_t)(by + ty + r*8)*N + bx + tx];
    __syncthreads();
    #pragma unroll
    for (int r = 0; r < 4; r++) {
        int n = bx + ty + r*8, k = by + tx;
        float v = t[tx][ty + r*8];
        size_t o = off + (size_t)n*K + k;
        split2h(v, WS, T0[o], T1[o]);
    }
}

__global__ void k_assemble(const float* __restrict__ cls, const float* __restrict__ pos) {
    int idx = blockIdx.x*blockDim.x + threadIdx.x;
    if (idx >= BT*DM) return;
    int img = idx / (NT*DM);
    int rem = idx % (NT*DM);
    int t = rem / DM, c = rem % DM;
    float v = (t == 0) ? cls[c] : d_tok[((size_t)img*NPATCH + (t-1))*DM + c];
    d_x[idx] = v + pos[(size_t)t*DM + c];
}

// ---------------- layernorm ----------------
__global__ void k_ln(const float* __restrict__ in, float* __restrict__ out,
                     const float* __restrict__ g, const float* __restrict__ b,
                     int wout) {
    int row = blockIdx.x;
    int tid = threadIdx.x;
    const float* xr = in + (size_t)row*DM;
    __shared__ float red[256];
    float s = 0.f;
    for (int c = tid; c < DM; c += 256) s += xr[c];
    red[tid] = s; __syncthreads();
    for (int o = 128; o > 0; o >>= 1) { if (tid < o) red[tid] += red[tid+o]; __syncthreads(); }
    float mu = red[0] * (1.f/768.f);
    __syncthreads();
    float v = 0.f;
    for (int c = tid; c < DM; c += 256) { float dd = xr[c]-mu; v += dd*dd; }
    red[tid] = v; __syncthreads();
    for (int o = 128; o > 0; o >>= 1) { if (tid < o) red[tid] += red[tid+o]; __syncthreads(); }
    float rstd = rsqrtf(red[0] * (1.f/768.f) + 1e-6f);
    for (int c = tid; c < DM; c += 256) {
        float val = (xr[c]-mu)*rstd*g[c] + b[c];
        size_t o = (size_t)row*DM + c;
        if (wout) out[o] = val;
        split2h(val, AS, d_h0[o], d_h1[o]);
    }
}

// ---------------- shared epilogue ----------------
__device__ __forceinline__ void gemm_epilogue(
        float v0, float v1, int gr, int gc, int N, int epi,
        const float* res, float* C, __half* C0, __half* C1) {
    if (epi == 1 || epi == 3) {
        if (epi == 1) {
            v0 = 0.5f*v0*(1.f + erff(v0*0.70710678118654752f));
            v1 = 0.5f*v1*(1.f + erff(v1*0.70710678118654752f));
        }
        size_t o = (size_t)gr*N + gc;
        __half h00, h01, h10, h11;
        split2h(v0, AS, h00, h01);
        split2h(v1, AS, h10, h11);
        __half2 p0; p0.x = h00; p0.y = h10;
        __half2 p1; p1.x = h01; p1.y = h11;
        *(__half2*)&C0[o] = p0;
        *(__half2*)&C1[o] = p1;
    } else {
        if (epi == 2) {
            float2 r2 = *(const float2*)&res[(size_t)gr*N + gc];
            v0 += r2.x; v1 += r2.y;
        }
        *(float2*)&C[(size_t)gr*N + gc] = make_float2(v0, v1);
    }
}

// ================= GEMM A: 256 threads, 128x128 tile, optional split-K ======
// epi: 0 bias->C; 1 gelu->C0/C1; 2 bias+res->C; 3 bias->C0/C1;
//      4 raw partial -> C (+ blockIdx.z * M*N), no bias/inv.
// K = split length, LDK = full row stride; blockIdx.z picks the K-slice.
#define APL 10240u
#define BPL128 10240u
#define BUFB128 (2u*APL + 2u*BPL128)
#define SMEM_GH (2u*BUFB128)

__global__ __launch_bounds__(256, 2) void k_gemm_h(
        const __half* __restrict__ A0, const __half* __restrict__ A1,
        const __half* __restrict__ B0, const __half* __restrict__ B1,
        const float* __restrict__ bias, const float* __restrict__ res,
        float* __restrict__ C, __half* __restrict__ C0, __half* __restrict__ C1,
        int M, int N, int K, int LDK, float inv, int epi) {
    extern __shared__ char smem[];
    uint32_t sb = s2u(smem);
    int tid = threadIdx.x, lane = tid & 31, warp = tid >> 5;
    int wm = (warp & 3)*32, wn = (warp >> 2)*64;
    int bm = blockIdx.y*128, bn = blockIdx.x*128;
    size_t koff = (size_t)blockIdx.z * K;
    int g = lane >> 2, q = lane & 3;

    float acc[2][8][4];
    #pragma unroll
    for (int i=0;i<2;i++)
        #pragma unroll
        for (int j=0;j<8;j++)
            #pragma unroll
            for (int r=0;r<4;r++) acc[i][j][r]=0.f;

    int lrow = tid >> 2;
    int lc   = tid & 3;

    auto load_chunk = [&](int kt, int buf) {
        int k0 = kt * 32;
        uint32_t base = sb + (uint32_t)buf * BUFB128;
        const __half* Ap[2] = {A0, A1};
        const __half* Bp[2] = {B0, B1};
        #pragma unroll
        for (int p = 0; p < 2; p++) {
            #pragma unroll
            for (int l = 0; l < 2; l++) {
                int row = lrow + l*64;
                int gr = bm + row; if (gr >= M) gr = M - 1;
                CP16(base + p*APL + (uint32_t)(row*80 + lc*16),
                     Ap[p] + (size_t)gr*LDK + koff + k0 + lc*8);
                CP16(base + 2*APL + p*BPL128 + (uint32_t)(row*80 + lc*16),
                     Bp[p] + (size_t)(bn + row)*LDK + koff + k0 + lc*8);
            }
        }
    };

    int KT = K >> 5;
    load_chunk(0, 0);
    CPCOMMIT();
    for (int kt = 0; kt < KT; kt++) {
        CPWAIT0();
        __syncthreads();
        if (kt + 1 < KT) { load_chunk(kt + 1, (kt + 1) & 1); CPCOMMIT(); }
        uint32_t base = sb + (uint32_t)(kt & 1) * BUFB128;
        uint32_t aBase = base + (uint32_t)((wm + (lane & 15))*80 + (lane >> 4)*16);
        int bn8 = (lane & 7) + ((lane >> 4) << 3);
        uint32_t bBase = base + 2*APL + (uint32_t)((wn + bn8)*80 + ((lane >> 3) & 1)*16);
        #pragma unroll
        for (int ks = 0; ks < 2; ks++) {
            unsigned a0f[2][4], a1f[2][4];
            #pragma unroll
            for (int mi = 0; mi < 2; mi++) {
                ldsm4(a0f[mi][0],a0f[mi][1],a0f[mi][2],a0f[mi][3],
                      aBase + mi*1280u + ks*32u);
                ldsm4(a1f[mi][0],a1f[mi][1],a1f[mi][2],a1f[mi][3],
                      aBase + APL + mi*1280u + ks*32u);
            }
            #pragma unroll
            for (int nq = 0; nq < 4; nq++) {
                unsigned b0f[4], b1f[4];
                ldsm4(b0f[0],b0f[1],b0f[2],b0f[3], bBase + nq*1280u + ks*32u);
                ldsm4(b1f[0],b1f[1],b1f[2],b1f[3], bBase + BPL128 + nq*1280u + ks*32u);
                #pragma unroll
                for (int mi = 0; mi < 2; mi++)
                    #pragma unroll
                    for (int h = 0; h < 2; h++) {
                        MMA_F16(acc[mi][nq*2+h], a0f[mi], b0f[h*2], b0f[h*2+1]);
                        MMA_F16(acc[mi][nq*2+h], a0f[mi], b1f[h*2], b1f[h*2+1]);
                        MMA_F16(acc[mi][nq*2+h], a1f[mi], b0f[h*2], b0f[h*2+1]);
                    }
            }
        }
    }
    __syncthreads();

    size_t pofs = (size_t)blockIdx.z * M * N;
    #pragma unroll
    for (int mi = 0; mi < 2; mi++)
        #pragma unroll
        for (int rr = 0; rr < 2; rr++) {
            int gr = bm + wm + mi*16 + g + rr*8;
            if (gr >= M) continue;
            #pragma unroll
            for (int nj = 0; nj < 8; nj++) {
                int gc = bn + wn + nj*8 + 2*q;
                if (epi == 4) {
                    *(float2*)&C[pofs + (size_t)gr*N + gc] =
                        make_float2(acc[mi][nj][rr*2+0], acc[mi][nj][rr*2+1]);
                } else {
                    gemm_epilogue(acc[mi][nj][rr*2+0]*inv + bias[gc],
                                  acc[mi][nj][rr*2+1]*inv + bias[gc+1],
                                  gr, gc, N, epi, res, C, C0, C1);
                }
            }
        }
}

// ---------------- split-K reduce: C = (sum partials)*inv + bias [+ res] -----
__global__ void k_red(const float* __restrict__ P, int ns, float inv,
                      const float* __restrict__ bias, const float* __restrict__ res,
                      float* __restrict__ C, int N, int total4) {
    int t = blockIdx.x*blockDim.x + threadIdx.x;
    if (t >= total4) return;
    size_t i = (size_t)t * 4;
    size_t MN = (size_t)total4 * 4;
    float4 s = *(const float4*)&P[i];
    for (int z = 1; z < ns; z++) {
        float4 p = *(const float4*)&P[(size_t)z*MN + i];
        s.x += p.x; s.y += p.y; s.z += p.z; s.w += p.w;
    }
    int c = (int)(i % N);
    float4 b = *(const float4*)&bias[c];
    float4 r = *(const float4*)&res[i];
    s.x = s.x*inv + b.x + r.x;
    s.y = s.y*inv + b.y + r.y;
    s.z = s.z*inv + b.z + r.z;
    s.w = s.w*inv + b.w + r.w;
    *(float4*)&C[i] = s;
}

// ================= GEMM W: 512 threads, 128x128 tile (patch / proj) =========
__global__ __launch_bounds__(512, 1) void k_gemm_w(
        const __half* __restrict__ A0, const __half* __restrict__ A1,
        const __half* __restrict__ B0, const __half* __restrict__ B1,
        const float* __restrict__ bias, const float* __restrict__ res,
        float* __restrict__ C, __half* __restrict__ C0, __half* __restrict__ C1,
        int M, int N, int K, float inv, int epi) {
    extern __shared__ char smem[];
    uint32_t sb = s2u(smem);
    int tid = threadIdx.x, lane = tid & 31, warp = tid >> 5;
    int wm = (warp & 3)*32, wn = (warp >> 2)*32;
    int bm = blockIdx.y*128, bn = blockIdx.x*128;
    int g = lane >> 2, q = lane & 3;

    float acc[2][4][4];
    #pragma unroll
    for (int i=0;i<2;i++)
        #pragma unroll
        for (int j=0;j<4;j++)
            #pragma unroll
            for (int r=0;r<4;r++) acc[i][j][r]=0.f;

    int lrow = tid >> 2;
    int lc   = tid & 3;

    auto load_chunk = [&](int kt, int buf) {
        int k0 = kt * 32;
        uint32_t base = sb + (uint32_t)buf * BUFB128;
        const __half* Ap[2] = {A0, A1};
        const __half* Bp[2] = {B0, B1};
        int gr = bm + lrow; if (gr >= M) gr = M - 1;
        #pragma unroll
        for (int p = 0; p < 2; p++) {
            CP16(base + p*APL + (uint32_t)(lrow*80 + lc*16),
                 Ap[p] + (size_t)gr*K + k0 + lc*8);
            CP16(base + 2*APL + p*BPL128 + (uint32_t)(lrow*80 + lc*16),
                 Bp[p] + (size_t)(bn + lrow)*K + k0 + lc*8);
        }
    };

    int KT = K >> 5;
    load_chunk(0, 0);
    CPCOMMIT();
    for (int kt = 0; kt < KT; kt++) {
        CPWAIT0();
        __syncthreads();
        if (kt + 1 < KT) { load_chunk(kt + 1, (kt + 1) & 1); CPCOMMIT(); }
        uint32_t base = sb + (uint32_t)(kt & 1) * BUFB128;
        uint32_t aBase = base + (uint32_t)((wm + (lane & 15))*80 + (lane >> 4)*16);
        int bn8 = (lane & 7) + ((lane >> 4) << 3);
        uint32_t bBase = base + 2*APL + (uint32_t)((wn + bn8)*80 + ((lane >> 3) & 1)*16);
        #pragma unroll
        for (int ks = 0; ks < 2; ks++) {
            unsigned a0f[2][4], a1f[2][4];
            #pragma unroll
            for (int mi = 0; mi < 2; mi++) {
                ldsm4(a0f[mi][0],a0f[mi][1],a0f[mi][2],a0f[mi][3],
                      aBase + mi*1280u + ks*32u);
                ldsm4(a1f[mi][0],a1f[mi][1],a1f[mi][2],a1f[mi][3],
                      aBase + APL + mi*1280u + ks*32u);
            }
            #pragma unroll
            for (int nq = 0; nq < 2; nq++) {
                unsigned b0f[4], b1f[4];
                ldsm4(b0f[0],b0f[1],b0f[2],b0f[3], bBase + nq*1280u + ks*32u);
                ldsm4(b1f[0],b1f[1],b1f[2],b1f[3], bBase + BPL128 + nq*1280u + ks*32u);
                #pragma unroll
                for (int mi = 0; mi < 2; mi++)
                    #pragma unroll
                    for (int h = 0; h < 2; h++) {
                        MMA_F16(acc[mi][nq*2+h], a0f[mi], b0f[h*2], b0f[h*2+1]);
                        MMA_F16(acc[mi][nq*2+h], a0f[mi], b1f[h*2], b1f[h*2+1]);
                        MMA_F16(acc[mi][nq*2+h], a1f[mi], b0f[h*2], b0f[h*2+1]);
                    }
            }
        }
    }
    __syncthreads();

    #pragma unroll
    for (int mi = 0; mi < 2; mi++)
        #pragma unroll
        for (int rr = 0; rr < 2; rr++) {
            int gr = bm + wm + mi*16 + g + rr*8;
            if (gr >= M) continue;
            #pragma unroll
            for (int nj = 0; nj < 4; nj++) {
                int gc = bn + wn + nj*8 + 2*q;
                gemm_epilogue(acc[mi][nj][rr*2+0]*inv + bias[gc],
                              acc[mi][nj][rr*2+1]*inv + bias[gc+1],
                              gr, gc, N, epi, res, C, C0, C1);
            }
        }
}

// ================= attention scores =================
#define SROW 144u
#define SPL  (128u*SROW)
#define SMEM_SC (4u*SPL)

__global__ __launch_bounds__(256, 2) void k_scores_h() {
    extern __shared__ char smem[];
    uint32_t sb = s2u(smem);
    int bh = blockIdx.z, b = bh / NHD, h = bh % NHD;
    int m0 = blockIdx.y*128, n0 = blockIdx.x*128;
    int tid = threadIdx.x, lane = tid & 31, warp = tid >> 5;
    int wm = (warp & 3)*32, wn = (warp >> 2)*64;
    int g = lane >> 2, q = lane & 3;

    #pragma unroll
    for (int l = 0; l < 4; l++) {
        int id = tid + l*256;
        int row = id >> 3, c = id & 7;
        int gm = m0 + row; if (gm >= NT) gm = NT - 1;
        int gn = n0 + row; if (gn >= NT) gn = NT - 1;
        size_t qo = (size_t)(b*NT + gm)*2304 + h*64 + c*8;
        size_t ko = (size_t)(b*NT + gn)*2304 + 768 + h*64 + c*8;
        uint32_t so = (uint32_t)(row*SROW + c*16);
        CP16(sb + so,          d_q0 + qo);
        CP16(sb + SPL + so,    d_q1 + qo);
        CP16(sb + 2*SPL + so,  d_q0 + ko);
        CP16(sb + 3*SPL + so,  d_q1 + ko);
    }
    CPCOMMIT(); CPWAIT0();
    __syncthreads();

    float acc[2][8][4];
    #pragma unroll
    for (int i=0;i<2;i++)
        #pragma unroll
        for (int j=0;j<8;j++)
            #pragma unroll
            for (int r=0;r<4;r++) acc[i][j][r]=0.f;

    uint32_t aBase = sb + (uint32_t)((wm + (lane & 15))*SROW + (lane >> 4)*16);
    int bn8 = (lane & 7) + ((lane >> 4) << 3);
    uint32_t bBase = sb + 2*SPL + (uint32_t)((wn + bn8)*SROW + ((lane >> 3) & 1)*16);

    #pragma unroll
    for (int ks = 0; ks < 4; ks++) {
        unsigned a0f[2][4], a1f[2][4];
        #pragma unroll
        for (int mi = 0; mi < 2; mi++) {
            ldsm4(a0f[mi][0],a0f[mi][1],a0f[mi][2],a0f[mi][3],
                  aBase + mi*16*SROW + ks*32u);
            ldsm4(a1f[mi][0],a1f[mi][1],a1f[mi][2],a1f[mi][3],
                  aBase + SPL + mi*16*SROW + ks*32u);
        }
        #pragma unroll
        for (int nq = 0; nq < 4; nq++) {
            unsigned b0f[4], b1f[4];
            ldsm4(b0f[0],b0f[1],b0f[2],b0f[3], bBase + nq*16*SROW + ks*32u);
            ldsm4(b1f[0],b1f[1],b1f[2],b1f[3], bBase + SPL + nq*16*SROW + ks*32u);
            #pragma unroll
            for (int mi = 0; mi < 2; mi++)
                #pragma unroll
                for (int hh = 0; hh < 2; hh++) {
                    MMA_F16(acc[mi][nq*2+hh], a0f[mi], b0f[hh*2], b0f[hh*2+1]);
                    MMA_F16(acc[mi][nq*2+hh], a0f[mi], b1f[hh*2], b1f[hh*2+1]);
                    MMA_F16(acc[mi][nq*2+hh], a1f[mi], b0f[hh*2], b0f[hh*2+1]);
                }
        }
    }

    const float SCL = 0.125f/(AS*AS);
    float* sbase = d_S + (size_t)bh*NT*NT;
    #pragma unroll
    for (int mi = 0; mi < 2; mi++)
        #pragma unroll
        for (int rr = 0; rr < 2; rr++) {
            int gm = m0 + wm + mi*16 + g + rr*8;
            if (gm >= NT) continue;
            #pragma unroll
            for (int nj = 0; nj < 8; nj++) {
                int gc = n0 + wn + nj*8 + 2*q;
                if (gc < NT)   sbase[(size_t)gm*NT + gc]   = acc[mi][nj][rr*2+0]*SCL;
                if (gc+1 < NT) sbase[(size_t)gm*NT + gc+1] = acc[mi][nj][rr*2+1]*SCL;
            }
        }
}

// ---------------- softmax ----------------
__global__ void k_softmax() {
    size_t row = blockIdx.x;
    const float* s = d_S + row*NT;
    __half* o0 = d_S0 + row*SP;
    __half* o1 = d_S1 + row*SP;
    int tid = threadIdx.x;
    __shared__ float red[128];
    float v[5];
    float mx = -3.4e38f;
    #pragma unroll
    for (int i = 0; i < 5; i++) {
        int c = tid + i*128;
        v[i] = (c < NT) ? s[c] : -3.4e38f;
        mx = fmaxf(mx, v[i]);
    }
    red[tid] = mx; __syncthreads();
    for (int o = 64; o > 0; o >>= 1) { if (tid < o) red[tid] = fmaxf(red[tid], red[tid+o]); __syncthreads(); }
    mx = red[0]; __syncthreads();
    float sum = 0.f;
    #pragma unroll
    for (int i = 0; i < 5; i++) { v[i] = __expf(v[i] - mx); sum += v[i]; }
    red[tid] = sum; __syncthreads();
    for (int o = 64; o > 0; o >>= 1) { if (tid < o) red[tid] += red[tid+o]; __syncthreads(); }
    float inv = SS / red[0];
    #pragma unroll
    for (int i = 0; i < 5; i++) {
        int c = tid + i*128;
        float p = v[i] * inv;
        __half h0 = __float2half_rn(p);
        o0[c] = h0;
        o1[c] = __float2half_rn(p - __half2float(h0));
    }
}

// ================= AV =================
#define AVAR 80u
#define AVAPL (128u*AVAR)
#define AVBR 144u
#define AVBPL (32u*AVBR)
#define AVBUF (2u*AVAPL + 2u*AVBPL)
#define SMEM_AV (2u*AVBUF)

__global__ __launch_bounds__(256, 2) void k_av_h() {
    extern __shared__ char smem[];
    uint32_t sb = s2u(smem);
    int bh = blockIdx.y, b = bh / NHD, h = bh % NHD;
    int m0 = blockIdx.x*128;
    int tid = threadIdx.x, lane = tid & 31, warp = tid >> 5;
    int wm = (warp & 3)*32, wn = (warp >> 2)*32;
    int g = lane >> 2, q = lane & 3;

    float acc[2][4][4];
    #pragma unroll
    for (int i=0;i<2;i++)
        #pragma unroll
        for (int j=0;j<4;j++)
            #pragma unroll
            for (int r=0;r<4;r++) acc[i][j][r]=0.f;

    const __half* S0b = d_S0 + (size_t)bh*NT*SP;
    const __half* S1b = d_S1 + (size_t)bh*NT*SP;

    auto load_chunk = [&](int kt, int buf) {
        int k0 = kt * 32;
        uint32_t base = sb + (uint32_t)buf * AVBUF;
        #pragma unroll
        for (int l = 0; l < 2; l++) {
            int id = tid + l*256;
            int row = id >> 2, c = id & 3;
            int gm = m0 + row; if (gm >= NT) gm = NT - 1;
            size_t so = (size_t)gm*SP + k0 + c*8;
            uint32_t d = (uint32_t)(row*AVAR + c*16);
            CP16(base + d,          S0b + so);
            CP16(base + AVAPL + d,  S1b + so);
        }
        {
            int row = tid >> 3, c = tid & 7;
            int gk = k0 + row; if (gk >= NT) gk = NT - 1;
            size_t vo = (size_t)(b*NT + gk)*2304 + 1536 + h*64 + c*8;
            uint32_t d = (uint32_t)(row*AVBR + c*16);
            CP16(base + 2*AVAPL + d,          d_q0 + vo);
            CP16(base + 2*AVAPL + AVBPL + d,  d_q1 + vo);
        }
    };

    const int KT = (NT + 31) / 32;   // 19
    load_chunk(0, 0);
    CPCOMMIT();
    for (int kt = 0; kt < KT; kt++) {
        CPWAIT0();
        __syncthreads();
        if (kt + 1 < KT) { load_chunk(kt + 1, (kt + 1) & 1); CPCOMMIT(); }
        uint32_t base = sb + (uint32_t)(kt & 1) * AVBUF;
        uint32_t aBase = base + (uint32_t)((wm + (lane & 15))*AVAR + (lane >> 4)*16);
        uint32_t bBase = base + 2*AVAPL +
                         (uint32_t)((lane & 15)*AVBR + wn*2 + (lane >> 4)*16);
        #pragma unroll
        for (int ks = 0; ks < 2; ks++) {
            unsigned a0f[2][4], a1f[2][4];
            #pragma unroll
            for (int mi = 0; mi < 2; mi++) {
                ldsm4(a0f[mi][0],a0f[mi][1],a0f[mi][2],a0f[mi][3],
                      aBase + mi*16*AVAR + ks*32u);
                ldsm4(a1f[mi][0],a1f[mi][1],a1f[mi][2],a1f[mi][3],
                      aBase + AVAPL + mi*16*AVAR + ks*32u);
            }
            #pragma unroll
            for (int nq = 0; nq < 2; nq++) {
                unsigned b0f[4], b1f[4];
                uint32_t ba = bBase + ks*16*AVBR + nq*32u;
                ldsm4t(b0f[0],b0f[1],b0f[2],b0f[3], ba);
                ldsm4t(b1f[0],b1f[1],b1f[2],b1f[3], ba + AVBPL);
                #pragma unroll
                for (int mi = 0; mi < 2; mi++)
                    #pragma unroll
                    for (int hh = 0; hh < 2; hh++) {
                        MMA_F16(acc[mi][nq*2+hh], a0f[mi], b0f[hh*2], b0f[hh*2+1]);
                        MMA_F16(acc[mi][nq*2+hh], a0f[mi], b1f[hh*2], b1f[hh*2+1]);
                        MMA_F16(acc[mi][nq*2+hh], a1f[mi], b0f[hh*2], b0f[hh*2+1]);
                    }
            }
        }
    }
    __syncthreads();

    const float INV_AV = 1.f/(SS*AS);
    #pragma unroll
    for (int mi = 0; mi < 2; mi++)
        #pragma unroll
        for (int rr = 0; rr < 2; rr++) {
            int gm = m0 + wm + mi*16 + g + rr*8;
            if (gm >= NT) continue;
            #pragma unroll
            for (int nj = 0; nj < 4; nj++) {
                int gc = wn + nj*8 + 2*q;
                size_t o = (size_t)(b*NT + gm)*DM + h*64 + gc;
                float v0 = acc[mi][nj][rr*2+0]*INV_AV;
                float v1 = acc[mi][nj][rr*2+1]*INV_AV;
                __half h00, h01, h10, h11;
                split2h(v0, AS, h00, h01);
                split2h(v1, AS, h10, h11);
                __half2 p0; p0.x = h00; p0.y = h10;
                __half2 p1; p1.x = h01; p1.y = h11;
                *(__half2*)&d_a0[o] = p0;
                *(__half2*)&d_a1[o] = p1;
            }
        }
}

// ---------------- final cosine loss ----------------
__global__ void k_loss(float* out) {
    __shared__ float sd[256], sa[256], sb2[256];
    int tid = threadIdx.x;
    float coss[2];
    for (int b = 0; b < 2; b++) {
        const float* fp = d_h + (size_t)b*NT*DM;
        const float* ft = d_h + (size_t)(2+b)*NT*DM;
        float dt = 0.f, na = 0.f, nb = 0.f;
        for (int c = tid; c < DM; c += 256) {
            float a = fp[c], bb = ft[c];
            dt += a*bb; na += a*a; nb += bb*bb;
        }
        sd[tid] = dt; sa[tid] = na; sb2[tid] = nb; __syncthreads();
        for (int o = 128; o > 0; o >>= 1) {
            if (tid < o) { sd[tid]+=sd[tid+o]; sa[tid]+=sa[tid+o]; sb2[tid]+=sb2[tid+o]; }
            __syncthreads();
        }
        coss[b] = sd[0] / (fmaxf(sqrtf(sa[0]), 1e-8f) * fmaxf(sqrtf(sb2[0]), 1e-8f));
        __syncthreads();
    }
    if (tid == 0) out[0] = 1.f - 0.5f*(coss[0] + coss[1]);
}

// ---------------- launch ----------------
extern "C" void kernel_launch(void* const* d_in, const int* in_sizes, int n_in,
                              void* d_out, int out_size) {
    const float* pred   = (const float*)d_in[0];
    const int*   tru    = (const int*)  d_in[1];
    const float* patchw = (const float*)d_in[2];
    const float* patchb = (const float*)d_in[3];
    const float* cls    = (const float*)d_in[4];
    const float* pos    = (const float*)d_in[5];
    const float* ln1g   = (const float*)d_in[6];
    const float* ln1b   = (const float*)d_in[7];
    const float* qkvw   = (const float*)d_in[8];
    const float* qkvb   = (const float*)d_in[9];
    const float* projw  = (const float*)d_in[10];
    const float* projb  = (const float*)d_in[11];
    const float* ln2g   = (const float*)d_in[12];
    const float* ln2b   = (const float*)d_in[13];
    const float* fc1w   = (const float*)d_in[14];
    const float* fc1b   = (const float*)d_in[15];
    const float* fc2w   = (const float*)d_in[16];
    const float* fc2b   = (const float*)d_in[17];
    const float* normg  = (const float*)d_in[18];
    const float* normb  = (const float*)d_in[19];

    float *px, *ph, *ptok, *ppart;
    cudaGetSymbolAddress((void**)&px,    d_x);
    cudaGetSymbolAddress((void**)&ph,    d_h);
    cudaGetSymbolAddress((void**)&ptok,  d_tok);
    cudaGetSymbolAddress((void**)&ppart, d_part);

    __half *h0,*h1,*a0,*a1,*m0,*m1,*p0,*p1,*qk0,*qk1;
    __half *ws0,*ws1,*q0,*q1,*pr0,*pr1,*f10,*f11,*f20,*f21;
    cudaGetSymbolAddress((void**)&h0, d_h0);   cudaGetSymbolAddress((void**)&h1, d_h1);
    cudaGetSymbolAddress((void**)&a0, d_a0);   cudaGetSymbolAddress((void**)&a1, d_a1);
    cudaGetSymbolAddress((void**)&m0, d_m0);   cudaGetSymbolAddress((void**)&m1, d_m1);
    cudaGetSymbolAddress((void**)&p0, d_p0);   cudaGetSymbolAddress((void**)&p1, d_p1);
    cudaGetSymbolAddress((void**)&qk0, d_q0);  cudaGetSymbolAddress((void**)&qk1, d_q1);
    cudaGetSymbolAddress((void**)&ws0, d_ws0); cudaGetSymbolAddress((void**)&ws1, d_ws1);
    cudaGetSymbolAddress((void**)&q0, d_qT0);  cudaGetSymbolAddress((void**)&q1, d_qT1);
    cudaGetSymbolAddress((void**)&pr0, d_pT0); cudaGetSymbolAddress((void**)&pr1, d_pT1);
    cudaGetSymbolAddress((void**)&f10, d_f1T0); cudaGetSymbolAddress((void**)&f11, d_f1T1);
    cudaGetSymbolAddress((void**)&f20, d_f2T0); cudaGetSymbolAddress((void**)&f21, d_f2T1);

    cudaFuncSetAttribute(k_gemm_h, cudaFuncAttributeMaxDynamicSharedMemorySize, SMEM_GH);
    cudaFuncSetAttribute(k_gemm_w, cudaFuncAttributeMaxDynamicSharedMemorySize, SMEM_GH);
    cudaFuncSetAttribute(k_scores_h, cudaFuncAttributeMaxDynamicSharedMemorySize, SMEM_SC);
    cudaFuncSetAttribute(k_av_h,     cudaFuncAttributeMaxDynamicSharedMemorySize, SMEM_AV);

    const float INV_W = 1.f/(AS*WS);
    const float INV_P = 1.f/(PS*WS);

    // front sequence
    k_edt_row<<<(NIMG*IH+127)/128, 128>>>(pred, tru);
    k_edt_col<<<(NIMG*NPIX+255)/256, 256>>>();
    k_wsumT  <<<(DM*256+255)/256, 256>>>(patchw);
    k_gemm_w<<<dim3(DM/128, (NIMG*NPATCH)/128), 512, SMEM_GH>>>(
        p0, p1, ws0, ws1, patchb, nullptr, ptok, nullptr, nullptr,
        NIMG*NPATCH, DM, 256, INV_P, 0);
    k_assemble<<<(BT*DM+255)/256, 256>>>(cls, pos);

    // weight prep
    k_tsplit<<<dim3(2304/32, DM/32, NL),  dim3(32,8)>>>(qkvw,  q0, q1, DM,   2304);
    k_tsplit<<<dim3(DM/32,   DM/32, NL),  dim3(32,8)>>>(projw, pr0, pr1, DM, DM);
    k_tsplit<<<dim3(3072/32, DM/32, NL),  dim3(32,8)>>>(fc1w,  f10, f11, DM, 3072);
    k_tsplit<<<dim3(DM/32, 3072/32, NL),  dim3(32,8)>>>(fc2w,  f20, f21, 3072, DM);

    int MT = (BT + 127) / 128;   // 19
    int R4 = (BT*DM/4 + 255) / 256;

    for (int l = 0; l < NL; l++) {
        k_ln<<<BT, 256>>>(px, ph, ln1g + (size_t)l*DM, ln1b + (size_t)l*DM, 0);
        k_gemm_h<<<dim3(2304/128, MT), 256, SMEM_GH>>>(
            h0, h1, q0 + (size_t)l*2304*DM, q1 + (size_t)l*2304*DM,
            qkvb + (size_t)l*2304, nullptr, nullptr, qk0, qk1,
            BT, 2304, DM, DM, INV_W, 3);
        k_scores_h<<<dim3(5, 5, NIMG*NHD), 256, SMEM_SC>>>();
        k_softmax <<<NIMG*NHD*NT, 128>>>();
        k_av_h    <<<dim3(5, NIMG*NHD), 256, SMEM_AV>>>();
        k_gemm_w<<<dim3(DM/128, MT), 512, SMEM_GH>>>(
            a0, a1, pr0 + (size_t)l*DM*DM, pr1 + (size_t)l*DM*DM,
            projb + (size_t)l*DM, px, px, nullptr, nullptr,
            BT, DM, DM, INV_W, 2);
        k_ln<<<BT, 256>>>(px, ph, ln2g + (size_t)l*DM, ln2b + (size_t)l*DM, 0);
        k_gemm_h<<<dim3(3072/128, MT), 256, SMEM_GH>>>(
            h0, h1, f10 + (size_t)l*3072*DM, f11 + (size_t)l*3072*DM,
            fc1b + (size_t)l*3072, nullptr, nullptr, m0, m1,
            BT, 3072, DM, DM, INV_W, 1);
        // fc2: split-K 4 -> partials -> reduce(+bias+residual)
        k_gemm_h<<<dim3(DM/128, MT, 4), 256, SMEM_GH>>>(
            m0, m1, f20 + (size_t)l*DM*3072, f21 + (size_t)l*DM*3072,
            nullptr, nullptr, ppart, nullptr, nullptr,
            BT, DM, 768, 3072, INV_W, 4);
        k_red<<<R4, 256>>>(ppart, 4, INV_W, fc2b + (size_t)l*DM, px, px, DM, BT*DM/4);
    }

    k_ln<<<BT, 256>>>(px, ph, normg, normb, 1);
    k_loss<<<1, 256>>>((float*)d_out);
}

// round 12
// speedup vs baseline: 1.1396x; 1.0201x over previous
#include <cuda_runtime.h>
#include <cuda_fp16.h>
#include <math.h>
#include <stdint.h>

// ---------------- problem constants ----------------
#define IH 384
#define IW 384
#define NPIX (IH*IW)
#define NIMG 4
#define NT 577
#define DM 768
#define NL 12
#define NHD 12
#define BT (NIMG*NT)    // 2308
#define NPATCH 576
#define BIGF 1e4f
#define SPF 640         // padded fp32 score row stride (floats)

// static scales (fp16 range management)
#define WS  4096.f
#define AS  256.f
#define PS  32.f
#define SS  256.f

// ---------------- scratch (device globals) ----------------
__device__ float d_g2fg[NIMG*NPIX];
__device__ float d_g2bg[NIMG*NPIX];
__device__ float d_tok [NIMG*NPATCH*DM];
__device__ float d_x   [BT*DM];
__device__ float d_h   [BT*DM];
__device__ __align__(128) float d_S[(size_t)NIMG*NHD*NT*SPF];
__device__ float2 d_rs [NIMG*NHD*NT];
__device__ float d_part[(size_t)4*BT*DM];

__device__ __align__(128) __half d_h0[BT*DM],    d_h1[BT*DM];
__device__ __align__(128) __half d_a0[BT*DM],    d_a1[BT*DM];
__device__ __align__(128) __half d_m0[BT*3072],  d_m1[BT*3072];
__device__ __align__(128) __half d_p0[NIMG*NPATCH*256], d_p1[NIMG*NPATCH*256];
__device__ __align__(128) __half d_q0[BT*3*DM],  d_q1[BT*3*DM];

__device__ __align__(128) __half d_ws0[DM*256],       d_ws1[DM*256];
__device__ __align__(128) __half d_qT0[NL*2304*DM],   d_qT1[NL*2304*DM];
__device__ __align__(128) __half d_pT0[NL*DM*DM],     d_pT1[NL*DM*DM];
__device__ __align__(128) __half d_f1T0[NL*3072*DM],  d_f1T1[NL*3072*DM];
__device__ __align__(128) __half d_f2T0[NL*DM*3072],  d_f2T1[NL*DM*3072];

// ---------------- helpers ----------------
__device__ __forceinline__ void split2h(float x, float s, __half& h0, __half& h1) {
    float xs = x * s;
    h0 = __float2half_rn(xs);
    h1 = __float2half_rn(xs - __half2float(h0));
}
__device__ __forceinline__ uint32_t s2u(const void* p) {
    uint32_t a;
    asm("{ .reg .u64 t; cvta.to.shared.u64 t, %1; cvt.u32.u64 %0, t; }" : "=r"(a) : "l"(p));
    return a;
}
#define CP16(s,g)  asm volatile("cp.async.cg.shared.global [%0], [%1], 16;" :: "r"(s), "l"(g))
#define CPCOMMIT() asm volatile("cp.async.commit_group;")
#define CPWAIT0()  asm volatile("cp.async.wait_group 0;")

__device__ __forceinline__ void ldsm4(unsigned &r0, unsigned &r1, unsigned &r2,
                                      unsigned &r3, uint32_t addr) {
    asm volatile("ldmatrix.sync.aligned.m8n8.x4.shared.b16 {%0,%1,%2,%3}, [%4];"
        : "=r"(r0), "=r"(r1), "=r"(r2), "=r"(r3) : "r"(addr));
}
__device__ __forceinline__ void ldsm4t(unsigned &r0, unsigned &r1, unsigned &r2,
                                       unsigned &r3, uint32_t addr) {
    asm volatile("ldmatrix.sync.aligned.m8n8.x4.trans.shared.b16 {%0,%1,%2,%3}, [%4];"
        : "=r"(r0), "=r"(r1), "=r"(r2), "=r"(r3) : "r"(addr));
}
#define MMA_F16(c, a, b0v, b1v) \
    asm volatile("mma.sync.aligned.m16n8k16.row.col.f32.f16.f16.f32 " \
                 "{%0,%1,%2,%3},{%4,%5,%6,%7},{%8,%9},{%0,%1,%2,%3};" \
                 : "+f"((c)[0]), "+f"((c)[1]), "+f"((c)[2]), "+f"((c)[3]) \
                 : "r"((a)[0]), "r"((a)[1]), "r"((a)[2]), "r"((a)[3]), \
                   "r"(b0v), "r"(b1v))

// ---------------- EDT row pass (mask fused) ----------------
__global__ void k_edt_row(const float* __restrict__ logits, const int* __restrict__ tr) {
    int idx = blockIdx.x*blockDim.x + threadIdx.x;
    if (idx >= NIMG*IH) return;
    int img = idx / IH, i = idx % IH;
    float* gf = d_g2fg + (size_t)img*NPIX + (size_t)i*IW;
    float* gb = d_g2bg + (size_t)img*NPIX + (size_t)i*IW;
    const float* l0p = logits + ((size_t)img*2)*NPIX + (size_t)i*IW;
    const float* l1p = l0p + NPIX;
    const int*   trp = tr + (size_t)(img-2)*NPIX + (size_t)i*IW;
    bool islog = (img < 2);

    float lf = -BIGF, lb = -BIGF;
    for (int j = 0; j < IW; j++) {
        bool mz = islog ? !(l1p[j] > l0p[j]) : (trp[j] == 0);
        float jj = (float)j;
        if (mz) lf = jj; else lb = jj;
        gf[j] = jj - lf;
        gb[j] = jj - lb;
    }
    float rf = BIGF, rb = BIGF;
    for (int j = IW-1; j >= 0; j--) {
        bool mz = islog ? !(l1p[j] > l0p[j]) : (trp[j] == 0);
        float jj = (float)j;
        if (mz) rf = jj; else rb = jj;
        float g1 = fminf(fminf(gf[j], rf - jj), BIGF);
        float g2 = fminf(fminf(gb[j], rb - jj), BIGF);
        gf[j] = g1*g1;
        gb[j] = g2*g2;
    }
}

// ---------------- EDT column pass + SDM + patch-split write ----------------
__global__ void k_edt_col() {
    int idx = blockIdx.x*blockDim.x + threadIdx.x;
    if (idx >= NIMG*NPIX) return;
    int img = idx / NPIX, r = idx % NPIX;
    int i = r / IW, j = r % IW;
    const float* gf = d_g2fg + (size_t)img*NPIX;
    const float* gb = d_g2bg + (size_t)img*NPIX;
    float mf = 3.4e38f, mb = 3.4e38f;
    float fi = (float)i;
    for (int ii = 0; ii < IH; ii++) {
        float off = fi - (float)ii; off *= off;
        mf = fminf(mf, gf[(size_t)ii*IW + j] + off);
        mb = fminf(mb, gb[(size_t)ii*IW + j] + off);
    }
    float v = sqrtf(mb) - sqrtf(mf);
    int t = (i >> 4)*24 + (j >> 4);
    int k = ((i & 15) << 4) + (j & 15);
    size_t o = (size_t)img*NPATCH*256 + (size_t)t*256 + k;
    split2h(v, PS, d_p0[o], d_p1[o]);
}

// ---------------- weight prep ----------------
__global__ void k_wsumT(const float* __restrict__ pw) {
    int idx = blockIdx.x*blockDim.x + threadIdx.x;
    if (idx >= DM*256) return;
    int o = idx / 256, k = idx % 256;
    float v = pw[(size_t)k*DM + o] + pw[(size_t)(256+k)*DM + o] + pw[(size_t)(512+k)*DM + o];
    split2h(v, WS, d_ws0[idx], d_ws1[idx]);
}

__global__ void k_tsplit(const float* __restrict__ W, __half* __restrict__ T0,
                         __half* __restrict__ T1, int K, int N) {
    __shared__ float t[32][33];
    size_t off = (size_t)blockIdx.z * K * N;
    const float* w = W + off;
    int bx = blockIdx.x*32, by = blockIdx.y*32;
    int tx = threadIdx.x, ty = threadIdx.y;
    #pragma unroll
    for (int r = 0; r < 4; r++)
        t[ty + r*8][tx] = w[(size_t)(by + ty + r*8)*N + bx + tx];
    __syncthreads();
    #pragma unroll
    for (int r = 0; r < 4; r++) {
        int n = bx + ty + r*8, k = by + tx;
        float v = t[tx][ty + r*8];
        size_t o = off + (size_t)n*K + k;
        split2h(v, WS, T0[o], T1[o]);
    }
}

__global__ void k_assemble(const float* __restrict__ cls, const float* __restrict__ pos) {
    int idx = blockIdx.x*blockDim.x + threadIdx.x;
    if (idx >= BT*DM) return;
    int img = idx / (NT*DM);
    int rem = idx % (NT*DM);
    int t = rem / DM, c = rem % DM;
    float v = (t == 0) ? cls[c] : d_tok[((size_t)img*NPATCH + (t-1))*DM + c];
    d_x[idx] = v + pos[(size_t)t*DM + c];
}

// ---------------- layernorm ----------------
__global__ void k_ln(const float* __restrict__ in, float* __restrict__ out,
                     const float* __restrict__ g, const float* __restrict__ b,
                     int wout) {
    int row = blockIdx.x;
    int tid = threadIdx.x;
    const float* xr = in + (size_t)row*DM;
    __shared__ float red[256];
    float s = 0.f;
    for (int c = tid; c < DM; c += 256) s += xr[c];
    red[tid] = s; __syncthreads();
    for (int o = 128; o > 0; o >>= 1) { if (tid < o) red[tid] += red[tid+o]; __syncthreads(); }
    float mu = red[0] * (1.f/768.f);
    __syncthreads();
    float v = 0.f;
    for (int c = tid; c < DM; c += 256) { float dd = xr[c]-mu; v += dd*dd; }
    red[tid] = v; __syncthreads();
    for (int o = 128; o > 0; o >>= 1) { if (tid < o) red[tid] += red[tid+o]; __syncthreads(); }
    float rstd = rsqrtf(red[0] * (1.f/768.f) + 1e-6f);
    for (int c = tid; c < DM; c += 256) {
        float val = (xr[c]-mu)*rstd*g[c] + b[c];
        size_t o = (size_t)row*DM + c;
        if (wout) out[o] = val;
        split2h(val, AS, d_h0[o], d_h1[o]);
    }
}

// ---------------- shared epilogue ----------------
__device__ __forceinline__ void gemm_epilogue(
        float v0, float v1, int gr, int gc, int N, int epi,
        const float* res, float* C, __half* C0, __half* C1) {
    if (epi == 1 || epi == 3) {
        if (epi == 1) {
            v0 = 0.5f*v0*(1.f + erff(v0*0.70710678118654752f));
            v1 = 0.5f*v1*(1.f + erff(v1*0.70710678118654752f));
        }
        size_t o = (size_t)gr*N + gc;
        __half h00, h01, h10, h11;
        split2h(v0, AS, h00, h01);
        split2h(v1, AS, h10, h11);
        __half2 p0; p0.x = h00; p0.y = h10;
        __half2 p1; p1.x = h01; p1.y = h11;
        *(__half2*)&C0[o] = p0;
        *(__half2*)&C1[o] = p1;
    } else {
        if (epi == 2) {
            float2 r2 = *(const float2*)&res[(size_t)gr*N + gc];
            v0 += r2.x; v1 += r2.y;
        }
        *(float2*)&C[(size_t)gr*N + gc] = make_float2(v0, v1);
    }
}

// ================= GEMM A: 256 threads, 128x128 tile, optional split-K ======
#define APL 10240u
#define BPL128 10240u
#define BUFB128 (2u*APL + 2u*BPL128)
#define SMEM_GH (2u*BUFB128)

__global__ __launch_bounds__(256, 2) void k_gemm_h(
        const __half* __restrict__ A0, const __half* __restrict__ A1,
        const __half* __restrict__ B0, const __half* __restrict__ B1,
        const float* __restrict__ bias, const float* __restrict__ res,
        float* __restrict__ C, __half* __restrict__ C0, __half* __restrict__ C1,
        int M, int N, int K, int LDK, float inv, int epi) {
    extern __shared__ char smem[];
    uint32_t sb = s2u(smem);
    int tid = threadIdx.x, lane = tid & 31, warp = tid >> 5;
    int wm = (warp & 3)*32, wn = (warp >> 2)*64;
    int bm = blockIdx.y*128, bn = blockIdx.x*128;
    size_t koff = (size_t)blockIdx.z * K;
    int g = lane >> 2, q = lane & 3;

    float acc[2][8][4];
    #pragma unroll
    for (int i=0;i<2;i++)
        #pragma unroll
        for (int j=0;j<8;j++)
            #pragma unroll
            for (int r=0;r<4;r++) acc[i][j][r]=0.f;

    int lrow = tid >> 2;
    int lc   = tid & 3;

    auto load_chunk = [&](int kt, int buf) {
        int k0 = kt * 32;
        uint32_t base = sb + (uint32_t)buf * BUFB128;
        const __half* Ap[2] = {A0, A1};
        const __half* Bp[2] = {B0, B1};
        #pragma unroll
        for (int p = 0; p < 2; p++) {
            #pragma unroll
            for (int l = 0; l < 2; l++) {
                int row = lrow + l*64;
                int gr = bm + row; if (gr >= M) gr = M - 1;
                CP16(base + p*APL + (uint32_t)(row*80 + lc*16),
                     Ap[p] + (size_t)gr*LDK + koff + k0 + lc*8);
                CP16(base + 2*APL + p*BPL128 + (uint32_t)(row*80 + lc*16),
                     Bp[p] + (size_t)(bn + row)*LDK + koff + k0 + lc*8);
            }
        }
    };

    int KT = K >> 5;
    load_chunk(0, 0);
    CPCOMMIT();
    for (int kt = 0; kt < KT; kt++) {
        CPWAIT0();
        __syncthreads();
        if (kt + 1 < KT) { load_chunk(kt + 1, (kt + 1) & 1); CPCOMMIT(); }
        uint32_t base = sb + (uint32_t)(kt & 1) * BUFB128;
        uint32_t aBase = base + (uint32_t)((wm + (lane & 15))*80 + (lane >> 4)*16);
        int bn8 = (lane & 7) + ((lane >> 4) << 3);
        uint32_t bBase = base + 2*APL + (uint32_t)((wn + bn8)*80 + ((lane >> 3) & 1)*16);
        #pragma unroll
        for (int ks = 0; ks < 2; ks++) {
            unsigned a0f[2][4], a1f[2][4];
            #pragma unroll
            for (int mi = 0; mi < 2; mi++) {
                ldsm4(a0f[mi][0],a0f[mi][1],a0f[mi][2],a0f[mi][3],
                      aBase + mi*1280u + ks*32u);
                ldsm4(a1f[mi][0],a1f[mi][1],a1f[mi][2],a1f[mi][3],
                      aBase + APL + mi*1280u + ks*32u);
            }
            #pragma unroll
            for (int nq = 0; nq < 4; nq++) {
                unsigned b0f[4], b1f[4];
                ldsm4(b0f[0],b0f[1],b0f[2],b0f[3], bBase + nq*1280u + ks*32u);
                ldsm4(b1f[0],b1f[1],b1f[2],b1f[3], bBase + BPL128 + nq*1280u + ks*32u);
                #pragma unroll
                for (int mi = 0; mi < 2; mi++)
                    #pragma unroll
                    for (int h = 0; h < 2; h++) {
                        MMA_F16(acc[mi][nq*2+h], a0f[mi], b0f[h*2], b0f[h*2+1]);
                        MMA_F16(acc[mi][nq*2+h], a0f[mi], b1f[h*2], b1f[h*2+1]);
                        MMA_F16(acc[mi][nq*2+h], a1f[mi], b0f[h*2], b0f[h*2+1]);
                    }
            }
        }
    }
    __syncthreads();

    size_t pofs = (size_t)blockIdx.z * M * N;
    #pragma unroll
    for (int mi = 0; mi < 2; mi++)
        #pragma unroll
        for (int rr = 0; rr < 2; rr++) {
            int gr = bm + wm + mi*16 + g + rr*8;
            if (gr >= M) continue;
            #pragma unroll
            for (int nj = 0; nj < 8; nj++) {
                int gc = bn + wn + nj*8 + 2*q;
                if (epi == 4) {
                    *(float2*)&C[pofs + (size_t)gr*N + gc] =
                        make_float2(acc[mi][nj][rr*2+0], acc[mi][nj][rr*2+1]);
                } else {
                    gemm_epilogue(acc[mi][nj][rr*2+0]*inv + bias[gc],
                                  acc[mi][nj][rr*2+1]*inv + bias[gc+1],
                                  gr, gc, N, epi, res, C, C0, C1);
                }
            }
        }
}

// ---------------- split-K reduce ----------------
__global__ void k_red(const float* __restrict__ P, int ns, float inv,
                      const float* __restrict__ bias, const float* __restrict__ res,
                      float* __restrict__ C, int N, int total4) {
    int t = blockIdx.x*blockDim.x + threadIdx.x;
    if (t >= total4) return;
    size_t i = (size_t)t * 4;
    size_t MN = (size_t)total4 * 4;
    float4 s = *(const float4*)&P[i];
    for (int z = 1; z < ns; z++) {
        float4 p = *(const float4*)&P[(size_t)z*MN + i];
        s.x += p.x; s.y += p.y; s.z += p.z; s.w += p.w;
    }
    int c = (int)(i % N);
    float4 b = *(const float4*)&bias[c];
    float4 r = *(const float4*)&res[i];
    s.x = s.x*inv + b.x + r.x;
    s.y = s.y*inv + b.y + r.y;
    s.z = s.z*inv + b.z + r.z;
    s.w = s.w*inv + b.w + r.w;
    *(float4*)&C[i] = s;
}

// ================= GEMM W: 512 threads, 128x128 tile (patch) ===============
__global__ __launch_bounds__(512, 1) void k_gemm_w(
        const __half* __restrict__ A0, const __half* __restrict__ A1,
        const __half* __restrict__ B0, const __half* __restrict__ B1,
        const float* __restrict__ bias, const float* __restrict__ res,
        float* __restrict__ C, __half* __restrict__ C0, __half* __restrict__ C1,
        int M, int N, int K, float inv, int epi) {
    extern __shared__ char smem[];
    uint32_t sb = s2u(smem);
    int tid = threadIdx.x, lane = tid & 31, warp = tid >> 5;
    int wm = (warp & 3)*32, wn = (warp >> 2)*32;
    int bm = blockIdx.y*128, bn = blockIdx.x*128;
    int g = lane >> 2, q = lane & 3;

    float acc[2][4][4];
    #pragma unroll
    for (int i=0;i<2;i++)
        #pragma unroll
        for (int j=0;j<4;j++)
            #pragma unroll
            for (int r=0;r<4;r++) acc[i][j][r]=0.f;

    int lrow = tid >> 2;
    int lc   = tid & 3;

    auto load_chunk = [&](int kt, int buf) {
        int k0 = kt * 32;
        uint32_t base = sb + (uint32_t)buf * BUFB128;
        const __half* Ap[2] = {A0, A1};
        const __half* Bp[2] = {B0, B1};
        int gr = bm + lrow; if (gr >= M) gr = M - 1;
        #pragma unroll
        for (int p = 0; p < 2; p++) {
            CP16(base + p*APL + (uint32_t)(lrow*80 + lc*16),
                 Ap[p] + (size_t)gr*K + k0 + lc*8);
            CP16(base + 2*APL + p*BPL128 + (uint32_t)(lrow*80 + lc*16),
                 Bp[p] + (size_t)(bn + lrow)*K + k0 + lc*8);
        }
    };

    int KT = K >> 5;
    load_chunk(0, 0);
    CPCOMMIT();
    for (int kt = 0; kt < KT; kt++) {
        CPWAIT0();
        __syncthreads();
        if (kt + 1 < KT) { load_chunk(kt + 1, (kt + 1) & 1); CPCOMMIT(); }
        uint32_t base = sb + (uint32_t)(kt & 1) * BUFB128;
        uint32_t aBase = base + (uint32_t)((wm + (lane & 15))*80 + (lane >> 4)*16);
        int bn8 = (lane & 7) + ((lane >> 4) << 3);
        uint32_t bBase = base + 2*APL + (uint32_t)((wn + bn8)*80 + ((lane >> 3) & 1)*16);
        #pragma unroll
        for (int ks = 0; ks < 2; ks++) {
            unsigned a0f[2][4], a1f[2][4];
            #pragma unroll
            for (int mi = 0; mi < 2; mi++) {
                ldsm4(a0f[mi][0],a0f[mi][1],a0f[mi][2],a0f[mi][3],
                      aBase + mi*1280u + ks*32u);
                ldsm4(a1f[mi][0],a1f[mi][1],a1f[mi][2],a1f[mi][3],
                      aBase + APL + mi*1280u + ks*32u);
            }
            #pragma unroll
            for (int nq = 0; nq < 2; nq++) {
                unsigned b0f[4], b1f[4];
                ldsm4(b0f[0],b0f[1],b0f[2],b0f[3], bBase + nq*1280u + ks*32u);
                ldsm4(b1f[0],b1f[1],b1f[2],b1f[3], bBase + BPL128 + nq*1280u + ks*32u);
                #pragma unroll
                for (int mi = 0; mi < 2; mi++)
                    #pragma unroll
                    for (int h = 0; h < 2; h++) {
                        MMA_F16(acc[mi][nq*2+h], a0f[mi], b0f[h*2], b0f[h*2+1]);
                        MMA_F16(acc[mi][nq*2+h], a0f[mi], b1f[h*2], b1f[h*2+1]);
                        MMA_F16(acc[mi][nq*2+h], a1f[mi], b0f[h*2], b0f[h*2+1]);
                    }
            }
        }
    }
    __syncthreads();

    #pragma unroll
    for (int mi = 0; mi < 2; mi++)
        #pragma unroll
        for (int rr = 0; rr < 2; rr++) {
            int gr = bm + wm + mi*16 + g + rr*8;
            if (gr >= M) continue;
            #pragma unroll
            for (int nj = 0; nj < 4; nj++) {
                int gc = bn + wn + nj*8 + 2*q;
                gemm_epilogue(acc[mi][nj][rr*2+0]*inv + bias[gc],
                              acc[mi][nj][rr*2+1]*inv + bias[gc+1],
                              gr, gc, N, epi, res, C, C0, C1);
            }
        }
}

// ================= attention scores (fp32 out, padded stride SPF) ===========
#define SROW 144u
#define SPL  (128u*SROW)
#define SMEM_SC (4u*SPL)

__global__ __launch_bounds__(256, 2) void k_scores_h() {
    extern __shared__ char smem[];
    uint32_t sb = s2u(smem);
    int bh = blockIdx.z, b = bh / NHD, h = bh % NHD;
    int m0 = blockIdx.y*128, n0 = blockIdx.x*128;
    int tid = threadIdx.x, lane = tid & 31, warp = tid >> 5;
    int wm = (warp & 3)*32, wn = (warp >> 2)*64;
    int g = lane >> 2, q = lane & 3;

    #pragma unroll
    for (int l = 0; l < 4; l++) {
        int id = tid + l*256;
        int row = id >> 3, c = id & 7;
        int gm = m0 + row; if (gm >= NT) gm = NT - 1;
        int gn = n0 + row; if (gn >= NT) gn = NT - 1;
        size_t qo = (size_t)(b*NT + gm)*2304 + h*64 + c*8;
        size_t ko = (size_t)(b*NT + gn)*2304 + 768 + h*64 + c*8;
        uint32_t so = (uint32_t)(row*SROW + c*16);
        CP16(sb + so,          d_q0 + qo);
        CP16(sb + SPL + so,    d_q1 + qo);
        CP16(sb + 2*SPL + so,  d_q0 + ko);
        CP16(sb + 3*SPL + so,  d_q1 + ko);
    }
    CPCOMMIT(); CPWAIT0();
    __syncthreads();

    float acc[2][8][4];
    #pragma unroll
    for (int i=0;i<2;i++)
        #pragma unroll
        for (int j=0;j<8;j++)
            #pragma unroll
            for (int r=0;r<4;r++) acc[i][j][r]=0.f;

    uint32_t aBase = sb + (uint32_t)((wm + (lane & 15))*SROW + (lane >> 4)*16);
    int bn8 = (lane & 7) + ((lane >> 4) << 3);
    uint32_t bBase = sb + 2*SPL + (uint32_t)((wn + bn8)*SROW + ((lane >> 3) & 1)*16);

    #pragma unroll
    for (int ks = 0; ks < 4; ks++) {
        unsigned a0f[2][4], a1f[2][4];
        #pragma unroll
        for (int mi = 0; mi < 2; mi++) {
            ldsm4(a0f[mi][0],a0f[mi][1],a0f[mi][2],a0f[mi][3],
                  aBase + mi*16*SROW + ks*32u);
            ldsm4(a1f[mi][0],a1f[mi][1],a1f[mi][2],a1f[mi][3],
                  aBase + SPL + mi*16*SROW + ks*32u);
        }
        #pragma unroll
        for (int nq = 0; nq < 4; nq++) {
            unsigned b0f[4], b1f[4];
            ldsm4(b0f[0],b0f[1],b0f[2],b0f[3], bBase + nq*16*SROW + ks*32u);
            ldsm4(b1f[0],b1f[1],b1f[2],b1f[3], bBase + SPL + nq*16*SROW + ks*32u);
            #pragma unroll
            for (int mi = 0; mi < 2; mi++)
                #pragma unroll
                for (int hh = 0; hh < 2; hh++) {
                    MMA_F16(acc[mi][nq*2+hh], a0f[mi], b0f[hh*2], b0f[hh*2+1]);
                    MMA_F16(acc[mi][nq*2+hh], a0f[mi], b1f[hh*2], b1f[hh*2+1]);
                    MMA_F16(acc[mi][nq*2+hh], a1f[mi], b0f[hh*2], b0f[hh*2+1]);
                }
        }
    }

    const float SCL = 0.125f/(AS*AS);
    float* sbase = d_S + (size_t)bh*NT*SPF;
    #pragma unroll
    for (int mi = 0; mi < 2; mi++)
        #pragma unroll
        for (int rr = 0; rr < 2; rr++) {
            int gm = m0 + wm + mi*16 + g + rr*8;
            if (gm >= NT) continue;
            #pragma unroll
            for (int nj = 0; nj < 8; nj++) {
                int gc = n0 + wn + nj*8 + 2*q;
                if (gc < NT)   sbase[(size_t)gm*SPF + gc]   = acc[mi][nj][rr*2+0]*SCL;
                if (gc+1 < NT) sbase[(size_t)gm*SPF + gc+1] = acc[mi][nj][rr*2+1]*SCL;
            }
        }
}

// ---------------- row stats: max and SS/sum per score row ----------------
__global__ void k_rowstat() {
    size_t row = blockIdx.x;
    const float* s = d_S + row*SPF;
    int tid = threadIdx.x;
    __shared__ float red[128];
    float v[5];
    float mx = -3.4e38f;
    #pragma unroll
    for (int i = 0; i < 5; i++) {
        int c = tid + i*128;
        v[i] = (c < NT) ? s[c] : -3.4e38f;
        mx = fmaxf(mx, v[i]);
    }
    red[tid] = mx; __syncthreads();
    for (int o = 64; o > 0; o >>= 1) { if (tid < o) red[tid] = fmaxf(red[tid], red[tid+o]); __syncthreads(); }
    mx = red[0]; __syncthreads();
    float sum = 0.f;
    #pragma unroll
    for (int i = 0; i < 5; i++) sum += __expf(v[i] - mx);
    red[tid] = sum; __syncthreads();
    for (int o = 64; o > 0; o >>= 1) { if (tid < o) red[tid] += red[tid+o]; __syncthreads(); }
    if (tid == 0) d_rs[row] = make_float2(mx, SS / red[0]);
}

// ================= AV: fused exp/normalize + split + MMA ====================
// smem: rs[128]f2 | P0,P1 (128x80B) | 2 x { F(128x144B fp32 tile) V0 V1 (32x144) }
#define AV_RS   0u
#define AV_P0   1024u
#define AV_P1   11264u
#define AV_BUF0 21504u
#define AV_FB   18432u
#define AV_VPL  4608u
#define AV_BUFSZ (AV_FB + 2u*AV_VPL)          // 27648
#define SMEM_AV (AV_BUF0 + 2u*AV_BUFSZ)       // 76800

__global__ __launch_bounds__(256, 2) void k_av_h() {
    extern __shared__ char smem[];
    uint32_t sb = s2u(smem);
    int bh = blockIdx.y, b = bh / NHD, h = bh % NHD;
    int m0 = blockIdx.x*128;
    int tid = threadIdx.x, lane = tid & 31, warp = tid >> 5;
    int wm = (warp & 3)*32, wn = (warp >> 2)*32;
    int g = lane >> 2, q = lane & 3;

    float acc[2][4][4];
    #pragma unroll
    for (int i=0;i<2;i++)
        #pragma unroll
        for (int j=0;j<4;j++)
            #pragma unroll
            for (int r=0;r<4;r++) acc[i][j][r]=0.f;

    const float* Sf = d_S + (size_t)bh*NT*SPF;

    // per-row stats into smem (visible after first barrier)
    if (tid < 128) {
        int gm = m0 + tid; if (gm >= NT) gm = NT - 1;
        *(float2*)(smem + AV_RS + tid*8) = d_rs[(size_t)bh*NT + gm];
    }

    auto load_chunk = [&](int kt, int buf) {
        int k0 = kt * 32;
        uint32_t base = sb + AV_BUF0 + (uint32_t)buf * AV_BUFSZ;
        // F: 128 rows x 32 fp32 (128 B), row stride 144 B
        #pragma unroll
        for (int l = 0; l < 4; l++) {
            int id = tid + l*256;
            int row = id >> 3, c = id & 7;
            int gm = m0 + row; if (gm >= NT) gm = NT - 1;
            CP16(base + (uint32_t)(row*144 + c*16),
                 Sf + (size_t)gm*SPF + k0 + c*4);
        }
        // V planes: 32 k-rows x 64 cols, stride 144 B
        {
            int row = tid >> 3, c = tid & 7;
            int gk = k0 + row; if (gk >= NT) gk = NT - 1;
            size_t vo = (size_t)(b*NT + gk)*2304 + 1536 + h*64 + c*8;
            uint32_t d = (uint32_t)(row*144 + c*16);
            CP16(base + AV_FB + d,           d_q0 + vo);
            CP16(base + AV_FB + AV_VPL + d,  d_q1 + vo);
        }
    };

    const int KT = (NT + 31) / 32;   // 19
    load_chunk(0, 0);
    CPCOMMIT();
    for (int kt = 0; kt < KT; kt++) {
        int buf = kt & 1;
        int k0 = kt * 32;
        CPWAIT0();
        __syncthreads();                       // F,V ready; prev ldsm of P done
        if (kt + 1 < KT) { load_chunk(kt + 1, (kt + 1) & 1); CPCOMMIT(); }
        // convert F -> split-2 P planes
        {
            int row = tid >> 1, colh = (tid & 1)*16;
            float2 ri = *(const float2*)(smem + AV_RS + row*8);
            const float* F = (const float*)(smem + AV_BUF0 + buf*AV_BUFSZ) + row*36 + colh;
            char* P0w = smem + AV_P0 + row*80 + colh*2;
            char* P1w = smem + AV_P1 + row*80 + colh*2;
            #pragma unroll
            for (int j = 0; j < 16; j += 2) {
                int k = k0 + colh + j;
                float f0 = F[j], f1 = F[j+1];
                float p0 = (k     < NT) ? __expf(f0 - ri.x)*ri.y : 0.f;
                float p1 = (k + 1 < NT) ? __expf(f1 - ri.x)*ri.y : 0.f;
                __half a0h = __float2half_rn(p0);
                __half b0h = __float2half_rn(p1);
                __half a1h = __float2half_rn(p0 - __half2float(a0h));
                __half b1h = __float2half_rn(p1 - __half2float(b0h));
                __half2 w0; w0.x = a0h; w0.y = b0h;
                __half2 w1; w1.x = a1h; w1.y = b1h;
                *(__half2*)(P0w + j*2) = w0;
                *(__half2*)(P1w + j*2) = w1;
            }
        }
        __syncthreads();                       // P ready
        uint32_t aBase = sb + AV_P0 + (uint32_t)((wm + (lane & 15))*80 + (lane >> 4)*16);
        uint32_t vb0 = sb + AV_BUF0 + (uint32_t)buf*AV_BUFSZ + AV_FB;
        uint32_t bBase = vb0 + (uint32_t)((lane & 15)*144 + wn*2 + (lane >> 4)*16);
        #pragma unroll
        for (int ks = 0; ks < 2; ks++) {
            unsigned a0f[2][4], a1f[2][4];
            #pragma unroll
            for (int mi = 0; mi < 2; mi++) {
                ldsm4(a0f[mi][0],a0f[mi][1],a0f[mi][2],a0f[mi][3],
                      aBase + mi*16*80u + ks*32u);
                ldsm4(a1f[mi][0],a1f[mi][1],a1f[mi][2],a1f[mi][3],
                      aBase + (AV_P1 - AV_P0) + mi*16*80u + ks*32u);
            }
            #pragma unroll
            for (int nq = 0; nq < 2; nq++) {
                unsigned b0f[4], b1f[4];
                uint32_t ba = bBase + ks*16*144u + nq*32u;
                ldsm4t(b0f[0],b0f[1],b0f[2],b0f[3], ba);
                ldsm4t(b1f[0],b1f[1],b1f[2],b1f[3], ba + AV_VPL);
                #pragma unroll
                for (int mi = 0; mi < 2; mi++)
                    #pragma unroll
                    for (int hh = 0; hh < 2; hh++) {
                        MMA_F16(acc[mi][nq*2+hh], a0f[mi], b0f[hh*2], b0f[hh*2+1]);
                        MMA_F16(acc[mi][nq*2+hh], a0f[mi], b1f[hh*2], b1f[hh*2+1]);
                        MMA_F16(acc[mi][nq*2+hh], a1f[mi], b0f[hh*2], b0f[hh*2+1]);
                    }
            }
        }
    }

    const float INV_AV = 1.f/(SS*AS);
    #pragma unroll
    for (int mi = 0; mi < 2; mi++)
        #pragma unroll
        for (int rr = 0; rr < 2; rr++) {
            int gm = m0 + wm + mi*16 + g + rr*8;
            if (gm >= NT) continue;
            #pragma unroll
            for (int nj = 0; nj < 4; nj++) {
                int gc = wn + nj*8 + 2*q;
                size_t o = (size_t)(b*NT + gm)*DM + h*64 + gc;
                float v0 = acc[mi][nj][rr*2+0]*INV_AV;
                float v1 = acc[mi][nj][rr*2+1]*INV_AV;
                __half h00, h01, h10, h11;
                split2h(v0, AS, h00, h01);
                split2h(v1, AS, h10, h11);
                __half2 p0; p0.x = h00; p0.y = h10;
                __half2 p1; p1.x = h01; p1.y = h11;
                *(__half2*)&d_a0[o] = p0;
                *(__half2*)&d_a1[o] = p1;
            }
        }
}

// ---------------- final cosine loss ----------------
__global__ void k_loss(float* out) {
    __shared__ float sd[256], sa[256], sb2[256];
    int tid = threadIdx.x;
    float coss[2];
    for (int b = 0; b < 2; b++) {
        const float* fp = d_h + (size_t)b*NT*DM;
        const float* ft = d_h + (size_t)(2+b)*NT*DM;
        float dt = 0.f, na = 0.f, nb = 0.f;
        for (int c = tid; c < DM; c += 256) {
            float a = fp[c], bb = ft[c];
            dt += a*bb; na += a*a; nb += bb*bb;
        }
        sd[tid] = dt; sa[tid] = na; sb2[tid] = nb; __syncthreads();
        for (int o = 128; o > 0; o >>= 1) {
            if (tid < o) { sd[tid]+=sd[tid+o]; sa[tid]+=sa[tid+o]; sb2[tid]+=sb2[tid+o]; }
            __syncthreads();
        }
        coss[b] = sd[0] / (fmaxf(sqrtf(sa[0]), 1e-8f) * fmaxf(sqrtf(sb2[0]), 1e-8f));
        __syncthreads();
    }
    if (tid == 0) out[0] = 1.f - 0.5f*(coss[0] + coss[1]);
}

// ---------------- launch ----------------
extern "C" void kernel_launch(void* const* d_in, const int* in_sizes, int n_in,
                              void* d_out, int out_size) {
    const float* pred   = (const float*)d_in[0];
    const int*   tru    = (const int*)  d_in[1];
    const float* patchw = (const float*)d_in[2];
    const float* patchb = (const float*)d_in[3];
    const float* cls    = (const float*)d_in[4];
    const float* pos    = (const float*)d_in[5];
    const float* ln1g   = (const float*)d_in[6];
    const float* ln1b   = (const float*)d_in[7];
    const float* qkvw   = (const float*)d_in[8];
    const float* qkvb   = (const float*)d_in[9];
    const float* projw  = (const float*)d_in[10];
    const float* projb  = (const float*)d_in[11];
    const float* ln2g   = (const float*)d_in[12];
    const float* ln2b   = (const float*)d_in[13];
    const float* fc1w   = (const float*)d_in[14];
    const float* fc1b   = (const float*)d_in[15];
    const float* fc2w   = (const float*)d_in[16];
    const float* fc2b   = (const float*)d_in[17];
    const float* normg  = (const float*)d_in[18];
    const float* normb  = (const float*)d_in[19];

    float *px, *ph, *ptok, *ppart;
    cudaGetSymbolAddress((void**)&px,    d_x);
    cudaGetSymbolAddress((void**)&ph,    d_h);
    cudaGetSymbolAddress((void**)&ptok,  d_tok);
    cudaGetSymbolAddress((void**)&ppart, d_part);

    __half *h0,*h1,*a0,*a1,*m0,*m1,*p0,*p1,*qk0,*qk1;
    __half *ws0,*ws1,*q0,*q1,*pr0,*pr1,*f10,*f11,*f20,*f21;
    cudaGetSymbolAddress((void**)&h0, d_h0);   cudaGetSymbolAddress((void**)&h1, d_h1);
    cudaGetSymbolAddress((void**)&a0, d_a0);   cudaGetSymbolAddress((void**)&a1, d_a1);
    cudaGetSymbolAddress((void**)&m0, d_m0);   cudaGetSymbolAddress((void**)&m1, d_m1);
    cudaGetSymbolAddress((void**)&p0, d_p0);   cudaGetSymbolAddress((void**)&p1, d_p1);
    cudaGetSymbolAddress((void**)&qk0, d_q0);  cudaGetSymbolAddress((void**)&qk1, d_q1);
    cudaGetSymbolAddress((void**)&ws0, d_ws0); cudaGetSymbolAddress((void**)&ws1, d_ws1);
    cudaGetSymbolAddress((void**)&q0, d_qT0);  cudaGetSymbolAddress((void**)&q1, d_qT1);
    cudaGetSymbolAddress((void**)&pr0, d_pT0); cudaGetSymbolAddress((void**)&pr1, d_pT1);
    cudaGetSymbolAddress((void**)&f10, d_f1T0); cudaGetSymbolAddress((void**)&f11, d_f1T1);
    cudaGetSymbolAddress((void**)&f20, d_f2T0); cudaGetSymbolAddress((void**)&f21, d_f2T1);

    cudaFuncSetAttribute(k_gemm_h, cudaFuncAttributeMaxDynamicSharedMemorySize, SMEM_GH);
    cudaFuncSetAttribute(k_gemm_w, cudaFuncAttributeMaxDynamicSharedMemorySize, SMEM_GH);
    cudaFuncSetAttribute(k_scores_h, cudaFuncAttributeMaxDynamicSharedMemorySize, SMEM_SC);
    cudaFuncSetAttribute(k_av_h,     cudaFuncAttributeMaxDynamicSharedMemorySize, SMEM_AV);

    const float INV_W = 1.f/(AS*WS);
    const float INV_P = 1.f/(PS*WS);

    // front sequence
    k_edt_row<<<(NIMG*IH+127)/128, 128>>>(pred, tru);
    k_edt_col<<<(NIMG*NPIX+255)/256, 256>>>();
    k_wsumT  <<<(DM*256+255)/256, 256>>>(patchw);
    k_gemm_w<<<dim3(DM/128, (NIMG*NPATCH)/128), 512, SMEM_GH>>>(
        p0, p1, ws0, ws1, patchb, nullptr, ptok, nullptr, nullptr,
        NIMG*NPATCH, DM, 256, INV_P, 0);
    k_assemble<<<(BT*DM+255)/256, 256>>>(cls, pos);

    // weight prep
    k_tsplit<<<dim3(2304/32, DM/32, NL),  dim3(32,8)>>>(qkvw,  q0, q1, DM,   2304);
    k_tsplit<<<dim3(DM/32,   DM/32, NL),  dim3(32,8)>>>(projw, pr0, pr1, DM, DM);
    k_tsplit<<<dim3(3072/32, DM/32, NL),  dim3(32,8)>>>(fc1w,  f10, f11, DM, 3072);
    k_tsplit<<<dim3(DM/32, 3072/32, NL),  dim3(32,8)>>>(fc2w,  f20, f21, 3072, DM);

    int MT = (BT + 127) / 128;   // 19
    int R4 = (BT*DM/4 + 255) / 256;

    for (int l = 0; l < NL; l++) {
        k_ln<<<BT, 256>>>(px, ph, ln1g + (size_t)l*DM, ln1b + (size_t)l*DM, 0);
        k_gemm_h<<<dim3(2304/128, MT), 256, SMEM_GH>>>(
            h0, h1, q0 + (size_t)l*2304*DM, q1 + (size_t)l*2304*DM,
            qkvb + (size_t)l*2304, nullptr, nullptr, qk0, qk1,
            BT, 2304, DM, DM, INV_W, 3);
        k_scores_h<<<dim3(5, 5, NIMG*NHD), 256, SMEM_SC>>>();
        k_rowstat <<<NIMG*NHD*NT, 128>>>();
        k_av_h    <<<dim3(5, NIMG*NHD), 256, SMEM_AV>>>();
        // proj: split-K 2
        k_gemm_h<<<dim3(DM/128, MT, 2), 256, SMEM_GH>>>(
            a0, a1, pr0 + (size_t)l*DM*DM, pr1 + (size_t)l*DM*DM,
            nullptr, nullptr, ppart, nullptr, nullptr,
            BT, DM, 384, 768, INV_W, 4);
        k_red<<<R4, 256>>>(ppart, 2, INV_W, projb + (size_t)l*DM, px, px, DM, BT*DM/4);
        k_ln<<<BT, 256>>>(px, ph, ln2g + (size_t)l*DM, ln2b + (size_t)l*DM, 0);
        k_gemm_h<<<dim3(3072/128, MT), 256, SMEM_GH>>>(
            h0, h1, f10 + (size_t)l*3072*DM, f11 + (size_t)l*3072*DM,
            fc1b + (size_t)l*3072, nullptr, nullptr, m0, m1,
            BT, 3072, DM, DM, INV_W, 1);
        // fc2: split-K 4
        k_gemm_h<<<dim3(DM/128, MT, 4), 256, SMEM_GH>>>(
            m0, m1, f20 + (size_t)l*DM*3072, f21 + (size_t)l*DM*3072,
            nullptr, nullptr, ppart, nullptr, nullptr,
            BT, DM, 768, 3072, INV_W, 4);
        k_red<<<R4, 256>>>(ppart, 4, INV_W, fc2b + (size_t)l*DM, px, px, DM, BT*DM/4);
    }

    k_ln<<<BT, 256>>>(px, ph, normg, normb, 1);
    k_loss<<<1, 256>>>((float*)d_out);
}

// round 13
// speedup vs baseline: 1.1518x; 1.0106x over previous
#include <cuda_runtime.h>
#include <cuda_fp16.h>
#include <math.h>
#include <stdint.h>

// ---------------- problem constants ----------------
#define IH 384
#define IW 384
#define NPIX (IH*IW)
#define NIMG 4
#define NT 577
#define DM 768
#define NL 12
#define NHD 12
#define BT (NIMG*NT)    // 2308
#define NPATCH 576
#define BIGF 1e4f
#define SPF 640

// static scales
#define WS  4096.f
#define AS  256.f
#define PS  32.f
#define SS  256.f

// ---------------- scratch ----------------
__device__ float d_g2fg[NIMG*NPIX];
__device__ float d_g2bg[NIMG*NPIX];
__device__ float d_tok [NIMG*NPATCH*DM];
__device__ float d_x   [BT*DM];
__device__ float d_h   [BT*DM];
__device__ __align__(128) float d_S[(size_t)NIMG*NHD*NT*SPF];
__device__ float2 d_rs [NIMG*NHD*NT];
__device__ float d_part[(size_t)4*BT*DM];

__device__ __align__(128) __half d_h0[BT*DM],    d_h1[BT*DM];
__device__ __align__(128) __half d_a0[BT*DM],    d_a1[BT*DM];
__device__ __align__(128) __half d_m0[BT*3072],  d_m1[BT*3072];
__device__ __align__(128) __half d_p0[NIMG*NPATCH*256], d_p1[NIMG*NPATCH*256];
__device__ __align__(128) __half d_q0[BT*3*DM],  d_q1[BT*3*DM];

__device__ __align__(128) __half d_ws0[DM*256],       d_ws1[DM*256];
__device__ __align__(128) __half d_qT0[NL*2304*DM],   d_qT1[NL*2304*DM];
__device__ __align__(128) __half d_pT0[NL*DM*DM],     d_pT1[NL*DM*DM];
__device__ __align__(128) __half d_f1T0[NL*3072*DM],  d_f1T1[NL*3072*DM];
__device__ __align__(128) __half d_f2T0[NL*DM*3072],  d_f2T1[NL*DM*3072];

// ---------------- helpers ----------------
__device__ __forceinline__ void split2h(float x, float s, __half& h0, __half& h1) {
    float xs = x * s;
    h0 = __float2half_rn(xs);
    h1 = __float2half_rn(xs - __half2float(h0));
}
__device__ __forceinline__ uint32_t s2u(const void* p) {
    uint32_t a;
    asm("{ .reg .u64 t; cvta.to.shared.u64 t, %1; cvt.u32.u64 %0, t; }" : "=r"(a) : "l"(p));
    return a;
}
#define CP16(s,g)  asm volatile("cp.async.cg.shared.global [%0], [%1], 16;" :: "r"(s), "l"(g))
#define CPCOMMIT() asm volatile("cp.async.commit_group;")
#define CPWAIT0()  asm volatile("cp.async.wait_group 0;")

__device__ __forceinline__ void ldsm4(unsigned &r0, unsigned &r1, unsigned &r2,
                                      unsigned &r3, uint32_t addr) {
    asm volatile("ldmatrix.sync.aligned.m8n8.x4.shared.b16 {%0,%1,%2,%3}, [%4];"
        : "=r"(r0), "=r"(r1), "=r"(r2), "=r"(r3) : "r"(addr));
}
__device__ __forceinline__ void ldsm4t(unsigned &r0, unsigned &r1, unsigned &r2,
                                       unsigned &r3, uint32_t addr) {
    asm volatile("ldmatrix.sync.aligned.m8n8.x4.trans.shared.b16 {%0,%1,%2,%3}, [%4];"
        : "=r"(r0), "=r"(r1), "=r"(r2), "=r"(r3) : "r"(addr));
}
#define MMA_F16(c, a, b0v, b1v) \
    asm volatile("mma.sync.aligned.m16n8k16.row.col.f32.f16.f16.f32 " \
                 "{%0,%1,%2,%3},{%4,%5,%6,%7},{%8,%9},{%0,%1,%2,%3};" \
                 : "+f"((c)[0]), "+f"((c)[1]), "+f"((c)[2]), "+f"((c)[3]) \
                 : "r"((a)[0]), "r"((a)[1]), "r"((a)[2]), "r"((a)[3]), \
                   "r"(b0v), "r"(b1v))

// ---------------- EDT row pass (mask fused) ----------------
__global__ void k_edt_row(const float* __restrict__ logits, const int* __restrict__ tr) {
    int idx = blockIdx.x*blockDim.x + threadIdx.x;
    if (idx >= NIMG*IH) return;
    int img = idx / IH, i = idx % IH;
    float* gf = d_g2fg + (size_t)img*NPIX + (size_t)i*IW;
    float* gb = d_g2bg + (size_t)img*NPIX + (size_t)i*IW;
    const float* l0p = logits + ((size_t)img*2)*NPIX + (size_t)i*IW;
    const float* l1p = l0p + NPIX;
    const int*   trp = tr + (size_t)(img-2)*NPIX + (size_t)i*IW;
    bool islog = (img < 2);

    float lf = -BIGF, lb = -BIGF;
    for (int j = 0; j < IW; j++) {
        bool mz = islog ? !(l1p[j] > l0p[j]) : (trp[j] == 0);
        float jj = (float)j;
        if (mz) lf = jj; else lb = jj;
        gf[j] = jj - lf;
        gb[j] = jj - lb;
    }
    float rf = BIGF, rb = BIGF;
    for (int j = IW-1; j >= 0; j--) {
        bool mz = islog ? !(l1p[j] > l0p[j]) : (trp[j] == 0);
        float jj = (float)j;
        if (mz) rf = jj; else rb = jj;
        float g1 = fminf(fminf(gf[j], rf - jj), BIGF);
        float g2 = fminf(fminf(gb[j], rb - jj), BIGF);
        gf[j] = g1*g1;
        gb[j] = g2*g2;
    }
}

// ---------------- EDT column pass + SDM + patch-split write ----------------
__global__ void k_edt_col() {
    int idx = blockIdx.x*blockDim.x + threadIdx.x;
    if (idx >= NIMG*NPIX) return;
    int img = idx / NPIX, r = idx % NPIX;
    int i = r / IW, j = r % IW;
    const float* gf = d_g2fg + (size_t)img*NPIX;
    const float* gb = d_g2bg + (size_t)img*NPIX;
    float mf = 3.4e38f, mb = 3.4e38f;
    float fi = (float)i;
    for (int ii = 0; ii < IH; ii++) {
        float off = fi - (float)ii; off *= off;
        mf = fminf(mf, gf[(size_t)ii*IW + j] + off);
        mb = fminf(mb, gb[(size_t)ii*IW + j] + off);
    }
    float v = sqrtf(mb) - sqrtf(mf);
    int t = (i >> 4)*24 + (j >> 4);
    int k = ((i & 15) << 4) + (j & 15);
    size_t o = (size_t)img*NPATCH*256 + (size_t)t*256 + k;
    split2h(v, PS, d_p0[o], d_p1[o]);
}

// ---------------- weight prep ----------------
__global__ void k_wsumT(const float* __restrict__ pw) {
    int idx = blockIdx.x*blockDim.x + threadIdx.x;
    if (idx >= DM*256) return;
    int o = idx / 256, k = idx % 256;
    float v = pw[(size_t)k*DM + o] + pw[(size_t)(256+k)*DM + o] + pw[(size_t)(512+k)*DM + o];
    split2h(v, WS, d_ws0[idx], d_ws1[idx]);
}

__global__ void k_tsplit(const float* __restrict__ W, __half* __restrict__ T0,
                         __half* __restrict__ T1, int K, int N) {
    __shared__ float t[32][33];
    size_t off = (size_t)blockIdx.z * K * N;
    const float* w = W + off;
    int bx = blockIdx.x*32, by = blockIdx.y*32;
    int tx = threadIdx.x, ty = threadIdx.y;
    #pragma unroll
    for (int r = 0; r < 4; r++)
        t[ty + r*8][tx] = w[(size_t)(by + ty + r*8)*N + bx + tx];
    __syncthreads();
    #pragma unroll
    for (int r = 0; r < 4; r++) {
        int n = bx + ty + r*8, k = by + tx;
        float v = t[tx][ty + r*8];
        size_t o = off + (size_t)n*K + k;
        split2h(v, WS, T0[o], T1[o]);
    }
}

__global__ void k_assemble(const float* __restrict__ cls, const float* __restrict__ pos) {
    int idx = blockIdx.x*blockDim.x + threadIdx.x;
    if (idx >= BT*DM) return;
    int img = idx / (NT*DM);
    int rem = idx % (NT*DM);
    int t = rem / DM, c = rem % DM;
    float v = (t == 0) ? cls[c] : d_tok[((size_t)img*NPATCH + (t-1))*DM + c];
    d_x[idx] = v + pos[(size_t)t*DM + c];
}

// ---------------- layernorm (split planes only) ----------------
__global__ void k_ln(const float* __restrict__ in,
                     const float* __restrict__ g, const float* __restrict__ b) {
    int row = blockIdx.x;
    int tid = threadIdx.x;
    const float* xr = in + (size_t)row*DM;
    __shared__ float red[256];
    float v[3];
    #pragma unroll
    for (int i = 0; i < 3; i++) v[i] = xr[tid + i*256];
    float s = v[0] + v[1] + v[2];
    red[tid] = s; __syncthreads();
    for (int o = 128; o > 0; o >>= 1) { if (tid < o) red[tid] += red[tid+o]; __syncthreads(); }
    float mu = red[0] * (1.f/768.f);
    __syncthreads();
    float var = 0.f;
    #pragma unroll
    for (int i = 0; i < 3; i++) { float dd = v[i]-mu; var += dd*dd; }
    red[tid] = var; __syncthreads();
    for (int o = 128; o > 0; o >>= 1) { if (tid < o) red[tid] += red[tid+o]; __syncthreads(); }
    float rstd = rsqrtf(red[0] * (1.f/768.f) + 1e-6f);
    #pragma unroll
    for (int i = 0; i < 3; i++) {
        int c = tid + i*256;
        float val = (v[i]-mu)*rstd*g[c] + b[c];
        size_t o = (size_t)row*DM + c;
        split2h(val, AS, d_h0[o], d_h1[o]);
    }
}

// ---------------- fused split-K reduce + residual + LN + split write --------
__global__ void k_redln(const float* __restrict__ P, int ns, float inv,
                        const float* __restrict__ bias, float* __restrict__ x,
                        const float* __restrict__ g, const float* __restrict__ b) {
    int row = blockIdx.x;
    int tid = threadIdx.x;
    __shared__ float red[256];
    const size_t MN = (size_t)BT*DM;
    float v[3];
    #pragma unroll
    for (int i = 0; i < 3; i++) {
        int c = tid + i*256;
        size_t o = (size_t)row*DM + c;
        float s = P[o];
        for (int z = 1; z < ns; z++) s += P[(size_t)z*MN + o];
        v[i] = s*inv + bias[c] + x[o];
        x[o] = v[i];
    }
    float s = v[0] + v[1] + v[2];
    red[tid] = s; __syncthreads();
    for (int o = 128; o > 0; o >>= 1) { if (tid < o) red[tid] += red[tid+o]; __syncthreads(); }
    float mu = red[0] * (1.f/768.f);
    __syncthreads();
    float var = 0.f;
    #pragma unroll
    for (int i = 0; i < 3; i++) { float dd = v[i]-mu; var += dd*dd; }
    red[tid] = var; __syncthreads();
    for (int o = 128; o > 0; o >>= 1) { if (tid < o) red[tid] += red[tid+o]; __syncthreads(); }
    float rstd = rsqrtf(red[0] * (1.f/768.f) + 1e-6f);
    #pragma unroll
    for (int i = 0; i < 3; i++) {
        int c = tid + i*256;
        float val = (v[i]-mu)*rstd*g[c] + b[c];
        size_t o = (size_t)row*DM + c;
        split2h(val, AS, d_h0[o], d_h1[o]);
    }
}

// ---------------- final LN on the 4 cls rows only ----------------
__global__ void k_lncls(const float* __restrict__ in, float* __restrict__ out,
                        const float* __restrict__ g, const float* __restrict__ b) {
    int row = blockIdx.x * NT;     // cls token of image blockIdx.x
    int tid = threadIdx.x;
    const float* xr = in + (size_t)row*DM;
    __shared__ float red[256];
    float v[3];
    #pragma unroll
    for (int i = 0; i < 3; i++) v[i] = xr[tid + i*256];
    float s = v[0] + v[1] + v[2];
    red[tid] = s; __syncthreads();
    for (int o = 128; o > 0; o >>= 1) { if (tid < o) red[tid] += red[tid+o]; __syncthreads(); }
    float mu = red[0] * (1.f/768.f);
    __syncthreads();
    float var = 0.f;
    #pragma unroll
    for (int i = 0; i < 3; i++) { float dd = v[i]-mu; var += dd*dd; }
    red[tid] = var; __syncthreads();
    for (int o = 128; o > 0; o >>= 1) { if (tid < o) red[tid] += red[tid+o]; __syncthreads(); }
    float rstd = rsqrtf(red[0] * (1.f/768.f) + 1e-6f);
    #pragma unroll
    for (int i = 0; i < 3; i++) {
        int c = tid + i*256;
        out[(size_t)row*DM + c] = (v[i]-mu)*rstd*g[c] + b[c];
    }
}

// ---------------- shared epilogue ----------------
__device__ __forceinline__ void gemm_epilogue(
        float v0, float v1, int gr, int gc, int N, int epi,
        const float* res, float* C, __half* C0, __half* C1) {
    if (epi == 1 || epi == 3) {
        if (epi == 1) {
            v0 = 0.5f*v0*(1.f + erff(v0*0.70710678118654752f));
            v1 = 0.5f*v1*(1.f + erff(v1*0.70710678118654752f));
        }
        size_t o = (size_t)gr*N + gc;
        __half h00, h01, h10, h11;
        split2h(v0, AS, h00, h01);
        split2h(v1, AS, h10, h11);
        __half2 p0; p0.x = h00; p0.y = h10;
        __half2 p1; p1.x = h01; p1.y = h11;
        *(__half2*)&C0[o] = p0;
        *(__half2*)&C1[o] = p1;
    } else {
        if (epi == 2) {
            float2 r2 = *(const float2*)&res[(size_t)gr*N + gc];
            v0 += r2.x; v1 += r2.y;
        }
        *(float2*)&C[(size_t)gr*N + gc] = make_float2(v0, v1);
    }
}

// ================= GEMM A: 256 threads, 128x128 tile, optional split-K ======
#define APL 10240u
#define BPL128 10240u
#define BUFB128 (2u*APL + 2u*BPL128)
#define SMEM_GH (2u*BUFB128)

__global__ __launch_bounds__(256, 2) void k_gemm_h(
        const __half* __restrict__ A0, const __half* __restrict__ A1,
        const __half* __restrict__ B0, const __half* __restrict__ B1,
        const float* __restrict__ bias, const float* __restrict__ res,
        float* __restrict__ C, __half* __restrict__ C0, __half* __restrict__ C1,
        int M, int N, int K, int LDK, float inv, int epi) {
    extern __shared__ char smem[];
    uint32_t sb = s2u(smem);
    int tid = threadIdx.x, lane = tid & 31, warp = tid >> 5;
    int wm = (warp & 3)*32, wn = (warp >> 2)*64;
    int bm = blockIdx.y*128, bn = blockIdx.x*128;
    size_t koff = (size_t)blockIdx.z * K;
    int g = lane >> 2, q = lane & 3;

    float acc[2][8][4];
    #pragma unroll
    for (int i=0;i<2;i++)
        #pragma unroll
        for (int j=0;j<8;j++)
            #pragma unroll
            for (int r=0;r<4;r++) acc[i][j][r]=0.f;

    int lrow = tid >> 2;
    int lc   = tid & 3;

    auto load_chunk = [&](int kt, int buf) {
        int k0 = kt * 32;
        uint32_t base = sb + (uint32_t)buf * BUFB128;
        const __half* Ap[2] = {A0, A1};
        const __half* Bp[2] = {B0, B1};
        #pragma unroll
        for (int p = 0; p < 2; p++) {
            #pragma unroll
            for (int l = 0; l < 2; l++) {
                int row = lrow + l*64;
                int gr = bm + row; if (gr >= M) gr = M - 1;
                CP16(base + p*APL + (uint32_t)(row*80 + lc*16),
                     Ap[p] + (size_t)gr*LDK + koff + k0 + lc*8);
                CP16(base + 2*APL + p*BPL128 + (uint32_t)(row*80 + lc*16),
                     Bp[p] + (size_t)(bn + row)*LDK + koff + k0 + lc*8);
            }
        }
    };

    int KT = K >> 5;
    load_chunk(0, 0);
    CPCOMMIT();
    for (int kt = 0; kt < KT; kt++) {
        CPWAIT0();
        __syncthreads();
        if (kt + 1 < KT) { load_chunk(kt + 1, (kt + 1) & 1); CPCOMMIT(); }
        uint32_t base = sb + (uint32_t)(kt & 1) * BUFB128;
        uint32_t aBase = base + (uint32_t)((wm + (lane & 15))*80 + (lane >> 4)*16);
        int bn8 = (lane & 7) + ((lane >> 4) << 3);
        uint32_t bBase = base + 2*APL + (uint32_t)((wn + bn8)*80 + ((lane >> 3) & 1)*16);
        #pragma unroll
        for (int ks = 0; ks < 2; ks++) {
            unsigned a0f[2][4], a1f[2][4];
            #pragma unroll
            for (int mi = 0; mi < 2; mi++) {
                ldsm4(a0f[mi][0],a0f[mi][1],a0f[mi][2],a0f[mi][3],
                      aBase + mi*1280u + ks*32u);
                ldsm4(a1f[mi][0],a1f[mi][1],a1f[mi][2],a1f[mi][3],
                      aBase + APL + mi*1280u + ks*32u);
            }
            #pragma unroll
            for (int nq = 0; nq < 4; nq++) {
                unsigned b0f[4], b1f[4];
                ldsm4(b0f[0],b0f[1],b0f[2],b0f[3], bBase + nq*1280u + ks*32u);
                ldsm4(b1f[0],b1f[1],b1f[2],b1f[3], bBase + BPL128 + nq*1280u + ks*32u);
                #pragma unroll
                for (int mi = 0; mi < 2; mi++)
                    #pragma unroll
                    for (int h = 0; h < 2; h++) {
                        MMA_F16(acc[mi][nq*2+h], a0f[mi], b0f[h*2], b0f[h*2+1]);
                        MMA_F16(acc[mi][nq*2+h], a0f[mi], b1f[h*2], b1f[h*2+1]);
                        MMA_F16(acc[mi][nq*2+h], a1f[mi], b0f[h*2], b0f[h*2+1]);
                    }
            }
        }
    }
    __syncthreads();

    size_t pofs = (size_t)blockIdx.z * M * N;
    #pragma unroll
    for (int mi = 0; mi < 2; mi++)
        #pragma unroll
        for (int rr = 0; rr < 2; rr++) {
            int gr = bm + wm + mi*16 + g + rr*8;
            if (gr >= M) continue;
            #pragma unroll
            for (int nj = 0; nj < 8; nj++) {
                int gc = bn + wn + nj*8 + 2*q;
                if (epi == 4) {
                    *(float2*)&C[pofs + (size_t)gr*N + gc] =
                        make_float2(acc[mi][nj][rr*2+0], acc[mi][nj][rr*2+1]);
                } else {
                    gemm_epilogue(acc[mi][nj][rr*2+0]*inv + bias[gc],
                                  acc[mi][nj][rr*2+1]*inv + bias[gc+1],
                                  gr, gc, N, epi, res, C, C0, C1);
                }
            }
        }
}

// ---------------- split-K reduce (plain; last layer fc2) ----------------
__global__ void k_red(const float* __restrict__ P, int ns, float inv,
                      const float* __restrict__ bias, const float* __restrict__ res,
                      float* __restrict__ C, int N, int total4) {
    int t = blockIdx.x*blockDim.x + threadIdx.x;
    if (t >= total4) return;
    size_t i = (size_t)t * 4;
    size_t MN = (size_t)total4 * 4;
    float4 s = *(const float4*)&P[i];
    for (int z = 1; z < ns; z++) {
        float4 p = *(const float4*)&P[(size_t)z*MN + i];
        s.x += p.x; s.y += p.y; s.z += p.z; s.w += p.w;
    }
    int c = (int)(i % N);
    float4 b = *(const float4*)&bias[c];
    float4 r = *(const float4*)&res[i];
    s.x = s.x*inv + b.x + r.x;
    s.y = s.y*inv + b.y + r.y;
    s.z = s.z*inv + b.z + r.z;
    s.w = s.w*inv + b.w + r.w;
    *(float4*)&C[i] = s;
}

// ================= GEMM W: 512 threads, 128x128 tile (patch) ===============
__global__ __launch_bounds__(512, 1) void k_gemm_w(
        const __half* __restrict__ A0, const __half* __restrict__ A1,
        const __half* __restrict__ B0, const __half* __restrict__ B1,
        const float* __restrict__ bias, const float* __restrict__ res,
        float* __restrict__ C, __half* __restrict__ C0, __half* __restrict__ C1,
        int M, int N, int K, float inv, int epi) {
    extern __shared__ char smem[];
    uint32_t sb = s2u(smem);
    int tid = threadIdx.x, lane = tid & 31, warp = tid >> 5;
    int wm = (warp & 3)*32, wn = (warp >> 2)*32;
    int bm = blockIdx.y*128, bn = blockIdx.x*128;
    int g = lane >> 2, q = lane & 3;

    float acc[2][4][4];
    #pragma unroll
    for (int i=0;i<2;i++)
        #pragma unroll
        for (int j=0;j<4;j++)
            #pragma unroll
            for (int r=0;r<4;r++) acc[i][j][r]=0.f;

    int lrow = tid >> 2;
    int lc   = tid & 3;

    auto load_chunk = [&](int kt, int buf) {
        int k0 = kt * 32;
        uint32_t base = sb + (uint32_t)buf * BUFB128;
        const __half* Ap[2] = {A0, A1};
        const __half* Bp[2] = {B0, B1};
        int gr = bm + lrow; if (gr >= M) gr = M - 1;
        #pragma unroll
        for (int p = 0; p < 2; p++) {
            CP16(base + p*APL + (uint32_t)(lrow*80 + lc*16),
                 Ap[p] + (size_t)gr*K + k0 + lc*8);
            CP16(base + 2*APL + p*BPL128 + (uint32_t)(lrow*80 + lc*16),
                 Bp[p] + (size_t)(bn + lrow)*K + k0 + lc*8);
        }
    };

    int KT = K >> 5;
    load_chunk(0, 0);
    CPCOMMIT();
    for (int kt = 0; kt < KT; kt++) {
        CPWAIT0();
        __syncthreads();
        if (kt + 1 < KT) { load_chunk(kt + 1, (kt + 1) & 1); CPCOMMIT(); }
        uint32_t base = sb + (uint32_t)(kt & 1) * BUFB128;
        uint32_t aBase = base + (uint32_t)((wm + (lane & 15))*80 + (lane >> 4)*16);
        int bn8 = (lane & 7) + ((lane >> 4) << 3);
        uint32_t bBase = base + 2*APL + (uint32_t)((wn + bn8)*80 + ((lane >> 3) & 1)*16);
        #pragma unroll
        for (int ks = 0; ks < 2; ks++) {
            unsigned a0f[2][4], a1f[2][4];
            #pragma unroll
            for (int mi = 0; mi < 2; mi++) {
                ldsm4(a0f[mi][0],a0f[mi][1],a0f[mi][2],a0f[mi][3],
                      aBase + mi*1280u + ks*32u);
                ldsm4(a1f[mi][0],a1f[mi][1],a1f[mi][2],a1f[mi][3],
                      aBase + APL + mi*1280u + ks*32u);
            }
            #pragma unroll
            for (int nq = 0; nq < 2; nq++) {
                unsigned b0f[4], b1f[4];
                ldsm4(b0f[0],b0f[1],b0f[2],b0f[3], bBase + nq*1280u + ks*32u);
                ldsm4(b1f[0],b1f[1],b1f[2],b1f[3], bBase + BPL128 + nq*1280u + ks*32u);
                #pragma unroll
                for (int mi = 0; mi < 2; mi++)
                    #pragma unroll
                    for (int h = 0; h < 2; h++) {
                        MMA_F16(acc[mi][nq*2+h], a0f[mi], b0f[h*2], b0f[h*2+1]);
                        MMA_F16(acc[mi][nq*2+h], a0f[mi], b1f[h*2], b1f[h*2+1]);
                        MMA_F16(acc[mi][nq*2+h], a1f[mi], b0f[h*2], b0f[h*2+1]);
                    }
            }
        }
    }
    __syncthreads();

    #pragma unroll
    for (int mi = 0; mi < 2; mi++)
        #pragma unroll
        for (int rr = 0; rr < 2; rr++) {
            int gr = bm + wm + mi*16 + g + rr*8;
            if (gr >= M) continue;
            #pragma unroll
            for (int nj = 0; nj < 4; nj++) {
                int gc = bn + wn + nj*8 + 2*q;
                gemm_epilogue(acc[mi][nj][rr*2+0]*inv + bias[gc],
                              acc[mi][nj][rr*2+1]*inv + bias[gc+1],
                              gr, gc, N, epi, res, C, C0, C1);
            }
        }
}

// ================= attention scores (fp32 out, padded stride SPF) ===========
#define SROW 144u
#define SPL  (128u*SROW)
#define SMEM_SC (4u*SPL)

__global__ __launch_bounds__(256, 2) void k_scores_h() {
    extern __shared__ char smem[];
    uint32_t sb = s2u(smem);
    int bh = blockIdx.z, b = bh / NHD, h = bh % NHD;
    int m0 = blockIdx.y*128, n0 = blockIdx.x*128;
    int tid = threadIdx.x, lane = tid & 31, warp = tid >> 5;
    int wm = (warp & 3)*32, wn = (warp >> 2)*64;
    int g = lane >> 2, q = lane & 3;

    #pragma unroll
    for (int l = 0; l < 4; l++) {
        int id = tid + l*256;
        int row = id >> 3, c = id & 7;
        int gm = m0 + row; if (gm >= NT) gm = NT - 1;
        int gn = n0 + row; if (gn >= NT) gn = NT - 1;
        size_t qo = (size_t)(b*NT + gm)*2304 + h*64 + c*8;
        size_t ko = (size_t)(b*NT + gn)*2304 + 768 + h*64 + c*8;
        uint32_t so = (uint32_t)(row*SROW + c*16);
        CP16(sb + so,          d_q0 + qo);
        CP16(sb + SPL + so,    d_q1 + qo);
        CP16(sb + 2*SPL + so,  d_q0 + ko);
        CP16(sb + 3*SPL + so,  d_q1 + ko);
    }
    CPCOMMIT(); CPWAIT0();
    __syncthreads();

    float acc[2][8][4];
    #pragma unroll
    for (int i=0;i<2;i++)
        #pragma unroll
        for (int j=0;j<8;j++)
            #pragma unroll
            for (int r=0;r<4;r++) acc[i][j][r]=0.f;

    uint32_t aBase = sb + (uint32_t)((wm + (lane & 15))*SROW + (lane >> 4)*16);
    int bn8 = (lane & 7) + ((lane >> 4) << 3);
    uint32_t bBase = sb + 2*SPL + (uint32_t)((wn + bn8)*SROW + ((lane >> 3) & 1)*16);

    #pragma unroll
    for (int ks = 0; ks < 4; ks++) {
        unsigned a0f[2][4], a1f[2][4];
        #pragma unroll
        for (int mi = 0; mi < 2; mi++) {
            ldsm4(a0f[mi][0],a0f[mi][1],a0f[mi][2],a0f[mi][3],
                  aBase + mi*16*SROW + ks*32u);
            ldsm4(a1f[mi][0],a1f[mi][1],a1f[mi][2],a1f[mi][3],
                  aBase + SPL + mi*16*SROW + ks*32u);
        }
        #pragma unroll
        for (int nq = 0; nq < 4; nq++) {
            unsigned b0f[4], b1f[4];
            ldsm4(b0f[0],b0f[1],b0f[2],b0f[3], bBase + nq*16*SROW + ks*32u);
            ldsm4(b1f[0],b1f[1],b1f[2],b1f[3], bBase + SPL + nq*16*SROW + ks*32u);
            #pragma unroll
            for (int mi = 0; mi < 2; mi++)
                #pragma unroll
                for (int hh = 0; hh < 2; hh++) {
                    MMA_F16(acc[mi][nq*2+hh], a0f[mi], b0f[hh*2], b0f[hh*2+1]);
                    MMA_F16(acc[mi][nq*2+hh], a0f[mi], b1f[hh*2], b1f[hh*2+1]);
                    MMA_F16(acc[mi][nq*2+hh], a1f[mi], b0f[hh*2], b0f[hh*2+1]);
                }
        }
    }

    const float SCL = 0.125f/(AS*AS);
    float* sbase = d_S + (size_t)bh*NT*SPF;
    #pragma unroll
    for (int mi = 0; mi < 2; mi++)
        #pragma unroll
        for (int rr = 0; rr < 2; rr++) {
            int gm = m0 + wm + mi*16 + g + rr*8;
            if (gm >= NT) continue;
            #pragma unroll
            for (int nj = 0; nj < 8; nj++) {
                int gc = n0 + wn + nj*8 + 2*q;
                if (gc < NT)   sbase[(size_t)gm*SPF + gc]   = acc[mi][nj][rr*2+0]*SCL;
                if (gc+1 < NT) sbase[(size_t)gm*SPF + gc+1] = acc[mi][nj][rr*2+1]*SCL;
            }
        }
}

// ---------------- row stats ----------------
__global__ void k_rowstat() {
    size_t row = blockIdx.x;
    const float* s = d_S + row*SPF;
    int tid = threadIdx.x;
    __shared__ float red[128];
    float v[5];
    float mx = -3.4e38f;
    #pragma unroll
    for (int i = 0; i < 5; i++) {
        int c = tid + i*128;
        v[i] = (c < NT) ? s[c] : -3.4e38f;
        mx = fmaxf(mx, v[i]);
    }
    red[tid] = mx; __syncthreads();
    for (int o = 64; o > 0; o >>= 1) { if (tid < o) red[tid] = fmaxf(red[tid], red[tid+o]); __syncthreads(); }
    mx = red[0]; __syncthreads();
    float sum = 0.f;
    #pragma unroll
    for (int i = 0; i < 5; i++) sum += __expf(v[i] - mx);
    red[tid] = sum; __syncthreads();
    for (int o = 64; o > 0; o >>= 1) { if (tid < o) red[tid] += red[tid+o]; __syncthreads(); }
    if (tid == 0) d_rs[row] = make_float2(mx, SS / red[0]);
}

// ================= AV: fused exp/normalize + split + MMA ====================
#define AV_RS   0u
#define AV_P0   1024u
#define AV_P1   11264u
#define AV_BUF0 21504u
#define AV_FB   18432u
#define AV_VPL  4608u
#define AV_BUFSZ (AV_FB + 2u*AV_VPL)
#define SMEM_AV (AV_BUF0 + 2u*AV_BUFSZ)

__global__ __launch_bounds__(256, 2) void k_av_h() {
    extern __shared__ char smem[];
    uint32_t sb = s2u(smem);
    int bh = blockIdx.y, b = bh / NHD, h = bh % NHD;
    int m0 = blockIdx.x*128;
    int tid = threadIdx.x, lane = tid & 31, warp = tid >> 5;
    int wm = (warp & 3)*32, wn = (warp >> 2)*32;
    int g = lane >> 2, q = lane & 3;

    float acc[2][4][4];
    #pragma unroll
    for (int i=0;i<2;i++)
        #pragma unroll
        for (int j=0;j<4;j++)
            #pragma unroll
            for (int r=0;r<4;r++) acc[i][j][r]=0.f;

    const float* Sf = d_S + (size_t)bh*NT*SPF;

    if (tid < 128) {
        int gm = m0 + tid; if (gm >= NT) gm = NT - 1;
        *(float2*)(smem + AV_RS + tid*8) = d_rs[(size_t)bh*NT + gm];
    }

    auto load_chunk = [&](int kt, int buf) {
        int k0 = kt * 32;
        uint32_t base = sb + AV_BUF0 + (uint32_t)buf * AV_BUFSZ;
        #pragma unroll
        for (int l = 0; l < 4; l++) {
            int id = tid + l*256;
            int row = id >> 3, c = id & 7;
            int gm = m0 + row; if (gm >= NT) gm = NT - 1;
            CP16(base + (uint32_t)(row*144 + c*16),
                 Sf + (size_t)gm*SPF + k0 + c*4);
        }
        {
            int row = tid >> 3, c = tid & 7;
            int gk = k0 + row; if (gk >= NT) gk = NT - 1;
            size_t vo = (size_t)(b*NT + gk)*2304 + 1536 + h*64 + c*8;
            uint32_t d = (uint32_t)(row*144 + c*16);
            CP16(base + AV_FB + d,           d_q0 + vo);
            CP16(base + AV_FB + AV_VPL + d,  d_q1 + vo);
        }
    };

    const int KT = (NT + 31) / 32;   // 19
    load_chunk(0, 0);
    CPCOMMIT();
    for (int kt = 0; kt < KT; kt++) {
        int buf = kt & 1;
        int k0 = kt * 32;
        CPWAIT0();
        __syncthreads();
        if (kt + 1 < KT) { load_chunk(kt + 1, (kt + 1) & 1); CPCOMMIT(); }
        {
            int row = tid >> 1, colh = (tid & 1)*16;
            float2 ri = *(const float2*)(smem + AV_RS + row*8);
            const float* F = (const float*)(smem + AV_BUF0 + buf*AV_BUFSZ) + row*36 + colh;
            char* P0w = smem + AV_P0 + row*80 + colh*2;
            char* P1w = smem + AV_P1 + row*80 + colh*2;
            #pragma unroll
            for (int j = 0; j < 16; j += 2) {
                int k = k0 + colh + j;
                float f0 = F[j], f1 = F[j+1];
                float p0 = (k     < NT) ? __expf(f0 - ri.x)*ri.y : 0.f;
                float p1 = (k + 1 < NT) ? __expf(f1 - ri.x)*ri.y : 0.f;
                __half a0h = __float2half_rn(p0);
                __half b0h = __float2half_rn(p1);
                __half a1h = __float2half_rn(p0 - __half2float(a0h));
                __half b1h = __float2half_rn(p1 - __half2float(b0h));
                __half2 w0; w0.x = a0h; w0.y = b0h;
                __half2 w1; w1.x = a1h; w1.y = b1h;
                *(__half2*)(P0w + j*2) = w0;
                *(__half2*)(P1w + j*2) = w1;
            }
        }
        __syncthreads();
        uint32_t aBase = sb + AV_P0 + (uint32_t)((wm + (lane & 15))*80 + (lane >> 4)*16);
        uint32_t vb0 = sb + AV_BUF0 + (uint32_t)buf*AV_BUFSZ + AV_FB;
        uint32_t bBase = vb0 + (uint32_t)((lane & 15)*144 + wn*2 + (lane >> 4)*16);
        #pragma unroll
        for (int ks = 0; ks < 2; ks++) {
            unsigned a0f[2][4], a1f[2][4];
            #pragma unroll
            for (int mi = 0; mi < 2; mi++) {
                ldsm4(a0f[mi][0],a0f[mi][1],a0f[mi][2],a0f[mi][3],
                      aBase + mi*16*80u + ks*32u);
                ldsm4(a1f[mi][0],a1f[mi][1],a1f[mi][2],a1f[mi][3],
                      aBase + (AV_P1 - AV_P0) + mi*16*80u + ks*32u);
            }
            #pragma unroll
            for (int nq = 0; nq < 2; nq++) {
                unsigned b0f[4], b1f[4];
                uint32_t ba = bBase + ks*16*144u + nq*32u;
                ldsm4t(b0f[0],b0f[1],b0f[2],b0f[3], ba);
                ldsm4t(b1f[0],b1f[1],b1f[2],b1f[3], ba + AV_VPL);
                #pragma unroll
                for (int mi = 0; mi < 2; mi++)
                    #pragma unroll
                    for (int hh = 0; hh < 2; hh++) {
                        MMA_F16(acc[mi][nq*2+hh], a0f[mi], b0f[hh*2], b0f[hh*2+1]);
                        MMA_F16(acc[mi][nq*2+hh], a0f[mi], b1f[hh*2], b1f[hh*2+1]);
                        MMA_F16(acc[mi][nq*2+hh], a1f[mi], b0f[hh*2], b0f[hh*2+1]);
                    }
            }
        }
    }

    const float INV_AV = 1.f/(SS*AS);
    #pragma unroll
    for (int mi = 0; mi < 2; mi++)
        #pragma unroll
        for (int rr = 0; rr < 2; rr++) {
            int gm = m0 + wm + mi*16 + g + rr*8;
            if (gm >= NT) continue;
            #pragma unroll
            for (int nj = 0; nj < 4; nj++) {
                int gc = wn + nj*8 + 2*q;
                size_t o = (size_t)(b*NT + gm)*DM + h*64 + gc;
                float v0 = acc[mi][nj][rr*2+0]*INV_AV;
                float v1 = acc[mi][nj][rr*2+1]*INV_AV;
                __half h00, h01, h10, h11;
                split2h(v0, AS, h00, h01);
                split2h(v1, AS, h10, h11);
                __half2 p0; p0.x = h00; p0.y = h10;
                __half2 p1; p1.x = h01; p1.y = h11;
                *(__half2*)&d_a0[o] = p0;
                *(__half2*)&d_a1[o] = p1;
            }
        }
}

// ---------------- final cosine loss ----------------
__global__ void k_loss(float* out) {
    __shared__ float sd[256], sa[256], sb2[256];
    int tid = threadIdx.x;
    float coss[2];
    for (int b = 0; b < 2; b++) {
        const float* fp = d_h + (size_t)b*NT*DM;
        const float* ft = d_h + (size_t)(2+b)*NT*DM;
        float dt = 0.f, na = 0.f, nb = 0.f;
        for (int c = tid; c < DM; c += 256) {
            float a = fp[c], bb = ft[c];
            dt += a*bb; na += a*a; nb += bb*bb;
        }
        sd[tid] = dt; sa[tid] = na; sb2[tid] = nb; __syncthreads();
        for (int o = 128; o > 0; o >>= 1) {
            if (tid < o) { sd[tid]+=sd[tid+o]; sa[tid]+=sa[tid+o]; sb2[tid]+=sb2[tid+o]; }
            __syncthreads();
        }
        coss[b] = sd[0] / (fmaxf(sqrtf(sa[0]), 1e-8f) * fmaxf(sqrtf(sb2[0]), 1e-8f));
        __syncthreads();
    }
    if (tid == 0) out[0] = 1.f - 0.5f*(coss[0] + coss[1]);
}

// ---------------- launch ----------------
extern "C" void kernel_launch(void* const* d_in, const int* in_sizes, int n_in,
                              void* d_out, int out_size) {
    const float* pred   = (const float*)d_in[0];
    const int*   tru    = (const int*)  d_in[1];
    const float* patchw = (const float*)d_in[2];
    const float* patchb = (const float*)d_in[3];
    const float* cls    = (const float*)d_in[4];
    const float* pos    = (const float*)d_in[5];
    const float* ln1g   = (const float*)d_in[6];
    const float* ln1b   = (const float*)d_in[7];
    const float* qkvw   = (const float*)d_in[8];
    const float* qkvb   = (const float*)d_in[9];
    const float* projw  = (const float*)d_in[10];
    const float* projb  = (const float*)d_in[11];
    const float* ln2g   = (const float*)d_in[12];
    const float* ln2b   = (const float*)d_in[13];
    const float* fc1w   = (const float*)d_in[14];
    const float* fc1b   = (const float*)d_in[15];
    const float* fc2w   = (const float*)d_in[16];
    const float* fc2b   = (const float*)d_in[17];
    const float* normg  = (const float*)d_in[18];
    const float* normb  = (const float*)d_in[19];

    float *px, *ph, *ptok, *ppart;
    cudaGetSymbolAddress((void**)&px,    d_x);
    cudaGetSymbolAddress((void**)&ph,    d_h);
    cudaGetSymbolAddress((void**)&ptok,  d_tok);
    cudaGetSymbolAddress((void**)&ppart, d_part);

    __half *h0,*h1,*a0,*a1,*m0,*m1,*p0,*p1,*qk0,*qk1;
    __half *ws0,*ws1,*q0,*q1,*pr0,*pr1,*f10,*f11,*f20,*f21;
    cudaGetSymbolAddress((void**)&h0, d_h0);   cudaGetSymbolAddress((void**)&h1, d_h1);
    cudaGetSymbolAddress((void**)&a0, d_a0);   cudaGetSymbolAddress((void**)&a1, d_a1);
    cudaGetSymbolAddress((void**)&m0, d_m0);   cudaGetSymbolAddress((void**)&m1, d_m1);
    cudaGetSymbolAddress((void**)&p0, d_p0);   cudaGetSymbolAddress((void**)&p1, d_p1);
    cudaGetSymbolAddress((void**)&qk0, d_q0);  cudaGetSymbolAddress((void**)&qk1, d_q1);
    cudaGetSymbolAddress((void**)&ws0, d_ws0); cudaGetSymbolAddress((void**)&ws1, d_ws1);
    cudaGetSymbolAddress((void**)&q0, d_qT0);  cudaGetSymbolAddress((void**)&q1, d_qT1);
    cudaGetSymbolAddress((void**)&pr0, d_pT0); cudaGetSymbolAddress((void**)&pr1, d_pT1);
    cudaGetSymbolAddress((void**)&f10, d_f1T0); cudaGetSymbolAddress((void**)&f11, d_f1T1);
    cudaGetSymbolAddress((void**)&f20, d_f2T0); cudaGetSymbolAddress((void**)&f21, d_f2T1);

    cudaFuncSetAttribute(k_gemm_h, cudaFuncAttributeMaxDynamicSharedMemorySize, SMEM_GH);
    cudaFuncSetAttribute(k_gemm_w, cudaFuncAttributeMaxDynamicSharedMemorySize, SMEM_GH);
    cudaFuncSetAttribute(k_scores_h, cudaFuncAttributeMaxDynamicSharedMemorySize, SMEM_SC);
    cudaFuncSetAttribute(k_av_h,     cudaFuncAttributeMaxDynamicSharedMemorySize, SMEM_AV);

    const float INV_W = 1.f/(AS*WS);
    const float INV_P = 1.f/(PS*WS);

    // front sequence
    k_edt_row<<<(NIMG*IH+127)/128, 128>>>(pred, tru);
    k_edt_col<<<(NIMG*NPIX+255)/256, 256>>>();
    k_wsumT  <<<(DM*256+255)/256, 256>>>(patchw);
    k_gemm_w<<<dim3(DM/128, (NIMG*NPATCH)/128), 512, SMEM_GH>>>(
        p0, p1, ws0, ws1, patchb, nullptr, ptok, nullptr, nullptr,
        NIMG*NPATCH, DM, 256, INV_P, 0);
    k_assemble<<<(BT*DM+255)/256, 256>>>(cls, pos);

    // weight prep
    k_tsplit<<<dim3(2304/32, DM/32, NL),  dim3(32,8)>>>(qkvw,  q0, q1, DM,   2304);
    k_tsplit<<<dim3(DM/32,   DM/32, NL),  dim3(32,8)>>>(projw, pr0, pr1, DM, DM);
    k_tsplit<<<dim3(3072/32, DM/32, NL),  dim3(32,8)>>>(fc1w,  f10, f11, DM, 3072);
    k_tsplit<<<dim3(DM/32, 3072/32, NL),  dim3(32,8)>>>(fc2w,  f20, f21, 3072, DM);

    int MT = (BT + 127) / 128;   // 19
    int R4 = (BT*DM/4 + 255) / 256;

    // layer-0 ln1
    k_ln<<<BT, 256>>>(px, ln1g, ln1b);

    for (int l = 0; l < NL; l++) {
        k_gemm_h<<<dim3(2304/128, MT), 256, SMEM_GH>>>(
            h0, h1, q0 + (size_t)l*2304*DM, q1 + (size_t)l*2304*DM,
            qkvb + (size_t)l*2304, nullptr, nullptr, qk0, qk1,
            BT, 2304, DM, DM, INV_W, 3);
        k_scores_h<<<dim3(5, 5, NIMG*NHD), 256, SMEM_SC>>>();
        k_rowstat <<<NIMG*NHD*NT, 128>>>();
        k_av_h    <<<dim3(5, NIMG*NHD), 256, SMEM_AV>>>();
        // proj: split-K 2 -> fused reduce + residual + ln2
        k_gemm_h<<<dim3(DM/128, MT, 2), 256, SMEM_GH>>>(
            a0, a1, pr0 + (size_t)l*DM*DM, pr1 + (size_t)l*DM*DM,
            nullptr, nullptr, ppart, nullptr, nullptr,
            BT, DM, 384, 768, INV_W, 4);
        k_redln<<<BT, 256>>>(ppart, 2, INV_W, projb + (size_t)l*DM, px,
                             ln2g + (size_t)l*DM, ln2b + (size_t)l*DM);
        k_gemm_h<<<dim3(3072/128, MT), 256, SMEM_GH>>>(
            h0, h1, f10 + (size_t)l*3072*DM, f11 + (size_t)l*3072*DM,
            fc1b + (size_t)l*3072, nullptr, nullptr, m0, m1,
            BT, 3072, DM, DM, INV_W, 1);
        // fc2: split-K 4 -> fused reduce + residual + next ln1 (or plain last)
        k_gemm_h<<<dim3(DM/128, MT, 4), 256, SMEM_GH>>>(
            m0, m1, f20 + (size_t)l*DM*3072, f21 + (size_t)l*DM*3072,
            nullptr, nullptr, ppart, nullptr, nullptr,
            BT, DM, 768, 3072, INV_W, 4);
        if (l + 1 < NL) {
            k_redln<<<BT, 256>>>(ppart, 4, INV_W, fc2b + (size_t)l*DM, px,
                                 ln1g + (size_t)(l+1)*DM, ln1b + (size_t)(l+1)*DM);
        } else {
            k_red<<<R4, 256>>>(ppart, 4, INV_W, fc2b + (size_t)l*DM, px, px,
                               DM, BT*DM/4);
        }
    }

    k_lncls<<<NIMG, 256>>>(px, ph, normg, normb);
    k_loss<<<1, 256>>>((float*)d_out);
}